// round 1
// baseline (speedup 1.0000x reference)
#include <cuda_runtime.h>
#include <cuda_bf16.h>

// ---------------------------------------------------------------------------
// EntityClassify: 2-layer hetero R-GCN.
//   per relation: m = x_src @ W + b  (node transform)
//                 agg = scatter_add(m[src[e]] -> dst[e])
//   layer combine (exact reference order):
//     h_paper  = relu(relu(agg_cites) + agg_writes)
//     h_author = relu(agg_writtenby)
// Layer1: D 128->128 ; Layer2: 128->16. Output = [paper(200k,16) ; author(100k,16)]
// ---------------------------------------------------------------------------

#define N_PAPER_MAX 200000
#define N_AUTHOR_MAX 100000

// Scratch (device globals; allocation-free per harness rules)
__device__ float g_m[N_PAPER_MAX * 128];     // transformed features (reused per relation)
__device__ float g_h1p[N_PAPER_MAX * 128];   // layer-1 paper accumulator / output
__device__ float g_h1a[N_AUTHOR_MAX * 128];  // layer-1 author accumulator / output

// ---------------------------------------------------------------------------
// GEMM + bias, N=128, K=128. Block: 256 thr, 64 rows; per-thread 8x4 tile.
// ---------------------------------------------------------------------------
__global__ void gemm_bias_128(const float* __restrict__ X, const float* __restrict__ W,
                              const float* __restrict__ b, float* __restrict__ Y, int M) {
    __shared__ float xs[64][33];
    __shared__ float ws[32][128];
    __shared__ float bs[128];

    int tid = threadIdx.x;
    int tx = tid & 31;    // column group (cols tx + 32*rn)
    int ty = tid >> 5;    // row group (rows ty*8 + rm)
    int row_base = blockIdx.x * 64;

    if (tid < 128) bs[tid] = b[tid];

    float acc[8][4];
#pragma unroll
    for (int i = 0; i < 8; i++)
#pragma unroll
        for (int j = 0; j < 4; j++) acc[i][j] = 0.f;

    for (int kc = 0; kc < 128; kc += 32) {
        // X chunk: 64 rows x 32 k
#pragma unroll
        for (int i = 0; i < 8; i++) {
            int idx = tid + 256 * i;           // 0..2047
            int r = idx >> 5, c = idx & 31;
            int gr = row_base + r;
            xs[r][c] = (gr < M) ? X[(long)gr * 128 + kc + c] : 0.f;
        }
        // W chunk: 32 k x 128 cols
#pragma unroll
        for (int i = 0; i < 16; i++) {
            int idx = tid + 256 * i;           // 0..4095
            int r = idx >> 7, c = idx & 127;
            ws[r][c] = W[(long)(kc + r) * 128 + c];
        }
        __syncthreads();

#pragma unroll
        for (int k = 0; k < 32; k++) {
            float wv[4];
#pragma unroll
            for (int rn = 0; rn < 4; rn++) wv[rn] = ws[k][tx + 32 * rn];
#pragma unroll
            for (int rm = 0; rm < 8; rm++) {
                float a = xs[ty * 8 + rm][k];
#pragma unroll
                for (int rn = 0; rn < 4; rn++) acc[rm][rn] += a * wv[rn];
            }
        }
        __syncthreads();
    }

#pragma unroll
    for (int rm = 0; rm < 8; rm++) {
        int gr = row_base + ty * 8 + rm;
        if (gr < M) {
#pragma unroll
            for (int rn = 0; rn < 4; rn++) {
                int c = tx + 32 * rn;
                Y[(long)gr * 128 + c] = acc[rm][rn] + bs[c];
            }
        }
    }
}

// ---------------------------------------------------------------------------
// GEMM + bias, N=16, K=128. Block: 256 thr, 128 rows; per-thread 8x1 tile.
// ---------------------------------------------------------------------------
__global__ void gemm_bias_16(const float* __restrict__ X, const float* __restrict__ W,
                             const float* __restrict__ b, float* __restrict__ Y, int M) {
    __shared__ float xs[128][33];
    __shared__ float ws[32][16];
    __shared__ float bs[16];

    int tid = threadIdx.x;
    int tx = tid & 15;    // column 0..15
    int ty = tid >> 4;    // row group 0..15 (rows ty*8 + rm)
    int row_base = blockIdx.x * 128;

    if (tid < 16) bs[tid] = b[tid];

    float acc[8];
#pragma unroll
    for (int i = 0; i < 8; i++) acc[i] = 0.f;

    for (int kc = 0; kc < 128; kc += 32) {
#pragma unroll
        for (int i = 0; i < 16; i++) {
            int idx = tid + 256 * i;           // 0..4095
            int r = idx >> 5, c = idx & 31;
            int gr = row_base + r;
            xs[r][c] = (gr < M) ? X[(long)gr * 128 + kc + c] : 0.f;
        }
#pragma unroll
        for (int i = 0; i < 2; i++) {
            int idx = tid + 256 * i;           // 0..511
            int r = idx >> 4, c = idx & 15;
            ws[r][c] = W[(long)(kc + r) * 16 + c];
        }
        __syncthreads();

#pragma unroll
        for (int k = 0; k < 32; k++) {
            float wv = ws[k][tx];
#pragma unroll
            for (int rm = 0; rm < 8; rm++)
                acc[rm] += xs[ty * 8 + rm][k] * wv;
        }
        __syncthreads();
    }

#pragma unroll
    for (int rm = 0; rm < 8; rm++) {
        int gr = row_base + ty * 8 + rm;
        if (gr < M) Y[(long)gr * 16 + tx] = acc[rm] + bs[tx];
    }
}

// ---------------------------------------------------------------------------
// Scatter-add: out[dst[e]] += m[src[e]]  (F = feature dim)
// F=128: 32 threads per edge, float4 each. F=16: 4 threads per edge.
// ---------------------------------------------------------------------------
__global__ void scatter_add_128(const float* __restrict__ m, const int* __restrict__ src,
                                const int* __restrict__ dst, float* __restrict__ out, int E) {
    long idx = (long)blockIdx.x * blockDim.x + threadIdx.x;
    if (idx >= (long)E * 32) return;
    int e = (int)(idx >> 5);
    int q = (int)(idx & 31);
    const float4 v = reinterpret_cast<const float4*>(m + (long)src[e] * 128)[q];
    float* o = out + (long)dst[e] * 128 + q * 4;
    atomicAdd(o + 0, v.x);
    atomicAdd(o + 1, v.y);
    atomicAdd(o + 2, v.z);
    atomicAdd(o + 3, v.w);
}

__global__ void scatter_add_16(const float* __restrict__ m, const int* __restrict__ src,
                               const int* __restrict__ dst, float* __restrict__ out, int E) {
    long idx = (long)blockIdx.x * blockDim.x + threadIdx.x;
    if (idx >= (long)E * 4) return;
    int e = (int)(idx >> 2);
    int q = (int)(idx & 3);
    const float4 v = reinterpret_cast<const float4*>(m + (long)src[e] * 16)[q];
    float* o = out + (long)dst[e] * 16 + q * 4;
    atomicAdd(o + 0, v.x);
    atomicAdd(o + 1, v.y);
    atomicAdd(o + 2, v.z);
    atomicAdd(o + 3, v.w);
}

// ---------------------------------------------------------------------------
// Elementwise helpers
// ---------------------------------------------------------------------------
__global__ void zero_kernel(float* __restrict__ p, long n) {
    long i = (long)blockIdx.x * blockDim.x + threadIdx.x;
    if (i < n) p[i] = 0.f;
}

__global__ void relu_kernel(float* __restrict__ p, long n) {
    long i = (long)blockIdx.x * blockDim.x + threadIdx.x;
    if (i < n) p[i] = fmaxf(p[i], 0.f);
}

static inline int cdiv(long a, long b) { return (int)((a + b - 1) / b); }

// ---------------------------------------------------------------------------
extern "C" void kernel_launch(void* const* d_in, const int* in_sizes, int n_in,
                              void* d_out, int out_size) {
    const float* embed_paper  = (const float*)d_in[0];
    const float* embed_author = (const float*)d_in[1];
    const float* W1_cites     = (const float*)d_in[2];
    const float* b1_cites     = (const float*)d_in[3];
    const float* W1_writtenby = (const float*)d_in[4];
    const float* b1_writtenby = (const float*)d_in[5];
    const float* W1_writes    = (const float*)d_in[6];
    const float* b1_writes    = (const float*)d_in[7];
    const float* W2_cites     = (const float*)d_in[8];
    const float* b2_cites     = (const float*)d_in[9];
    const float* W2_writtenby = (const float*)d_in[10];
    const float* b2_writtenby = (const float*)d_in[11];
    const float* W2_writes    = (const float*)d_in[12];
    const float* b2_writes    = (const float*)d_in[13];
    const int* cites_src      = (const int*)d_in[14];
    const int* cites_dst      = (const int*)d_in[15];
    const int* writtenby_src  = (const int*)d_in[16];
    const int* writtenby_dst  = (const int*)d_in[17];
    const int* writes_src     = (const int*)d_in[18];
    const int* writes_dst     = (const int*)d_in[19];

    const int n_paper  = in_sizes[0] / 128;
    const int n_author = in_sizes[1] / 128;
    const int E_cites  = in_sizes[14];
    const int E_wb     = in_sizes[16];
    const int E_wr     = in_sizes[18];

    float* m;   cudaGetSymbolAddress((void**)&m,   g_m);
    float* h1p; cudaGetSymbolAddress((void**)&h1p, g_h1p);
    float* h1a; cudaGetSymbolAddress((void**)&h1a, g_h1a);

    float* out_paper  = (float*)d_out;                       // [n_paper, 16]
    float* out_author = (float*)d_out + (long)n_paper * 16;  // [n_author, 16]

    const long np128 = (long)n_paper * 128;
    const long na128 = (long)n_author * 128;

    // ---------------- Layer 1 (D=128) ----------------
    zero_kernel<<<cdiv(np128, 256), 256>>>(h1p, np128);
    zero_kernel<<<cdiv(na128, 256), 256>>>(h1a, na128);

    // cites: paper -> paper
    gemm_bias_128<<<cdiv(n_paper, 64), 256>>>(embed_paper, W1_cites, b1_cites, m, n_paper);
    scatter_add_128<<<cdiv((long)E_cites * 32, 256), 256>>>(m, cites_src, cites_dst, h1p, E_cites);
    relu_kernel<<<cdiv(np128, 256), 256>>>(h1p, np128);   // relu(agg_cites)

    // writes: author -> paper
    gemm_bias_128<<<cdiv(n_author, 64), 256>>>(embed_author, W1_writes, b1_writes, m, n_author);
    scatter_add_128<<<cdiv((long)E_wr * 32, 256), 256>>>(m, writes_src, writes_dst, h1p, E_wr);
    relu_kernel<<<cdiv(np128, 256), 256>>>(h1p, np128);   // h1_paper

    // writtenby: paper -> author
    gemm_bias_128<<<cdiv(n_paper, 64), 256>>>(embed_paper, W1_writtenby, b1_writtenby, m, n_paper);
    scatter_add_128<<<cdiv((long)E_wb * 32, 256), 256>>>(m, writtenby_src, writtenby_dst, h1a, E_wb);
    relu_kernel<<<cdiv(na128, 256), 256>>>(h1a, na128);   // h1_author

    // ---------------- Layer 2 (D=16) ----------------
    const long out_n = (long)out_size;
    zero_kernel<<<cdiv(out_n, 256), 256>>>((float*)d_out, out_n);

    const long np16 = (long)n_paper * 16;
    const long na16 = (long)n_author * 16;

    // cites: h1_paper -> paper
    gemm_bias_16<<<cdiv(n_paper, 128), 256>>>(h1p, W2_cites, b2_cites, m, n_paper);
    scatter_add_16<<<cdiv((long)E_cites * 4, 256), 256>>>(m, cites_src, cites_dst, out_paper, E_cites);
    relu_kernel<<<cdiv(np16, 256), 256>>>(out_paper, np16);

    // writes: h1_author -> paper
    gemm_bias_16<<<cdiv(n_author, 128), 256>>>(h1a, W2_writes, b2_writes, m, n_author);
    scatter_add_16<<<cdiv((long)E_wr * 4, 256), 256>>>(m, writes_src, writes_dst, out_paper, E_wr);
    relu_kernel<<<cdiv(np16, 256), 256>>>(out_paper, np16);

    // writtenby: h1_paper -> author
    gemm_bias_16<<<cdiv(n_paper, 128), 256>>>(h1p, W2_writtenby, b2_writtenby, m, n_paper);
    scatter_add_16<<<cdiv((long)E_wb * 4, 256), 256>>>(m, writtenby_src, writtenby_dst, out_author, E_wb);
    relu_kernel<<<cdiv(na16, 256), 256>>>(out_author, na16);
}

// round 2
// speedup vs baseline: 1.8454x; 1.8454x over previous
#include <cuda_runtime.h>
#include <cuda_bf16.h>
#include <cstdint>

// ---------------------------------------------------------------------------
// EntityClassify: 2-layer hetero R-GCN.
//   per relation: m = x_src @ W + b ; agg = scatter_add(m[src[e]] -> dst[e])
//   h_paper  = relu(relu(agg_cites) + agg_writes) ; h_author = relu(agg_writtenby)
// R2: tf32 MMA for 128x128 GEMMs, red.global.add.v4.f32 scatters.
// ---------------------------------------------------------------------------

#define N_PAPER_MAX 200000
#define N_AUTHOR_MAX 100000

__device__ float g_m[N_PAPER_MAX * 128];
__device__ float g_h1p[N_PAPER_MAX * 128];
__device__ float g_h1a[N_AUTHOR_MAX * 128];

__device__ __forceinline__ float tf32r(float x) {
    float r;
    asm("cvt.rna.tf32.f32 %0, %1;" : "=f"(r) : "f"(x));
    return r;
}

__device__ __forceinline__ void mma_tf32(float& c0, float& c1, float& c2, float& c3,
                                         uint32_t a0, uint32_t a1, uint32_t a2, uint32_t a3,
                                         uint32_t b0, uint32_t b1) {
    asm volatile(
        "mma.sync.aligned.m16n8k8.row.col.f32.tf32.tf32.f32 "
        "{%0,%1,%2,%3}, {%4,%5,%6,%7}, {%8,%9}, {%0,%1,%2,%3};"
        : "+f"(c0), "+f"(c1), "+f"(c2), "+f"(c3)
        : "r"(a0), "r"(a1), "r"(a2), "r"(a3), "r"(b0), "r"(b1));
}

__device__ __forceinline__ void red_add_v4(float* p, float4 v) {
    asm volatile("red.global.add.v4.f32 [%0], {%1,%2,%3,%4};"
                 :: "l"(p), "f"(v.x), "f"(v.y), "f"(v.z), "f"(v.w) : "memory");
}

// ---------------------------------------------------------------------------
// tf32 GEMM + bias: Y[M,128] = X[M,128] @ W[128,128] + b
// Block: 256 thr (8 warps), tile 128 rows x 128 cols. Warp w: rows [w*16, w*16+16).
// ---------------------------------------------------------------------------
__global__ void gemm_bias_128_tf32(const float* __restrict__ X, const float* __restrict__ W,
                                   const float* __restrict__ b, float* __restrict__ Y, int M) {
    __shared__ float xs[128][33];   // [row][k] padded
    __shared__ float ws[32][132];   // [k][col] padded
    __shared__ float bs[128];

    const int tid = threadIdx.x;
    const int wid = tid >> 5, lane = tid & 31;
    const int g = lane >> 2, tg = lane & 3;
    const int row_base = blockIdx.x * 128;
    const int mrow = wid * 16;

    if (tid < 128) bs[tid] = b[tid];

    float acc[16][4];
#pragma unroll
    for (int nt = 0; nt < 16; nt++)
#pragma unroll
        for (int j = 0; j < 4; j++) acc[nt][j] = 0.f;

    for (int kc = 0; kc < 128; kc += 32) {
        // X chunk: 128 rows x 32 k = 1024 float4
#pragma unroll
        for (int i = 0; i < 4; i++) {
            int idx = tid + 256 * i;
            int r = idx >> 3, c4 = idx & 7;
            int gr = row_base + r;
            float4 v = make_float4(0.f, 0.f, 0.f, 0.f);
            if (gr < M) v = reinterpret_cast<const float4*>(X + (long)gr * 128 + kc)[c4];
            xs[r][c4 * 4 + 0] = tf32r(v.x);
            xs[r][c4 * 4 + 1] = tf32r(v.y);
            xs[r][c4 * 4 + 2] = tf32r(v.z);
            xs[r][c4 * 4 + 3] = tf32r(v.w);
        }
        // W chunk: 32 k x 128 cols = 1024 float4
#pragma unroll
        for (int i = 0; i < 4; i++) {
            int idx = tid + 256 * i;
            int r = idx >> 5, c4 = idx & 31;
            float4 v = reinterpret_cast<const float4*>(W + (long)(kc + r) * 128)[c4];
            ws[r][c4 * 4 + 0] = tf32r(v.x);
            ws[r][c4 * 4 + 1] = tf32r(v.y);
            ws[r][c4 * 4 + 2] = tf32r(v.z);
            ws[r][c4 * 4 + 3] = tf32r(v.w);
        }
        __syncthreads();

#pragma unroll
        for (int ks = 0; ks < 4; ks++) {
            const int k0 = ks * 8;
            uint32_t a0 = __float_as_uint(xs[mrow + g][k0 + tg]);
            uint32_t a1 = __float_as_uint(xs[mrow + 8 + g][k0 + tg]);
            uint32_t a2 = __float_as_uint(xs[mrow + g][k0 + tg + 4]);
            uint32_t a3 = __float_as_uint(xs[mrow + 8 + g][k0 + tg + 4]);
#pragma unroll
            for (int nt = 0; nt < 16; nt++) {
                uint32_t b0 = __float_as_uint(ws[k0 + tg][nt * 8 + g]);
                uint32_t b1 = __float_as_uint(ws[k0 + tg + 4][nt * 8 + g]);
                mma_tf32(acc[nt][0], acc[nt][1], acc[nt][2], acc[nt][3],
                         a0, a1, a2, a3, b0, b1);
            }
        }
        __syncthreads();
    }

    const int r0 = row_base + mrow + g;
    const int r1 = r0 + 8;
#pragma unroll
    for (int nt = 0; nt < 16; nt++) {
        int c = nt * 8 + tg * 2;
        if (r0 < M) {
            float2 v = make_float2(acc[nt][0] + bs[c], acc[nt][1] + bs[c + 1]);
            *reinterpret_cast<float2*>(Y + (long)r0 * 128 + c) = v;
        }
        if (r1 < M) {
            float2 v = make_float2(acc[nt][2] + bs[c], acc[nt][3] + bs[c + 1]);
            *reinterpret_cast<float2*>(Y + (long)r1 * 128 + c) = v;
        }
    }
}

// ---------------------------------------------------------------------------
// GEMM + bias, N=16, K=128 (fp32, memory-bound).
// ---------------------------------------------------------------------------
__global__ void gemm_bias_16(const float* __restrict__ X, const float* __restrict__ W,
                             const float* __restrict__ b, float* __restrict__ Y, int M) {
    __shared__ float xs[128][33];
    __shared__ float ws[32][16];
    __shared__ float bs[16];

    int tid = threadIdx.x;
    int tx = tid & 15;
    int ty = tid >> 4;
    int row_base = blockIdx.x * 128;

    if (tid < 16) bs[tid] = b[tid];

    float acc[8];
#pragma unroll
    for (int i = 0; i < 8; i++) acc[i] = 0.f;

    for (int kc = 0; kc < 128; kc += 32) {
#pragma unroll
        for (int i = 0; i < 16; i++) {
            int idx = tid + 256 * i;
            int r = idx >> 5, c = idx & 31;
            int gr = row_base + r;
            xs[r][c] = (gr < M) ? X[(long)gr * 128 + kc + c] : 0.f;
        }
#pragma unroll
        for (int i = 0; i < 2; i++) {
            int idx = tid + 256 * i;
            int r = idx >> 4, c = idx & 15;
            ws[r][c] = W[(long)(kc + r) * 16 + c];
        }
        __syncthreads();

#pragma unroll
        for (int k = 0; k < 32; k++) {
            float wv = ws[k][tx];
#pragma unroll
            for (int rm = 0; rm < 8; rm++)
                acc[rm] += xs[ty * 8 + rm][k] * wv;
        }
        __syncthreads();
    }

#pragma unroll
    for (int rm = 0; rm < 8; rm++) {
        int gr = row_base + ty * 8 + rm;
        if (gr < M) Y[(long)gr * 16 + tx] = acc[rm] + bs[tx];
    }
}

// ---------------------------------------------------------------------------
// Scatter-add with vector reductions.
// ---------------------------------------------------------------------------
__global__ void scatter_add_128(const float* __restrict__ m, const int* __restrict__ src,
                                const int* __restrict__ dst, float* __restrict__ out, int E) {
    long idx = (long)blockIdx.x * blockDim.x + threadIdx.x;
    if (idx >= (long)E * 32) return;
    int e = (int)(idx >> 5);
    int q = (int)(idx & 31);
    int s = __ldg(src + e), d = __ldg(dst + e);
    float4 v = __ldg(reinterpret_cast<const float4*>(m + (long)s * 128) + q);
    red_add_v4(out + (long)d * 128 + q * 4, v);
}

__global__ void scatter_add_16(const float* __restrict__ m, const int* __restrict__ src,
                               const int* __restrict__ dst, float* __restrict__ out, int E) {
    long idx = (long)blockIdx.x * blockDim.x + threadIdx.x;
    if (idx >= (long)E * 4) return;
    int e = (int)(idx >> 2);
    int q = (int)(idx & 3);
    int s = __ldg(src + e), d = __ldg(dst + e);
    float4 v = __ldg(reinterpret_cast<const float4*>(m + (long)s * 16) + q);
    red_add_v4(out + (long)d * 16 + q * 4, v);
}

// ---------------------------------------------------------------------------
__global__ void relu4_kernel(float4* __restrict__ p, long n4) {
    long i = (long)blockIdx.x * blockDim.x + threadIdx.x;
    if (i < n4) {
        float4 v = p[i];
        v.x = fmaxf(v.x, 0.f); v.y = fmaxf(v.y, 0.f);
        v.z = fmaxf(v.z, 0.f); v.w = fmaxf(v.w, 0.f);
        p[i] = v;
    }
}

static inline int cdiv(long a, long b) { return (int)((a + b - 1) / b); }

// ---------------------------------------------------------------------------
extern "C" void kernel_launch(void* const* d_in, const int* in_sizes, int n_in,
                              void* d_out, int out_size) {
    const float* embed_paper  = (const float*)d_in[0];
    const float* embed_author = (const float*)d_in[1];
    const float* W1_cites     = (const float*)d_in[2];
    const float* b1_cites     = (const float*)d_in[3];
    const float* W1_writtenby = (const float*)d_in[4];
    const float* b1_writtenby = (const float*)d_in[5];
    const float* W1_writes    = (const float*)d_in[6];
    const float* b1_writes    = (const float*)d_in[7];
    const float* W2_cites     = (const float*)d_in[8];
    const float* b2_cites     = (const float*)d_in[9];
    const float* W2_writtenby = (const float*)d_in[10];
    const float* b2_writtenby = (const float*)d_in[11];
    const float* W2_writes    = (const float*)d_in[12];
    const float* b2_writes    = (const float*)d_in[13];
    const int* cites_src      = (const int*)d_in[14];
    const int* cites_dst      = (const int*)d_in[15];
    const int* writtenby_src  = (const int*)d_in[16];
    const int* writtenby_dst  = (const int*)d_in[17];
    const int* writes_src     = (const int*)d_in[18];
    const int* writes_dst     = (const int*)d_in[19];

    const int n_paper  = in_sizes[0] / 128;
    const int n_author = in_sizes[1] / 128;
    const int E_cites  = in_sizes[14];
    const int E_wb     = in_sizes[16];
    const int E_wr     = in_sizes[18];

    float* m;   cudaGetSymbolAddress((void**)&m,   g_m);
    float* h1p; cudaGetSymbolAddress((void**)&h1p, g_h1p);
    float* h1a; cudaGetSymbolAddress((void**)&h1a, g_h1a);

    float* out_paper  = (float*)d_out;
    float* out_author = (float*)d_out + (long)n_paper * 16;

    const long np128 = (long)n_paper * 128;
    const long na128 = (long)n_author * 128;

    // ---------------- Layer 1 (D=128) ----------------
    cudaMemsetAsync(h1p, 0, np128 * sizeof(float));
    cudaMemsetAsync(h1a, 0, na128 * sizeof(float));

    // cites: paper -> paper
    gemm_bias_128_tf32<<<cdiv(n_paper, 128), 256>>>(embed_paper, W1_cites, b1_cites, m, n_paper);
    scatter_add_128<<<cdiv((long)E_cites * 32, 256), 256>>>(m, cites_src, cites_dst, h1p, E_cites);
    relu4_kernel<<<cdiv(np128 / 4, 256), 256>>>((float4*)h1p, np128 / 4);

    // writes: author -> paper
    gemm_bias_128_tf32<<<cdiv(n_author, 128), 256>>>(embed_author, W1_writes, b1_writes, m, n_author);
    scatter_add_128<<<cdiv((long)E_wr * 32, 256), 256>>>(m, writes_src, writes_dst, h1p, E_wr);
    relu4_kernel<<<cdiv(np128 / 4, 256), 256>>>((float4*)h1p, np128 / 4);

    // writtenby: paper -> author
    gemm_bias_128_tf32<<<cdiv(n_paper, 128), 256>>>(embed_paper, W1_writtenby, b1_writtenby, m, n_paper);
    scatter_add_128<<<cdiv((long)E_wb * 32, 256), 256>>>(m, writtenby_src, writtenby_dst, h1a, E_wb);
    relu4_kernel<<<cdiv(na128 / 4, 256), 256>>>((float4*)h1a, na128 / 4);

    // ---------------- Layer 2 (D=16) ----------------
    cudaMemsetAsync(d_out, 0, (long)out_size * sizeof(float));

    const long np16 = (long)n_paper * 16;
    const long na16 = (long)n_author * 16;

    // cites: h1_paper -> paper
    gemm_bias_16<<<cdiv(n_paper, 128), 256>>>(h1p, W2_cites, b2_cites, m, n_paper);
    scatter_add_16<<<cdiv((long)E_cites * 4, 256), 256>>>(m, cites_src, cites_dst, out_paper, E_cites);
    relu4_kernel<<<cdiv(np16 / 4, 256), 256>>>((float4*)out_paper, np16 / 4);

    // writes: h1_author -> paper
    gemm_bias_16<<<cdiv(n_author, 128), 256>>>(h1a, W2_writes, b2_writes, m, n_author);
    scatter_add_16<<<cdiv((long)E_wr * 4, 256), 256>>>(m, writes_src, writes_dst, out_paper, E_wr);
    relu4_kernel<<<cdiv(np16 / 4, 256), 256>>>((float4*)out_paper, np16 / 4);

    // writtenby: h1_paper -> author
    gemm_bias_16<<<cdiv(n_paper, 128), 256>>>(h1p, W2_writtenby, b2_writtenby, m, n_paper);
    scatter_add_16<<<cdiv((long)E_wb * 4, 256), 256>>>(m, writtenby_src, writtenby_dst, out_author, E_wb);
    relu4_kernel<<<cdiv(na16 / 4, 256), 256>>>((float4*)out_author, na16 / 4);
}

// round 3
// speedup vs baseline: 2.3386x; 1.2673x over previous
#include <cuda_runtime.h>
#include <cuda_bf16.h>
#include <cstdint>

// ---------------------------------------------------------------------------
// EntityClassify: 2-layer hetero R-GCN.
// R3: CSR gather-sum (no atomics in aggregation, fused prev+ReLU),
//     tf32 MMA GEMM with 32x64 warp tiles.
// ---------------------------------------------------------------------------

#define N_PAPER_MAX 200000
#define N_AUTHOR_MAX 100000
#define E_MAX 500000

__device__ float g_m[N_PAPER_MAX * 128];
__device__ float g_h1p[N_PAPER_MAX * 128];
__device__ float g_h1a[N_AUTHOR_MAX * 128];

// CSR scratch: 3 relations (0=cites->paper, 1=writtenby->author, 2=writes->paper)
__device__ int g_offs0[N_PAPER_MAX + 64];
__device__ int g_offs1[N_AUTHOR_MAX + 64];
__device__ int g_offs2[N_PAPER_MAX + 64];
__device__ int g_csr0[E_MAX];
__device__ int g_csr1[E_MAX];
__device__ int g_csr2[E_MAX];
__device__ int g_deg[N_PAPER_MAX + 64];
__device__ int g_cur[N_PAPER_MAX + 64];
__device__ int g_bsum[128];

__device__ __forceinline__ float tf32r(float x) {
    float r;
    asm("cvt.rna.tf32.f32 %0, %1;" : "=f"(r) : "f"(x));
    return r;
}

__device__ __forceinline__ void mma_tf32(float* c,
                                         uint32_t a0, uint32_t a1, uint32_t a2, uint32_t a3,
                                         uint32_t b0, uint32_t b1) {
    asm volatile(
        "mma.sync.aligned.m16n8k8.row.col.f32.tf32.tf32.f32 "
        "{%0,%1,%2,%3}, {%4,%5,%6,%7}, {%8,%9}, {%0,%1,%2,%3};"
        : "+f"(c[0]), "+f"(c[1]), "+f"(c[2]), "+f"(c[3])
        : "r"(a0), "r"(a1), "r"(a2), "r"(a3), "r"(b0), "r"(b1));
}

// ---------------------------------------------------------------------------
// CSR build kernels
// ---------------------------------------------------------------------------
__global__ void hist_kernel(const int* __restrict__ dst, int* __restrict__ deg, int E) {
    int i = blockIdx.x * blockDim.x + threadIdx.x;
    if (i < E) atomicAdd(&deg[dst[i]], 1);
}

// Per-block exclusive scan over 4096 ints; writes block total to bsum.
__global__ void scan_block(const int* __restrict__ deg, int* __restrict__ offs,
                           int* __restrict__ bsum, int n) {
    const int base = blockIdx.x * 4096;
    const int i0 = base + threadIdx.x * 16;
    int vals[16];
    int s = 0;
#pragma unroll
    for (int j = 0; j < 16; j++) {
        int idx = i0 + j;
        int v = (idx < n) ? deg[idx] : 0;
        vals[j] = s;
        s += v;
    }
    int lane = threadIdx.x & 31, wid = threadIdx.x >> 5;
    int x = s;
#pragma unroll
    for (int o = 1; o < 32; o <<= 1) {
        int y = __shfl_up_sync(0xffffffffu, x, o);
        if (lane >= o) x += y;
    }
    __shared__ int wsum[8];
    if (lane == 31) wsum[wid] = x;
    __syncthreads();
    if (wid == 0 && lane < 8) {
        int y = wsum[lane];
#pragma unroll
        for (int o = 1; o < 8; o <<= 1) {
            int z = __shfl_up_sync(0xffu, y, o);
            if (lane >= o) y += z;
        }
        wsum[lane] = y;
    }
    __syncthreads();
    int thread_excl = (x - s) + (wid > 0 ? wsum[wid - 1] : 0);
#pragma unroll
    for (int j = 0; j < 16; j++) {
        int idx = i0 + j;
        if (idx < n) offs[idx] = thread_excl + vals[j];
    }
    if (threadIdx.x == 255) bsum[blockIdx.x] = thread_excl + s;
}

__global__ void scan_bsums(int* __restrict__ bsum, int nb) {
    __shared__ int tmp[128];
    int t = threadIdx.x;
    tmp[t] = (t < nb) ? bsum[t] : 0;
    __syncthreads();
    if (t == 0) {
        int s = 0;
        for (int i = 0; i < nb; i++) { int x = tmp[i]; tmp[i] = s; s += x; }
    }
    __syncthreads();
    if (t < nb) bsum[t] = tmp[t];
}

__global__ void scan_add(int* __restrict__ offs, const int* __restrict__ bsum,
                         int* __restrict__ cur, int n, int E) {
    int i = blockIdx.x * blockDim.x + threadIdx.x;
    if (i < n) {
        int v = offs[i] + bsum[i >> 12];
        offs[i] = v;
        cur[i] = v;
    }
    if (i == 0) offs[n] = E;
}

__global__ void fill_kernel(const int* __restrict__ src, const int* __restrict__ dst,
                            int* __restrict__ cur, int* __restrict__ csr_src, int E) {
    int i = blockIdx.x * blockDim.x + threadIdx.x;
    if (i < E) {
        int p = atomicAdd(&cur[dst[i]], 1);
        csr_src[p] = src[i];
    }
}

// ---------------------------------------------------------------------------
// CSR gather-sum, fused prev-add + ReLU. One warp per dst row (F=128).
// ---------------------------------------------------------------------------
__global__ void gather_sum_128(const float* __restrict__ m, const int* __restrict__ offs,
                               const int* __restrict__ csr_src, const float* __restrict__ prev,
                               float* __restrict__ out, int n_dst) {
    int d = blockIdx.x * (blockDim.x >> 5) + (threadIdx.x >> 5);
    if (d >= n_dst) return;
    int lane = threadIdx.x & 31;
    int s0 = __ldg(offs + d), s1 = __ldg(offs + d + 1);
    float4 acc = make_float4(0.f, 0.f, 0.f, 0.f);
    for (int j = s0; j < s1; j++) {
        int s = __ldg(csr_src + j);
        float4 v = __ldg(reinterpret_cast<const float4*>(m + (long)s * 128) + lane);
        acc.x += v.x; acc.y += v.y; acc.z += v.z; acc.w += v.w;
    }
    if (prev) {
        float4 p = __ldg(reinterpret_cast<const float4*>(prev + (long)d * 128) + lane);
        acc.x += p.x; acc.y += p.y; acc.z += p.z; acc.w += p.w;
    }
    acc.x = fmaxf(acc.x, 0.f); acc.y = fmaxf(acc.y, 0.f);
    acc.z = fmaxf(acc.z, 0.f); acc.w = fmaxf(acc.w, 0.f);
    reinterpret_cast<float4*>(out + (long)d * 128)[lane] = acc;
}

// F=16: 4 threads per dst row.
__global__ void gather_sum_16(const float* __restrict__ m, const int* __restrict__ offs,
                              const int* __restrict__ csr_src, const float* __restrict__ prev,
                              float* __restrict__ out, int n_dst) {
    long idx = (long)blockIdx.x * blockDim.x + threadIdx.x;
    if (idx >= (long)n_dst * 4) return;
    int d = (int)(idx >> 2), q = (int)(idx & 3);
    int s0 = __ldg(offs + d), s1 = __ldg(offs + d + 1);
    float4 acc = make_float4(0.f, 0.f, 0.f, 0.f);
    for (int j = s0; j < s1; j++) {
        int s = __ldg(csr_src + j);
        float4 v = __ldg(reinterpret_cast<const float4*>(m + (long)s * 16) + q);
        acc.x += v.x; acc.y += v.y; acc.z += v.z; acc.w += v.w;
    }
    if (prev) {
        float4 p = __ldg(reinterpret_cast<const float4*>(prev + (long)d * 16) + q);
        acc.x += p.x; acc.y += p.y; acc.z += p.z; acc.w += p.w;
    }
    acc.x = fmaxf(acc.x, 0.f); acc.y = fmaxf(acc.y, 0.f);
    acc.z = fmaxf(acc.z, 0.f); acc.w = fmaxf(acc.w, 0.f);
    reinterpret_cast<float4*>(out + (long)d * 16)[q] = acc;
}

// ---------------------------------------------------------------------------
// tf32 GEMM + bias: Y[M,128] = X[M,128] @ W[128,128] + b
// Block: 256 thr, tile 128x128, warp tile 32 rows x 64 cols (warps 4x2).
// ---------------------------------------------------------------------------
__global__ __launch_bounds__(256, 2)
void gemm_bias_128_tf32(const float* __restrict__ X, const float* __restrict__ W,
                        const float* __restrict__ b, float* __restrict__ Y, int M) {
    __shared__ float xs[128][33];
    __shared__ float ws[32][132];
    __shared__ float bs[128];

    const int tid = threadIdx.x;
    const int wid = tid >> 5, lane = tid & 31;
    const int g = lane >> 2, tg = lane & 3;
    const int wm = wid >> 1, wn = wid & 1;
    const int row_base = blockIdx.x * 128;
    const int wrow = wm * 32;
    const int wcol = wn * 64;

    if (tid < 128) bs[tid] = b[tid];

    float acc[2][8][4];
#pragma unroll
    for (int mi = 0; mi < 2; mi++)
#pragma unroll
        for (int nt = 0; nt < 8; nt++)
#pragma unroll
            for (int j = 0; j < 4; j++) acc[mi][nt][j] = 0.f;

    for (int kc = 0; kc < 128; kc += 32) {
#pragma unroll
        for (int i = 0; i < 4; i++) {
            int idx = tid + 256 * i;
            int r = idx >> 3, c4 = idx & 7;
            int gr = row_base + r;
            float4 v = make_float4(0.f, 0.f, 0.f, 0.f);
            if (gr < M) v = __ldg(reinterpret_cast<const float4*>(X + (long)gr * 128 + kc) + c4);
            xs[r][c4 * 4 + 0] = tf32r(v.x);
            xs[r][c4 * 4 + 1] = tf32r(v.y);
            xs[r][c4 * 4 + 2] = tf32r(v.z);
            xs[r][c4 * 4 + 3] = tf32r(v.w);
        }
#pragma unroll
        for (int i = 0; i < 4; i++) {
            int idx = tid + 256 * i;
            int r = idx >> 5, c4 = idx & 31;
            float4 v = __ldg(reinterpret_cast<const float4*>(W + (long)(kc + r) * 128) + c4);
            ws[r][c4 * 4 + 0] = tf32r(v.x);
            ws[r][c4 * 4 + 1] = tf32r(v.y);
            ws[r][c4 * 4 + 2] = tf32r(v.z);
            ws[r][c4 * 4 + 3] = tf32r(v.w);
        }
        __syncthreads();

#pragma unroll
        for (int ks = 0; ks < 4; ks++) {
            const int k0 = ks * 8;
            uint32_t a[2][4];
#pragma unroll
            for (int mi = 0; mi < 2; mi++) {
                int r = wrow + mi * 16;
                a[mi][0] = __float_as_uint(xs[r + g][k0 + tg]);
                a[mi][1] = __float_as_uint(xs[r + 8 + g][k0 + tg]);
                a[mi][2] = __float_as_uint(xs[r + g][k0 + tg + 4]);
                a[mi][3] = __float_as_uint(xs[r + 8 + g][k0 + tg + 4]);
            }
#pragma unroll
            for (int nt = 0; nt < 8; nt++) {
                uint32_t b0 = __float_as_uint(ws[k0 + tg][wcol + nt * 8 + g]);
                uint32_t b1 = __float_as_uint(ws[k0 + tg + 4][wcol + nt * 8 + g]);
#pragma unroll
                for (int mi = 0; mi < 2; mi++)
                    mma_tf32(acc[mi][nt], a[mi][0], a[mi][1], a[mi][2], a[mi][3], b0, b1);
            }
        }
        __syncthreads();
    }

#pragma unroll
    for (int mi = 0; mi < 2; mi++) {
        int r0 = row_base + wrow + mi * 16 + g;
        int r1 = r0 + 8;
#pragma unroll
        for (int nt = 0; nt < 8; nt++) {
            int c = wcol + nt * 8 + tg * 2;
            if (r0 < M) {
                float2 v = make_float2(acc[mi][nt][0] + bs[c], acc[mi][nt][1] + bs[c + 1]);
                *reinterpret_cast<float2*>(Y + (long)r0 * 128 + c) = v;
            }
            if (r1 < M) {
                float2 v = make_float2(acc[mi][nt][2] + bs[c], acc[mi][nt][3] + bs[c + 1]);
                *reinterpret_cast<float2*>(Y + (long)r1 * 128 + c) = v;
            }
        }
    }
}

// ---------------------------------------------------------------------------
// GEMM + bias, N=16, K=128 (fp32, memory-bound).
// ---------------------------------------------------------------------------
__global__ void gemm_bias_16(const float* __restrict__ X, const float* __restrict__ W,
                             const float* __restrict__ b, float* __restrict__ Y, int M) {
    __shared__ float xs[128][33];
    __shared__ float ws[32][16];
    __shared__ float bs[16];

    int tid = threadIdx.x;
    int tx = tid & 15;
    int ty = tid >> 4;
    int row_base = blockIdx.x * 128;

    if (tid < 16) bs[tid] = b[tid];

    float acc[8];
#pragma unroll
    for (int i = 0; i < 8; i++) acc[i] = 0.f;

    for (int kc = 0; kc < 128; kc += 32) {
#pragma unroll
        for (int i = 0; i < 16; i++) {
            int idx = tid + 256 * i;
            int r = idx >> 5, c = idx & 31;
            int gr = row_base + r;
            xs[r][c] = (gr < M) ? X[(long)gr * 128 + kc + c] : 0.f;
        }
#pragma unroll
        for (int i = 0; i < 2; i++) {
            int idx = tid + 256 * i;
            int r = idx >> 4, c = idx & 15;
            ws[r][c] = W[(long)(kc + r) * 16 + c];
        }
        __syncthreads();

#pragma unroll
        for (int k = 0; k < 32; k++) {
            float wv = ws[k][tx];
#pragma unroll
            for (int rm = 0; rm < 8; rm++)
                acc[rm] += xs[ty * 8 + rm][k] * wv;
        }
        __syncthreads();
    }

#pragma unroll
    for (int rm = 0; rm < 8; rm++) {
        int gr = row_base + ty * 8 + rm;
        if (gr < M) Y[(long)gr * 16 + tx] = acc[rm] + bs[tx];
    }
}

static inline int cdiv(long a, long b) { return (int)((a + b - 1) / b); }

static void build_csr(const int* src, const int* dst, int E, int n_dst,
                      int* offs, int* csr_src, int* deg, int* cur, int* bsum) {
    cudaMemsetAsync(deg, 0, (size_t)n_dst * sizeof(int));
    hist_kernel<<<cdiv(E, 256), 256>>>(dst, deg, E);
    int nb = cdiv(n_dst, 4096);
    scan_block<<<nb, 256>>>(deg, offs, bsum, n_dst);
    scan_bsums<<<1, 128>>>(bsum, nb);
    scan_add<<<cdiv(n_dst, 256), 256>>>(offs, bsum, cur, n_dst, E);
    fill_kernel<<<cdiv(E, 256), 256>>>(src, dst, cur, csr_src, E);
}

// ---------------------------------------------------------------------------
extern "C" void kernel_launch(void* const* d_in, const int* in_sizes, int n_in,
                              void* d_out, int out_size) {
    const float* embed_paper  = (const float*)d_in[0];
    const float* embed_author = (const float*)d_in[1];
    const float* W1_cites     = (const float*)d_in[2];
    const float* b1_cites     = (const float*)d_in[3];
    const float* W1_writtenby = (const float*)d_in[4];
    const float* b1_writtenby = (const float*)d_in[5];
    const float* W1_writes    = (const float*)d_in[6];
    const float* b1_writes    = (const float*)d_in[7];
    const float* W2_cites     = (const float*)d_in[8];
    const float* b2_cites     = (const float*)d_in[9];
    const float* W2_writtenby = (const float*)d_in[10];
    const float* b2_writtenby = (const float*)d_in[11];
    const float* W2_writes    = (const float*)d_in[12];
    const float* b2_writes    = (const float*)d_in[13];
    const int* cites_src      = (const int*)d_in[14];
    const int* cites_dst      = (const int*)d_in[15];
    const int* writtenby_src  = (const int*)d_in[16];
    const int* writtenby_dst  = (const int*)d_in[17];
    const int* writes_src     = (const int*)d_in[18];
    const int* writes_dst     = (const int*)d_in[19];

    const int n_paper  = in_sizes[0] / 128;
    const int n_author = in_sizes[1] / 128;
    const int E_cites  = in_sizes[14];
    const int E_wb     = in_sizes[16];
    const int E_wr     = in_sizes[18];

    float *m, *h1p, *h1a;
    cudaGetSymbolAddress((void**)&m,   g_m);
    cudaGetSymbolAddress((void**)&h1p, g_h1p);
    cudaGetSymbolAddress((void**)&h1a, g_h1a);
    int *offs0, *offs1, *offs2, *csr0, *csr1, *csr2, *deg, *cur, *bsum;
    cudaGetSymbolAddress((void**)&offs0, g_offs0);
    cudaGetSymbolAddress((void**)&offs1, g_offs1);
    cudaGetSymbolAddress((void**)&offs2, g_offs2);
    cudaGetSymbolAddress((void**)&csr0, g_csr0);
    cudaGetSymbolAddress((void**)&csr1, g_csr1);
    cudaGetSymbolAddress((void**)&csr2, g_csr2);
    cudaGetSymbolAddress((void**)&deg,  g_deg);
    cudaGetSymbolAddress((void**)&cur,  g_cur);
    cudaGetSymbolAddress((void**)&bsum, g_bsum);

    float* out_paper  = (float*)d_out;
    float* out_author = (float*)d_out + (long)n_paper * 16;

    // ---------------- CSR builds (reused by both layers) ----------------
    build_csr(cites_src,     cites_dst,     E_cites, n_paper,  offs0, csr0, deg, cur, bsum);
    build_csr(writtenby_src, writtenby_dst, E_wb,    n_author, offs1, csr1, deg, cur, bsum);
    build_csr(writes_src,    writes_dst,    E_wr,    n_paper,  offs2, csr2, deg, cur, bsum);

    // ---------------- Layer 1 (D=128) ----------------
    // cites: paper -> paper, h1p = relu(agg)
    gemm_bias_128_tf32<<<cdiv(n_paper, 128), 256>>>(embed_paper, W1_cites, b1_cites, m, n_paper);
    gather_sum_128<<<cdiv(n_paper, 8), 256>>>(m, offs0, csr0, nullptr, h1p, n_paper);

    // writes: author -> paper, h1p = relu(h1p + agg)
    gemm_bias_128_tf32<<<cdiv(n_author, 128), 256>>>(embed_author, W1_writes, b1_writes, m, n_author);
    gather_sum_128<<<cdiv(n_paper, 8), 256>>>(m, offs2, csr2, h1p, h1p, n_paper);

    // writtenby: paper -> author, h1a = relu(agg)
    gemm_bias_128_tf32<<<cdiv(n_paper, 128), 256>>>(embed_paper, W1_writtenby, b1_writtenby, m, n_paper);
    gather_sum_128<<<cdiv(n_author, 8), 256>>>(m, offs1, csr1, nullptr, h1a, n_author);

    // ---------------- Layer 2 (D=16) ----------------
    // cites
    gemm_bias_16<<<cdiv(n_paper, 128), 256>>>(h1p, W2_cites, b2_cites, m, n_paper);
    gather_sum_16<<<cdiv((long)n_paper * 4, 256), 256>>>(m, offs0, csr0, nullptr, out_paper, n_paper);

    // writes
    gemm_bias_16<<<cdiv(n_author, 128), 256>>>(h1a, W2_writes, b2_writes, m, n_author);
    gather_sum_16<<<cdiv((long)n_paper * 4, 256), 256>>>(m, offs2, csr2, out_paper, out_paper, n_paper);

    // writtenby
    gemm_bias_16<<<cdiv(n_paper, 128), 256>>>(h1p, W2_writtenby, b2_writtenby, m, n_paper);
    gather_sum_16<<<cdiv((long)n_author * 4, 256), 256>>>(m, offs1, csr1, nullptr, out_author, n_author);
}

// round 4
// speedup vs baseline: 2.5026x; 1.0701x over previous
#include <cuda_runtime.h>
#include <cuda_bf16.h>
#include <cstdint>

// ---------------------------------------------------------------------------
// EntityClassify: 2-layer hetero R-GCN.
// R4: bf16 m16n8k16 MMA GEMM (whole-K-resident smem, single sync pair),
//     CSR gather-sum aggregation (fused prev+ReLU).
// ---------------------------------------------------------------------------

#define N_PAPER_MAX 200000
#define N_AUTHOR_MAX 100000
#define E_MAX 500000

__device__ float g_m[N_PAPER_MAX * 128];
__device__ float g_h1p[N_PAPER_MAX * 128];
__device__ float g_h1a[N_AUTHOR_MAX * 128];

__device__ int g_offs0[N_PAPER_MAX + 64];
__device__ int g_offs1[N_AUTHOR_MAX + 64];
__device__ int g_offs2[N_PAPER_MAX + 64];
__device__ int g_csr0[E_MAX];
__device__ int g_csr1[E_MAX];
__device__ int g_csr2[E_MAX];
__device__ int g_deg[N_PAPER_MAX + 64];
__device__ int g_cur[N_PAPER_MAX + 64];
__device__ int g_bsum[128];

__device__ __forceinline__ uint32_t pack_bf2(float a, float b) {
    __nv_bfloat162 p = __floats2bfloat162_rn(a, b);
    return *reinterpret_cast<uint32_t*>(&p);
}

__device__ __forceinline__ void mma_bf16(float* c, const uint32_t* a,
                                         uint32_t b0, uint32_t b1) {
    asm volatile(
        "mma.sync.aligned.m16n8k16.row.col.f32.bf16.bf16.f32 "
        "{%0,%1,%2,%3}, {%4,%5,%6,%7}, {%8,%9}, {%0,%1,%2,%3};"
        : "+f"(c[0]), "+f"(c[1]), "+f"(c[2]), "+f"(c[3])
        : "r"(a[0]), "r"(a[1]), "r"(a[2]), "r"(a[3]), "r"(b0), "r"(b1));
}

// ---------------------------------------------------------------------------
// CSR build kernels
// ---------------------------------------------------------------------------
__global__ void hist_kernel(const int* __restrict__ dst, int* __restrict__ deg, int E) {
    int i = blockIdx.x * blockDim.x + threadIdx.x;
    if (i < E) atomicAdd(&deg[dst[i]], 1);
}

__global__ void scan_block(const int* __restrict__ deg, int* __restrict__ offs,
                           int* __restrict__ bsum, int n) {
    const int base = blockIdx.x * 4096;
    const int i0 = base + threadIdx.x * 16;
    int vals[16];
    int s = 0;
#pragma unroll
    for (int j = 0; j < 16; j++) {
        int idx = i0 + j;
        int v = (idx < n) ? deg[idx] : 0;
        vals[j] = s;
        s += v;
    }
    int lane = threadIdx.x & 31, wid = threadIdx.x >> 5;
    int x = s;
#pragma unroll
    for (int o = 1; o < 32; o <<= 1) {
        int y = __shfl_up_sync(0xffffffffu, x, o);
        if (lane >= o) x += y;
    }
    __shared__ int wsum[8];
    if (lane == 31) wsum[wid] = x;
    __syncthreads();
    if (wid == 0 && lane < 8) {
        int y = wsum[lane];
#pragma unroll
        for (int o = 1; o < 8; o <<= 1) {
            int z = __shfl_up_sync(0xffu, y, o);
            if (lane >= o) y += z;
        }
        wsum[lane] = y;
    }
    __syncthreads();
    int thread_excl = (x - s) + (wid > 0 ? wsum[wid - 1] : 0);
#pragma unroll
    for (int j = 0; j < 16; j++) {
        int idx = i0 + j;
        if (idx < n) offs[idx] = thread_excl + vals[j];
    }
    if (threadIdx.x == 255) bsum[blockIdx.x] = thread_excl + s;
}

__global__ void scan_bsums(int* __restrict__ bsum, int nb) {
    __shared__ int tmp[128];
    int t = threadIdx.x;
    tmp[t] = (t < nb) ? bsum[t] : 0;
    __syncthreads();
    if (t == 0) {
        int s = 0;
        for (int i = 0; i < nb; i++) { int x = tmp[i]; tmp[i] = s; s += x; }
    }
    __syncthreads();
    if (t < nb) bsum[t] = tmp[t];
}

__global__ void scan_add(int* __restrict__ offs, const int* __restrict__ bsum,
                         int* __restrict__ cur, int n, int E) {
    int i = blockIdx.x * blockDim.x + threadIdx.x;
    if (i < n) {
        int v = offs[i] + bsum[i >> 12];
        offs[i] = v;
        cur[i] = v;
    }
    if (i == 0) offs[n] = E;
}

__global__ void fill_kernel(const int* __restrict__ src, const int* __restrict__ dst,
                            int* __restrict__ cur, int* __restrict__ csr_src, int E) {
    int i = blockIdx.x * blockDim.x + threadIdx.x;
    if (i < E) {
        int p = atomicAdd(&cur[dst[i]], 1);
        csr_src[p] = src[i];
    }
}

// ---------------------------------------------------------------------------
// CSR gather-sum, fused prev-add + ReLU. One warp per dst row (F=128).
// ---------------------------------------------------------------------------
__global__ void gather_sum_128(const float* __restrict__ m, const int* __restrict__ offs,
                               const int* __restrict__ csr_src, const float* __restrict__ prev,
                               float* __restrict__ out, int n_dst) {
    int d = blockIdx.x * (blockDim.x >> 5) + (threadIdx.x >> 5);
    if (d >= n_dst) return;
    int lane = threadIdx.x & 31;
    int s0 = __ldg(offs + d), s1 = __ldg(offs + d + 1);
    float4 acc = make_float4(0.f, 0.f, 0.f, 0.f);
    for (int j = s0; j < s1; j++) {
        int s = __ldg(csr_src + j);
        float4 v = __ldg(reinterpret_cast<const float4*>(m + (long)s * 128) + lane);
        acc.x += v.x; acc.y += v.y; acc.z += v.z; acc.w += v.w;
    }
    if (prev) {
        float4 p = __ldg(reinterpret_cast<const float4*>(prev + (long)d * 128) + lane);
        acc.x += p.x; acc.y += p.y; acc.z += p.z; acc.w += p.w;
    }
    acc.x = fmaxf(acc.x, 0.f); acc.y = fmaxf(acc.y, 0.f);
    acc.z = fmaxf(acc.z, 0.f); acc.w = fmaxf(acc.w, 0.f);
    reinterpret_cast<float4*>(out + (long)d * 128)[lane] = acc;
}

__global__ void gather_sum_16(const float* __restrict__ m, const int* __restrict__ offs,
                              const int* __restrict__ csr_src, const float* __restrict__ prev,
                              float* __restrict__ out, int n_dst) {
    long idx = (long)blockIdx.x * blockDim.x + threadIdx.x;
    if (idx >= (long)n_dst * 4) return;
    int d = (int)(idx >> 2), q = (int)(idx & 3);
    int s0 = __ldg(offs + d), s1 = __ldg(offs + d + 1);
    float4 acc = make_float4(0.f, 0.f, 0.f, 0.f);
    for (int j = s0; j < s1; j++) {
        int s = __ldg(csr_src + j);
        float4 v = __ldg(reinterpret_cast<const float4*>(m + (long)s * 16) + q);
        acc.x += v.x; acc.y += v.y; acc.z += v.z; acc.w += v.w;
    }
    if (prev) {
        float4 p = __ldg(reinterpret_cast<const float4*>(prev + (long)d * 16) + q);
        acc.x += p.x; acc.y += p.y; acc.z += p.z; acc.w += p.w;
    }
    acc.x = fmaxf(acc.x, 0.f); acc.y = fmaxf(acc.y, 0.f);
    acc.z = fmaxf(acc.z, 0.f); acc.w = fmaxf(acc.w, 0.f);
    reinterpret_cast<float4*>(out + (long)d * 16)[q] = acc;
}

// ---------------------------------------------------------------------------
// bf16 GEMM + bias: Y[M,128] = bf16(X[M,128]) @ bf16(W[128,128]) + b
// Block 256 thr (8 warps, 4x2), tile 128x128, K=128 fully smem-resident.
// Dynamic smem: xs[128][68] u32 (bf16x2 along k) + wt[128][68] u32 (W^T).
// Stride 68 (== 4 mod 32) => mainloop fragment LDS hits 32 distinct banks.
// ---------------------------------------------------------------------------
#define XS_STRIDE 68
#define GEMM128_SMEM (2 * 128 * XS_STRIDE * 4)

__global__ void __launch_bounds__(256)
gemm_bias_128_bf16(const float* __restrict__ X, const float* __restrict__ W,
                   const float* __restrict__ b, float* __restrict__ Y, int M) {
    extern __shared__ uint32_t sm[];
    uint32_t* xs = sm;                       // 128 * 68
    uint32_t* wt = sm + 128 * XS_STRIDE;     // 128 * 68 (W transposed, [n][kpair])
    __shared__ float bs[128];

    const int tid = threadIdx.x;
    const int wid = tid >> 5, lane = tid & 31;
    const int g = lane >> 2, tg = lane & 3;
    const int wrow = (wid >> 1) * 32;
    const int wcol = (wid & 1) * 64;
    const int row_base = blockIdx.x * 128;

    if (tid < 128) bs[tid] = b[tid];

    // Load X tile -> bf16x2 smem
#pragma unroll
    for (int i = 0; i < 16; i++) {
        int idx = tid + 256 * i;             // 0..4095 (128 rows x 32 float4)
        int r = idx >> 5, c4 = idx & 31;
        int gr = row_base + r;
        float4 v = make_float4(0.f, 0.f, 0.f, 0.f);
        if (gr < M) v = __ldg(reinterpret_cast<const float4*>(X + (long)gr * 128) + c4);
        xs[r * XS_STRIDE + c4 * 2 + 0] = pack_bf2(v.x, v.y);
        xs[r * XS_STRIDE + c4 * 2 + 1] = pack_bf2(v.z, v.w);
    }

    // Load W -> transposed bf16x2 smem: wt[n][kp] = (W[2kp][n], W[2kp+1][n])
#pragma unroll
    for (int i = 0; i < 8; i++) {
        int u = tid + 256 * i;               // 0..2047
        int n4 = u >> 6;                     // 0..31 (group of 4 n)
        int kp = u & 63;                     // 0..63 (k pair)
        float4 wa = __ldg(reinterpret_cast<const float4*>(W + (long)(2 * kp) * 128) + n4);
        float4 wb = __ldg(reinterpret_cast<const float4*>(W + (long)(2 * kp + 1) * 128) + n4);
        wt[(n4 * 4 + 0) * XS_STRIDE + kp] = pack_bf2(wa.x, wb.x);
        wt[(n4 * 4 + 1) * XS_STRIDE + kp] = pack_bf2(wa.y, wb.y);
        wt[(n4 * 4 + 2) * XS_STRIDE + kp] = pack_bf2(wa.z, wb.z);
        wt[(n4 * 4 + 3) * XS_STRIDE + kp] = pack_bf2(wa.w, wb.w);
    }
    __syncthreads();

    float acc[2][8][4];
#pragma unroll
    for (int mi = 0; mi < 2; mi++)
#pragma unroll
        for (int nt = 0; nt < 8; nt++)
#pragma unroll
            for (int j = 0; j < 4; j++) acc[mi][nt][j] = 0.f;

#pragma unroll
    for (int s = 0; s < 8; s++) {            // k-steps of 16 (8 k-pairs each)
        uint32_t a[2][4];
#pragma unroll
        for (int mi = 0; mi < 2; mi++) {
            int rb = (wrow + mi * 16 + g) * XS_STRIDE + s * 8;
            int rb8 = rb + 8 * XS_STRIDE;
            a[mi][0] = xs[rb + tg];
            a[mi][1] = xs[rb8 + tg];
            a[mi][2] = xs[rb + 4 + tg];
            a[mi][3] = xs[rb8 + 4 + tg];
        }
#pragma unroll
        for (int nt = 0; nt < 8; nt++) {
            int cb = (wcol + nt * 8 + g) * XS_STRIDE + s * 8 + tg;
            uint32_t b0 = wt[cb];
            uint32_t b1 = wt[cb + 4];
            mma_bf16(acc[0][nt], a[0], b0, b1);
            mma_bf16(acc[1][nt], a[1], b0, b1);
        }
    }

#pragma unroll
    for (int mi = 0; mi < 2; mi++) {
        int r0 = row_base + wrow + mi * 16 + g;
        int r1 = r0 + 8;
#pragma unroll
        for (int nt = 0; nt < 8; nt++) {
            int c = wcol + nt * 8 + tg * 2;
            if (r0 < M) {
                float2 v = make_float2(acc[mi][nt][0] + bs[c], acc[mi][nt][1] + bs[c + 1]);
                *reinterpret_cast<float2*>(Y + (long)r0 * 128 + c) = v;
            }
            if (r1 < M) {
                float2 v = make_float2(acc[mi][nt][2] + bs[c], acc[mi][nt][3] + bs[c + 1]);
                *reinterpret_cast<float2*>(Y + (long)r1 * 128 + c) = v;
            }
        }
    }
}

// ---------------------------------------------------------------------------
// GEMM + bias, N=16, K=128 (fp32, memory-bound).
// ---------------------------------------------------------------------------
__global__ void gemm_bias_16(const float* __restrict__ X, const float* __restrict__ W,
                             const float* __restrict__ b, float* __restrict__ Y, int M) {
    __shared__ float xs[128][33];
    __shared__ float ws[32][16];
    __shared__ float bs[16];

    int tid = threadIdx.x;
    int tx = tid & 15;
    int ty = tid >> 4;
    int row_base = blockIdx.x * 128;

    if (tid < 16) bs[tid] = b[tid];

    float acc[8];
#pragma unroll
    for (int i = 0; i < 8; i++) acc[i] = 0.f;

    for (int kc = 0; kc < 128; kc += 32) {
#pragma unroll
        for (int i = 0; i < 16; i++) {
            int idx = tid + 256 * i;
            int r = idx >> 5, c = idx & 31;
            int gr = row_base + r;
            xs[r][c] = (gr < M) ? X[(long)gr * 128 + kc + c] : 0.f;
        }
#pragma unroll
        for (int i = 0; i < 2; i++) {
            int idx = tid + 256 * i;
            int r = idx >> 4, c = idx & 15;
            ws[r][c] = W[(long)(kc + r) * 16 + c];
        }
        __syncthreads();

#pragma unroll
        for (int k = 0; k < 32; k++) {
            float wv = ws[k][tx];
#pragma unroll
            for (int rm = 0; rm < 8; rm++)
                acc[rm] += xs[ty * 8 + rm][k] * wv;
        }
        __syncthreads();
    }

#pragma unroll
    for (int rm = 0; rm < 8; rm++) {
        int gr = row_base + ty * 8 + rm;
        if (gr < M) Y[(long)gr * 16 + tx] = acc[rm] + bs[tx];
    }
}

static inline int cdiv(long a, long b) { return (int)((a + b - 1) / b); }

static void build_csr(const int* src, const int* dst, int E, int n_dst,
                      int* offs, int* csr_src, int* deg, int* cur, int* bsum) {
    cudaMemsetAsync(deg, 0, (size_t)n_dst * sizeof(int));
    hist_kernel<<<cdiv(E, 256), 256>>>(dst, deg, E);
    int nb = cdiv(n_dst, 4096);
    scan_block<<<nb, 256>>>(deg, offs, bsum, n_dst);
    scan_bsums<<<1, 128>>>(bsum, nb);
    scan_add<<<cdiv(n_dst, 256), 256>>>(offs, bsum, cur, n_dst, E);
    fill_kernel<<<cdiv(E, 256), 256>>>(src, dst, cur, csr_src, E);
}

// ---------------------------------------------------------------------------
extern "C" void kernel_launch(void* const* d_in, const int* in_sizes, int n_in,
                              void* d_out, int out_size) {
    const float* embed_paper  = (const float*)d_in[0];
    const float* embed_author = (const float*)d_in[1];
    const float* W1_cites     = (const float*)d_in[2];
    const float* b1_cites     = (const float*)d_in[3];
    const float* W1_writtenby = (const float*)d_in[4];
    const float* b1_writtenby = (const float*)d_in[5];
    const float* W1_writes    = (const float*)d_in[6];
    const float* b1_writes    = (const float*)d_in[7];
    const float* W2_cites     = (const float*)d_in[8];
    const float* b2_cites     = (const float*)d_in[9];
    const float* W2_writtenby = (const float*)d_in[10];
    const float* b2_writtenby = (const float*)d_in[11];
    const float* W2_writes    = (const float*)d_in[12];
    const float* b2_writes    = (const float*)d_in[13];
    const int* cites_src      = (const int*)d_in[14];
    const int* cites_dst      = (const int*)d_in[15];
    const int* writtenby_src  = (const int*)d_in[16];
    const int* writtenby_dst  = (const int*)d_in[17];
    const int* writes_src     = (const int*)d_in[18];
    const int* writes_dst     = (const int*)d_in[19];

    const int n_paper  = in_sizes[0] / 128;
    const int n_author = in_sizes[1] / 128;
    const int E_cites  = in_sizes[14];
    const int E_wb     = in_sizes[16];
    const int E_wr     = in_sizes[18];

    float *m, *h1p, *h1a;
    cudaGetSymbolAddress((void**)&m,   g_m);
    cudaGetSymbolAddress((void**)&h1p, g_h1p);
    cudaGetSymbolAddress((void**)&h1a, g_h1a);
    int *offs0, *offs1, *offs2, *csr0, *csr1, *csr2, *deg, *cur, *bsum;
    cudaGetSymbolAddress((void**)&offs0, g_offs0);
    cudaGetSymbolAddress((void**)&offs1, g_offs1);
    cudaGetSymbolAddress((void**)&offs2, g_offs2);
    cudaGetSymbolAddress((void**)&csr0, g_csr0);
    cudaGetSymbolAddress((void**)&csr1, g_csr1);
    cudaGetSymbolAddress((void**)&csr2, g_csr2);
    cudaGetSymbolAddress((void**)&deg,  g_deg);
    cudaGetSymbolAddress((void**)&cur,  g_cur);
    cudaGetSymbolAddress((void**)&bsum, g_bsum);

    cudaFuncSetAttribute(gemm_bias_128_bf16,
                         cudaFuncAttributeMaxDynamicSharedMemorySize, GEMM128_SMEM);

    float* out_paper  = (float*)d_out;
    float* out_author = (float*)d_out + (long)n_paper * 16;

    // ---------------- CSR builds (reused by both layers) ----------------
    build_csr(cites_src,     cites_dst,     E_cites, n_paper,  offs0, csr0, deg, cur, bsum);
    build_csr(writtenby_src, writtenby_dst, E_wb,    n_author, offs1, csr1, deg, cur, bsum);
    build_csr(writes_src,    writes_dst,    E_wr,    n_paper,  offs2, csr2, deg, cur, bsum);

    // ---------------- Layer 1 (D=128) ----------------
    // cites: paper -> paper, h1p = relu(agg)
    gemm_bias_128_bf16<<<cdiv(n_paper, 128), 256, GEMM128_SMEM>>>(embed_paper, W1_cites, b1_cites, m, n_paper);
    gather_sum_128<<<cdiv(n_paper, 8), 256>>>(m, offs0, csr0, nullptr, h1p, n_paper);

    // writes: author -> paper, h1p = relu(h1p + agg)
    gemm_bias_128_bf16<<<cdiv(n_author, 128), 256, GEMM128_SMEM>>>(embed_author, W1_writes, b1_writes, m, n_author);
    gather_sum_128<<<cdiv(n_paper, 8), 256>>>(m, offs2, csr2, h1p, h1p, n_paper);

    // writtenby: paper -> author, h1a = relu(agg)
    gemm_bias_128_bf16<<<cdiv(n_paper, 128), 256, GEMM128_SMEM>>>(embed_paper, W1_writtenby, b1_writtenby, m, n_paper);
    gather_sum_128<<<cdiv(n_author, 8), 256>>>(m, offs1, csr1, nullptr, h1a, n_author);

    // ---------------- Layer 2 (D=16) ----------------
    gemm_bias_16<<<cdiv(n_paper, 128), 256>>>(h1p, W2_cites, b2_cites, m, n_paper);
    gather_sum_16<<<cdiv((long)n_paper * 4, 256), 256>>>(m, offs0, csr0, nullptr, out_paper, n_paper);

    gemm_bias_16<<<cdiv(n_author, 128), 256>>>(h1a, W2_writes, b2_writes, m, n_author);
    gather_sum_16<<<cdiv((long)n_paper * 4, 256), 256>>>(m, offs2, csr2, out_paper, out_paper, n_paper);

    gemm_bias_16<<<cdiv(n_paper, 128), 256>>>(h1p, W2_writtenby, b2_writtenby, m, n_paper);
    gather_sum_16<<<cdiv((long)n_author * 4, 256), 256>>>(m, offs1, csr1, nullptr, out_author, n_author);
}

// round 5
// speedup vs baseline: 2.7746x; 1.1087x over previous
#include <cuda_runtime.h>
#include <cuda_bf16.h>
#include <cstdint>

// ---------------------------------------------------------------------------
// EntityClassify: 2-layer hetero R-GCN.
// R5: bf16 layer-1 messages, fused dual-relation gathers, batched CSR build.
// ---------------------------------------------------------------------------

#define N_PAPER_MAX 200000
#define N_AUTHOR_MAX 100000
#define E_MAX 500000
#define NP_PAD 200064
#define NA_PAD 100064

// layer-1 messages (bf16)
__device__ __nv_bfloat16 g_m0[N_PAPER_MAX * 128];   // cites:     embed_paper @ W1_cites
__device__ __nv_bfloat16 g_m1[N_AUTHOR_MAX * 128];  // writes:    embed_author @ W1_writes
__device__ __nv_bfloat16 g_m2[N_PAPER_MAX * 128];   // writtenby: embed_paper @ W1_writtenby
// layer-1 outputs (fp32)
__device__ float g_h1p[N_PAPER_MAX * 128];
__device__ float g_h1a[N_AUTHOR_MAX * 128];
// layer-2 messages (fp32)
__device__ float g_mA[N_PAPER_MAX * 16];
__device__ float g_mB[N_AUTHOR_MAX * 16];
__device__ float g_mC[N_PAPER_MAX * 16];

// CSR scratch (0=cites->paper, 1=writtenby->author, 2=writes->paper)
__device__ int g_offs0[NP_PAD + 1];
__device__ int g_offs1[NA_PAD + 1];
__device__ int g_offs2[NP_PAD + 1];
__device__ int g_csr0[E_MAX];
__device__ int g_csr1[E_MAX];
__device__ int g_csr2[E_MAX];
__device__ int g_deg[2 * NP_PAD + NA_PAD];   // bases: 0 / NP_PAD / NP_PAD+NA_PAD
__device__ int g_cur[2 * NP_PAD + NA_PAD];
__device__ int g_bsum[3 * 64];

__device__ __forceinline__ uint32_t pack_bf2(float a, float b) {
    __nv_bfloat162 p = __floats2bfloat162_rn(a, b);
    return *reinterpret_cast<uint32_t*>(&p);
}

__device__ __forceinline__ void mma_bf16(float* c, const uint32_t* a,
                                         uint32_t b0, uint32_t b1) {
    asm volatile(
        "mma.sync.aligned.m16n8k16.row.col.f32.bf16.bf16.f32 "
        "{%0,%1,%2,%3}, {%4,%5,%6,%7}, {%8,%9}, {%0,%1,%2,%3};"
        : "+f"(c[0]), "+f"(c[1]), "+f"(c[2]), "+f"(c[3])
        : "r"(a[0]), "r"(a[1]), "r"(a[2]), "r"(a[3]), "r"(b0), "r"(b1));
}

// ---------------------------------------------------------------------------
// Batched CSR build (all 3 relations per launch)
// ---------------------------------------------------------------------------
__global__ void hist3(const int* __restrict__ d0, const int* __restrict__ d1,
                      const int* __restrict__ d2, int* __restrict__ deg,
                      int E0, int E1, int E2) {
    int i = blockIdx.x * blockDim.x + threadIdx.x;
    if (i < E0) {
        atomicAdd(&deg[d0[i]], 1);
    } else if (i < E0 + E1) {
        atomicAdd(&deg[NP_PAD + d1[i - E0]], 1);
    } else if (i < E0 + E1 + E2) {
        atomicAdd(&deg[NP_PAD + NA_PAD + d2[i - E0 - E1]], 1);
    }
}

// Per-block exclusive scan over 4096 ints of one relation's deg slice.
__global__ void scan_block3(const int* __restrict__ deg,
                            int* __restrict__ offs0, int* __restrict__ offs1,
                            int* __restrict__ offs2, int* __restrict__ bsum,
                            int n0, int n1, int n2) {
    const int nb0 = (n0 + 4095) >> 12, nb1 = (n1 + 4095) >> 12;
    int b = blockIdx.x;
    int rel, lb, n;
    const int* dg;
    int* offs;
    if (b < nb0)            { rel = 0; lb = b;             dg = deg;                   offs = offs0; n = n0; }
    else if (b < nb0 + nb1) { rel = 1; lb = b - nb0;       dg = deg + NP_PAD;          offs = offs1; n = n1; }
    else                    { rel = 2; lb = b - nb0 - nb1; dg = deg + NP_PAD + NA_PAD; offs = offs2; n = n2; }

    const int i0 = lb * 4096 + threadIdx.x * 16;
    int vals[16];
    int s = 0;
#pragma unroll
    for (int j = 0; j < 16; j++) {
        int idx = i0 + j;
        int v = (idx < n) ? dg[idx] : 0;
        vals[j] = s;
        s += v;
    }
    int lane = threadIdx.x & 31, wid = threadIdx.x >> 5;
    int x = s;
#pragma unroll
    for (int o = 1; o < 32; o <<= 1) {
        int y = __shfl_up_sync(0xffffffffu, x, o);
        if (lane >= o) x += y;
    }
    __shared__ int wsum[8];
    if (lane == 31) wsum[wid] = x;
    __syncthreads();
    if (wid == 0 && lane < 8) {
        int y = wsum[lane];
#pragma unroll
        for (int o = 1; o < 8; o <<= 1) {
            int z = __shfl_up_sync(0xffu, y, o);
            if (lane >= o) y += z;
        }
        wsum[lane] = y;
    }
    __syncthreads();
    int thread_excl = (x - s) + (wid > 0 ? wsum[wid - 1] : 0);
#pragma unroll
    for (int j = 0; j < 16; j++) {
        int idx = i0 + j;
        if (idx < n) offs[idx] = thread_excl + vals[j];
    }
    if (threadIdx.x == 255) bsum[rel * 64 + lb] = thread_excl + s;
}

__global__ void scan_bsums3(int* __restrict__ bsum, int nb0, int nb1, int nb2) {
    int r = blockIdx.x;
    int nb = (r == 0) ? nb0 : (r == 1) ? nb1 : nb2;
    if (threadIdx.x == 0) {
        int* p = bsum + r * 64;
        int s = 0;
        for (int i = 0; i < nb; i++) { int x = p[i]; p[i] = s; s += x; }
    }
}

__global__ void scan_add3(int* __restrict__ offs0, int* __restrict__ offs1,
                          int* __restrict__ offs2, const int* __restrict__ bsum,
                          int* __restrict__ cur,
                          int n0, int n1, int n2, int E0, int E1, int E2) {
    int i = blockIdx.x * blockDim.x + threadIdx.x;
    if (i < n0) {
        int v = offs0[i] + bsum[i >> 12];
        offs0[i] = v; cur[i] = v;
        if (i == 0) offs0[n0] = E0;
    } else if (i < n0 + n1) {
        int j = i - n0;
        int v = offs1[j] + bsum[64 + (j >> 12)];
        offs1[j] = v; cur[NP_PAD + j] = v;
        if (j == 0) offs1[n1] = E1;
    } else if (i < n0 + n1 + n2) {
        int j = i - n0 - n1;
        int v = offs2[j] + bsum[128 + (j >> 12)];
        offs2[j] = v; cur[NP_PAD + NA_PAD + j] = v;
        if (j == 0) offs2[n2] = E2;
    }
}

__global__ void fill3(const int* __restrict__ s0, const int* __restrict__ d0,
                      const int* __restrict__ s1, const int* __restrict__ d1,
                      const int* __restrict__ s2, const int* __restrict__ d2,
                      int* __restrict__ cur,
                      int* __restrict__ c0, int* __restrict__ c1, int* __restrict__ c2,
                      int E0, int E1, int E2) {
    int i = blockIdx.x * blockDim.x + threadIdx.x;
    if (i < E0) {
        int p = atomicAdd(&cur[d0[i]], 1);
        c0[p] = s0[i];
    } else if (i < E0 + E1) {
        int j = i - E0;
        int p = atomicAdd(&cur[NP_PAD + d1[j]], 1);
        c1[p] = s1[j];
    } else if (i < E0 + E1 + E2) {
        int j = i - E0 - E1;
        int p = atomicAdd(&cur[NP_PAD + NA_PAD + d2[j]], 1);
        c2[p] = s2[j];
    }
}

// ---------------------------------------------------------------------------
// Fused dual-relation gather (F=128, bf16 messages):
//   out[d] = relu(relu(sum_csrA mA[src]) + sum_csrB mB[src])   (fp32 out)
// One warp per dst row; lane covers 4 features (uint2 = 4 bf16).
// ---------------------------------------------------------------------------
__global__ void gather2_128(const __nv_bfloat16* __restrict__ mA, const int* __restrict__ offsA,
                            const int* __restrict__ csrA,
                            const __nv_bfloat16* __restrict__ mB, const int* __restrict__ offsB,
                            const int* __restrict__ csrB,
                            float* __restrict__ out, int n_dst) {
    int d = blockIdx.x * (blockDim.x >> 5) + (threadIdx.x >> 5);
    if (d >= n_dst) return;
    int lane = threadIdx.x & 31;

    float4 acc = make_float4(0.f, 0.f, 0.f, 0.f);
    int a0 = __ldg(offsA + d), a1 = __ldg(offsA + d + 1);
    for (int j = a0; j < a1; j++) {
        int s = __ldg(csrA + j);
        uint2 v = __ldg(reinterpret_cast<const uint2*>(mA + (long)s * 128) + lane);
        float2 f0 = __bfloat1622float2(*reinterpret_cast<__nv_bfloat162*>(&v.x));
        float2 f1 = __bfloat1622float2(*reinterpret_cast<__nv_bfloat162*>(&v.y));
        acc.x += f0.x; acc.y += f0.y; acc.z += f1.x; acc.w += f1.y;
    }
    acc.x = fmaxf(acc.x, 0.f); acc.y = fmaxf(acc.y, 0.f);
    acc.z = fmaxf(acc.z, 0.f); acc.w = fmaxf(acc.w, 0.f);

    int b0 = __ldg(offsB + d), b1e = __ldg(offsB + d + 1);
    for (int j = b0; j < b1e; j++) {
        int s = __ldg(csrB + j);
        uint2 v = __ldg(reinterpret_cast<const uint2*>(mB + (long)s * 128) + lane);
        float2 f0 = __bfloat1622float2(*reinterpret_cast<__nv_bfloat162*>(&v.x));
        float2 f1 = __bfloat1622float2(*reinterpret_cast<__nv_bfloat162*>(&v.y));
        acc.x += f0.x; acc.y += f0.y; acc.z += f1.x; acc.w += f1.y;
    }
    acc.x = fmaxf(acc.x, 0.f); acc.y = fmaxf(acc.y, 0.f);
    acc.z = fmaxf(acc.z, 0.f); acc.w = fmaxf(acc.w, 0.f);
    reinterpret_cast<float4*>(out + (long)d * 128)[lane] = acc;
}

// Single-relation variant (authors).
__global__ void gather1_128(const __nv_bfloat16* __restrict__ m, const int* __restrict__ offs,
                            const int* __restrict__ csr, float* __restrict__ out, int n_dst) {
    int d = blockIdx.x * (blockDim.x >> 5) + (threadIdx.x >> 5);
    if (d >= n_dst) return;
    int lane = threadIdx.x & 31;
    float4 acc = make_float4(0.f, 0.f, 0.f, 0.f);
    int s0 = __ldg(offs + d), s1 = __ldg(offs + d + 1);
    for (int j = s0; j < s1; j++) {
        int s = __ldg(csr + j);
        uint2 v = __ldg(reinterpret_cast<const uint2*>(m + (long)s * 128) + lane);
        float2 f0 = __bfloat1622float2(*reinterpret_cast<__nv_bfloat162*>(&v.x));
        float2 f1 = __bfloat1622float2(*reinterpret_cast<__nv_bfloat162*>(&v.y));
        acc.x += f0.x; acc.y += f0.y; acc.z += f1.x; acc.w += f1.y;
    }
    acc.x = fmaxf(acc.x, 0.f); acc.y = fmaxf(acc.y, 0.f);
    acc.z = fmaxf(acc.z, 0.f); acc.w = fmaxf(acc.w, 0.f);
    reinterpret_cast<float4*>(out + (long)d * 128)[lane] = acc;
}

// F=16 fp32 fused dual-relation gather: 4 threads per dst row.
__global__ void gather2_16(const float* __restrict__ mA, const int* __restrict__ offsA,
                           const int* __restrict__ csrA,
                           const float* __restrict__ mB, const int* __restrict__ offsB,
                           const int* __restrict__ csrB,
                           float* __restrict__ out, int n_dst) {
    long idx = (long)blockIdx.x * blockDim.x + threadIdx.x;
    if (idx >= (long)n_dst * 4) return;
    int d = (int)(idx >> 2), q = (int)(idx & 3);
    float4 acc = make_float4(0.f, 0.f, 0.f, 0.f);
    int a0 = __ldg(offsA + d), a1 = __ldg(offsA + d + 1);
    for (int j = a0; j < a1; j++) {
        int s = __ldg(csrA + j);
        float4 v = __ldg(reinterpret_cast<const float4*>(mA + (long)s * 16) + q);
        acc.x += v.x; acc.y += v.y; acc.z += v.z; acc.w += v.w;
    }
    acc.x = fmaxf(acc.x, 0.f); acc.y = fmaxf(acc.y, 0.f);
    acc.z = fmaxf(acc.z, 0.f); acc.w = fmaxf(acc.w, 0.f);
    int b0 = __ldg(offsB + d), b1e = __ldg(offsB + d + 1);
    for (int j = b0; j < b1e; j++) {
        int s = __ldg(csrB + j);
        float4 v = __ldg(reinterpret_cast<const float4*>(mB + (long)s * 16) + q);
        acc.x += v.x; acc.y += v.y; acc.z += v.z; acc.w += v.w;
    }
    acc.x = fmaxf(acc.x, 0.f); acc.y = fmaxf(acc.y, 0.f);
    acc.z = fmaxf(acc.z, 0.f); acc.w = fmaxf(acc.w, 0.f);
    reinterpret_cast<float4*>(out + (long)d * 16)[q] = acc;
}

__global__ void gather1_16(const float* __restrict__ m, const int* __restrict__ offs,
                           const int* __restrict__ csr, float* __restrict__ out, int n_dst) {
    long idx = (long)blockIdx.x * blockDim.x + threadIdx.x;
    if (idx >= (long)n_dst * 4) return;
    int d = (int)(idx >> 2), q = (int)(idx & 3);
    float4 acc = make_float4(0.f, 0.f, 0.f, 0.f);
    int s0 = __ldg(offs + d), s1 = __ldg(offs + d + 1);
    for (int j = s0; j < s1; j++) {
        int s = __ldg(csr + j);
        float4 v = __ldg(reinterpret_cast<const float4*>(m + (long)s * 16) + q);
        acc.x += v.x; acc.y += v.y; acc.z += v.z; acc.w += v.w;
    }
    acc.x = fmaxf(acc.x, 0.f); acc.y = fmaxf(acc.y, 0.f);
    acc.z = fmaxf(acc.z, 0.f); acc.w = fmaxf(acc.w, 0.f);
    reinterpret_cast<float4*>(out + (long)d * 16)[q] = acc;
}

// ---------------------------------------------------------------------------
// bf16 GEMM + bias, bf16 output: Y[M,128] = bf16(X) @ bf16(W) + b
// Block 256 thr (8 warps, 4x2), tile 128x128, K=128 fully smem-resident.
// ---------------------------------------------------------------------------
#define XS_STRIDE 68
#define GEMM128_SMEM (2 * 128 * XS_STRIDE * 4)

__global__ void __launch_bounds__(256)
gemm_bias_128_bf16o(const float* __restrict__ X, const float* __restrict__ W,
                    const float* __restrict__ b, __nv_bfloat16* __restrict__ Y, int M) {
    extern __shared__ uint32_t sm[];
    uint32_t* xs = sm;
    uint32_t* wt = sm + 128 * XS_STRIDE;
    __shared__ float bs[128];

    const int tid = threadIdx.x;
    const int wid = tid >> 5, lane = tid & 31;
    const int g = lane >> 2, tg = lane & 3;
    const int wrow = (wid >> 1) * 32;
    const int wcol = (wid & 1) * 64;
    const int row_base = blockIdx.x * 128;

    if (tid < 128) bs[tid] = b[tid];

#pragma unroll
    for (int i = 0; i < 16; i++) {
        int idx = tid + 256 * i;
        int r = idx >> 5, c4 = idx & 31;
        int gr = row_base + r;
        float4 v = make_float4(0.f, 0.f, 0.f, 0.f);
        if (gr < M) v = __ldg(reinterpret_cast<const float4*>(X + (long)gr * 128) + c4);
        xs[r * XS_STRIDE + c4 * 2 + 0] = pack_bf2(v.x, v.y);
        xs[r * XS_STRIDE + c4 * 2 + 1] = pack_bf2(v.z, v.w);
    }
#pragma unroll
    for (int i = 0; i < 8; i++) {
        int u = tid + 256 * i;
        int n4 = u >> 6;
        int kp = u & 63;
        float4 wa = __ldg(reinterpret_cast<const float4*>(W + (long)(2 * kp) * 128) + n4);
        float4 wb = __ldg(reinterpret_cast<const float4*>(W + (long)(2 * kp + 1) * 128) + n4);
        wt[(n4 * 4 + 0) * XS_STRIDE + kp] = pack_bf2(wa.x, wb.x);
        wt[(n4 * 4 + 1) * XS_STRIDE + kp] = pack_bf2(wa.y, wb.y);
        wt[(n4 * 4 + 2) * XS_STRIDE + kp] = pack_bf2(wa.z, wb.z);
        wt[(n4 * 4 + 3) * XS_STRIDE + kp] = pack_bf2(wa.w, wb.w);
    }
    __syncthreads();

    float acc[2][8][4];
#pragma unroll
    for (int mi = 0; mi < 2; mi++)
#pragma unroll
        for (int nt = 0; nt < 8; nt++)
#pragma unroll
            for (int j = 0; j < 4; j++) acc[mi][nt][j] = 0.f;

#pragma unroll
    for (int s = 0; s < 8; s++) {
        uint32_t a[2][4];
#pragma unroll
        for (int mi = 0; mi < 2; mi++) {
            int rb = (wrow + mi * 16 + g) * XS_STRIDE + s * 8;
            int rb8 = rb + 8 * XS_STRIDE;
            a[mi][0] = xs[rb + tg];
            a[mi][1] = xs[rb8 + tg];
            a[mi][2] = xs[rb + 4 + tg];
            a[mi][3] = xs[rb8 + 4 + tg];
        }
#pragma unroll
        for (int nt = 0; nt < 8; nt++) {
            int cb = (wcol + nt * 8 + g) * XS_STRIDE + s * 8 + tg;
            uint32_t b0 = wt[cb];
            uint32_t b1 = wt[cb + 4];
            mma_bf16(acc[0][nt], a[0], b0, b1);
            mma_bf16(acc[1][nt], a[1], b0, b1);
        }
    }

    uint32_t* Yu = reinterpret_cast<uint32_t*>(Y);
#pragma unroll
    for (int mi = 0; mi < 2; mi++) {
        int r0 = row_base + wrow + mi * 16 + g;
        int r1 = r0 + 8;
#pragma unroll
        for (int nt = 0; nt < 8; nt++) {
            int c = wcol + nt * 8 + tg * 2;
            if (r0 < M)
                Yu[(long)r0 * 64 + (c >> 1)] = pack_bf2(acc[mi][nt][0] + bs[c], acc[mi][nt][1] + bs[c + 1]);
            if (r1 < M)
                Yu[(long)r1 * 64 + (c >> 1)] = pack_bf2(acc[mi][nt][2] + bs[c], acc[mi][nt][3] + bs[c + 1]);
        }
    }
}

// ---------------------------------------------------------------------------
// GEMM + bias, N=16, K=128 (fp32 in/out, memory-bound).
// ---------------------------------------------------------------------------
__global__ void gemm_bias_16(const float* __restrict__ X, const float* __restrict__ W,
                             const float* __restrict__ b, float* __restrict__ Y, int M) {
    __shared__ float xs[128][33];
    __shared__ float ws[32][16];
    __shared__ float bs[16];

    int tid = threadIdx.x;
    int tx = tid & 15;
    int ty = tid >> 4;
    int row_base = blockIdx.x * 128;

    if (tid < 16) bs[tid] = b[tid];

    float acc[8];
#pragma unroll
    for (int i = 0; i < 8; i++) acc[i] = 0.f;

    for (int kc = 0; kc < 128; kc += 32) {
#pragma unroll
        for (int i = 0; i < 16; i++) {
            int idx = tid + 256 * i;
            int r = idx >> 5, c = idx & 31;
            int gr = row_base + r;
            xs[r][c] = (gr < M) ? X[(long)gr * 128 + kc + c] : 0.f;
        }
#pragma unroll
        for (int i = 0; i < 2; i++) {
            int idx = tid + 256 * i;
            int r = idx >> 4, c = idx & 15;
            ws[r][c] = W[(long)(kc + r) * 16 + c];
        }
        __syncthreads();

#pragma unroll
        for (int k = 0; k < 32; k++) {
            float wv = ws[k][tx];
#pragma unroll
            for (int rm = 0; rm < 8; rm++)
                acc[rm] += xs[ty * 8 + rm][k] * wv;
        }
        __syncthreads();
    }

#pragma unroll
    for (int rm = 0; rm < 8; rm++) {
        int gr = row_base + ty * 8 + rm;
        if (gr < M) Y[(long)gr * 16 + tx] = acc[rm] + bs[tx];
    }
}

static inline int cdiv(long a, long b) { return (int)((a + b - 1) / b); }

// ---------------------------------------------------------------------------
extern "C" void kernel_launch(void* const* d_in, const int* in_sizes, int n_in,
                              void* d_out, int out_size) {
    const float* embed_paper  = (const float*)d_in[0];
    const float* embed_author = (const float*)d_in[1];
    const float* W1_cites     = (const float*)d_in[2];
    const float* b1_cites     = (const float*)d_in[3];
    const float* W1_writtenby = (const float*)d_in[4];
    const float* b1_writtenby = (const float*)d_in[5];
    const float* W1_writes    = (const float*)d_in[6];
    const float* b1_writes    = (const float*)d_in[7];
    const float* W2_cites     = (const float*)d_in[8];
    const float* b2_cites     = (const float*)d_in[9];
    const float* W2_writtenby = (const float*)d_in[10];
    const float* b2_writtenby = (const float*)d_in[11];
    const float* W2_writes    = (const float*)d_in[12];
    const float* b2_writes    = (const float*)d_in[13];
    const int* cites_src      = (const int*)d_in[14];
    const int* cites_dst      = (const int*)d_in[15];
    const int* writtenby_src  = (const int*)d_in[16];
    const int* writtenby_dst  = (const int*)d_in[17];
    const int* writes_src     = (const int*)d_in[18];
    const int* writes_dst     = (const int*)d_in[19];

    const int n_paper  = in_sizes[0] / 128;
    const int n_author = in_sizes[1] / 128;
    const int E0 = in_sizes[14];   // cites
    const int E1 = in_sizes[16];   // writtenby
    const int E2 = in_sizes[18];   // writes

    __nv_bfloat16 *m0, *m1, *m2;
    float *h1p, *h1a, *mA, *mB, *mC;
    cudaGetSymbolAddress((void**)&m0,  g_m0);
    cudaGetSymbolAddress((void**)&m1,  g_m1);
    cudaGetSymbolAddress((void**)&m2,  g_m2);
    cudaGetSymbolAddress((void**)&h1p, g_h1p);
    cudaGetSymbolAddress((void**)&h1a, g_h1a);
    cudaGetSymbolAddress((void**)&mA,  g_mA);
    cudaGetSymbolAddress((void**)&mB,  g_mB);
    cudaGetSymbolAddress((void**)&mC,  g_mC);
    int *offs0, *offs1, *offs2, *csr0, *csr1, *csr2, *deg, *cur, *bsum;
    cudaGetSymbolAddress((void**)&offs0, g_offs0);
    cudaGetSymbolAddress((void**)&offs1, g_offs1);
    cudaGetSymbolAddress((void**)&offs2, g_offs2);
    cudaGetSymbolAddress((void**)&csr0, g_csr0);
    cudaGetSymbolAddress((void**)&csr1, g_csr1);
    cudaGetSymbolAddress((void**)&csr2, g_csr2);
    cudaGetSymbolAddress((void**)&deg,  g_deg);
    cudaGetSymbolAddress((void**)&cur,  g_cur);
    cudaGetSymbolAddress((void**)&bsum, g_bsum);

    cudaFuncSetAttribute(gemm_bias_128_bf16o,
                         cudaFuncAttributeMaxDynamicSharedMemorySize, GEMM128_SMEM);

    float* out_paper  = (float*)d_out;
    float* out_author = (float*)d_out + (long)n_paper * 16;

    // ---------------- Batched CSR build ----------------
    cudaMemsetAsync(deg, 0, (size_t)(2 * NP_PAD + NA_PAD) * sizeof(int));
    hist3<<<cdiv((long)E0 + E1 + E2, 256), 256>>>(cites_dst, writtenby_dst, writes_dst,
                                                  deg, E0, E1, E2);
    int nb0 = cdiv(n_paper, 4096), nb1 = cdiv(n_author, 4096), nb2 = cdiv(n_paper, 4096);
    scan_block3<<<nb0 + nb1 + nb2, 256>>>(deg, offs0, offs1, offs2, bsum,
                                          n_paper, n_author, n_paper);
    scan_bsums3<<<3, 32>>>(bsum, nb0, nb1, nb2);
    scan_add3<<<cdiv((long)n_paper + n_author + n_paper, 256), 256>>>(
        offs0, offs1, offs2, bsum, cur, n_paper, n_author, n_paper, E0, E1, E2);
    fill3<<<cdiv((long)E0 + E1 + E2, 256), 256>>>(
        cites_src, cites_dst, writtenby_src, writtenby_dst, writes_src, writes_dst,
        cur, csr0, csr1, csr2, E0, E1, E2);

    // ---------------- Layer 1 (D=128) ----------------
    gemm_bias_128_bf16o<<<cdiv(n_paper, 128), 256, GEMM128_SMEM>>>(embed_paper, W1_cites, b1_cites, m0, n_paper);
    gemm_bias_128_bf16o<<<cdiv(n_paper, 128), 256, GEMM128_SMEM>>>(embed_paper, W1_writtenby, b1_writtenby, m2, n_paper);
    gemm_bias_128_bf16o<<<cdiv(n_author, 128), 256, GEMM128_SMEM>>>(embed_author, W1_writes, b1_writes, m1, n_author);

    // h1p = relu(relu(agg_cites) + agg_writes) ; h1a = relu(agg_writtenby)
    gather2_128<<<cdiv(n_paper, 8), 256>>>(m0, offs0, csr0, m1, offs2, csr2, h1p, n_paper);
    gather1_128<<<cdiv(n_author, 8), 256>>>(m2, offs1, csr1, h1a, n_author);

    // ---------------- Layer 2 (D=16) ----------------
    gemm_bias_16<<<cdiv(n_paper, 128), 256>>>(h1p, W2_cites, b2_cites, mA, n_paper);
    gemm_bias_16<<<cdiv(n_paper, 128), 256>>>(h1p, W2_writtenby, b2_writtenby, mC, n_paper);
    gemm_bias_16<<<cdiv(n_author, 128), 256>>>(h1a, W2_writes, b2_writes, mB, n_author);

    gather2_16<<<cdiv((long)n_paper * 4, 256), 256>>>(mA, offs0, csr0, mB, offs2, csr2, out_paper, n_paper);
    gather1_16<<<cdiv((long)n_author * 4, 256), 256>>>(mC, offs1, csr1, out_author, n_author);
}

// round 6
// speedup vs baseline: 3.4366x; 1.2386x over previous
#include <cuda_runtime.h>
#include <cuda_bf16.h>
#include <cuda_fp16.h>
#include <cstdint>

// ---------------------------------------------------------------------------
// EntityClassify: 2-layer hetero R-GCN.
// R6: multi-output GEMMs (X tile loaded once per consumer set), fp16 h1,
//     fused per-layer gathers, batched CSR build. 10 launches total.
// ---------------------------------------------------------------------------

#define N_PAPER_MAX 200000
#define N_AUTHOR_MAX 100000
#define E_MAX 500000
#define NP_PAD 200064
#define NA_PAD 100064

// layer-1 messages (bf16)
__device__ __nv_bfloat16 g_m0[N_PAPER_MAX * 128];   // embed_paper  @ W1_cites
__device__ __nv_bfloat16 g_m2[N_PAPER_MAX * 128];   // embed_paper  @ W1_writtenby
__device__ __nv_bfloat16 g_m1[N_AUTHOR_MAX * 128];  // embed_author @ W1_writes
// layer-1 outputs (fp16)
__device__ __half g_h1p[N_PAPER_MAX * 128];
__device__ __half g_h1a[N_AUTHOR_MAX * 128];
// layer-2 messages (fp32)
__device__ float g_mA[N_PAPER_MAX * 16];   // h1p @ W2_cites
__device__ float g_mC[N_PAPER_MAX * 16];   // h1p @ W2_writtenby
__device__ float g_mB[N_AUTHOR_MAX * 16];  // h1a @ W2_writes

// CSR scratch (0=cites->paper, 1=writtenby->author, 2=writes->paper)
__device__ int g_offs0[NP_PAD + 1];
__device__ int g_offs1[NA_PAD + 1];
__device__ int g_offs2[NP_PAD + 1];
__device__ int g_csr0[E_MAX];
__device__ int g_csr1[E_MAX];
__device__ int g_csr2[E_MAX];
__device__ int g_deg[2 * NP_PAD + NA_PAD];
__device__ int g_cur[2 * NP_PAD + NA_PAD];
__device__ int g_bsum[3 * 64];

__device__ __forceinline__ uint32_t pack_bf2(float a, float b) {
    __nv_bfloat162 p = __floats2bfloat162_rn(a, b);
    return *reinterpret_cast<uint32_t*>(&p);
}

__device__ __forceinline__ void mma_bf16(float* c, const uint32_t* a,
                                         uint32_t b0, uint32_t b1) {
    asm volatile(
        "mma.sync.aligned.m16n8k16.row.col.f32.bf16.bf16.f32 "
        "{%0,%1,%2,%3}, {%4,%5,%6,%7}, {%8,%9}, {%0,%1,%2,%3};"
        : "+f"(c[0]), "+f"(c[1]), "+f"(c[2]), "+f"(c[3])
        : "r"(a[0]), "r"(a[1]), "r"(a[2]), "r"(a[3]), "r"(b0), "r"(b1));
}

// ---------------------------------------------------------------------------
// Batched CSR build (all 3 relations per launch)
// ---------------------------------------------------------------------------
__global__ void hist3(const int* __restrict__ d0, const int* __restrict__ d1,
                      const int* __restrict__ d2, int* __restrict__ deg,
                      int E0, int E1, int E2) {
    int i = blockIdx.x * blockDim.x + threadIdx.x;
    if (i < E0) {
        atomicAdd(&deg[d0[i]], 1);
    } else if (i < E0 + E1) {
        atomicAdd(&deg[NP_PAD + d1[i - E0]], 1);
    } else if (i < E0 + E1 + E2) {
        atomicAdd(&deg[NP_PAD + NA_PAD + d2[i - E0 - E1]], 1);
    }
}

__global__ void scan_block3(const int* __restrict__ deg,
                            int* __restrict__ offs0, int* __restrict__ offs1,
                            int* __restrict__ offs2, int* __restrict__ bsum,
                            int n0, int n1, int n2) {
    const int nb0 = (n0 + 4095) >> 12, nb1 = (n1 + 4095) >> 12;
    int b = blockIdx.x;
    int rel, lb, n;
    const int* dg;
    int* offs;
    if (b < nb0)            { rel = 0; lb = b;             dg = deg;                   offs = offs0; n = n0; }
    else if (b < nb0 + nb1) { rel = 1; lb = b - nb0;       dg = deg + NP_PAD;          offs = offs1; n = n1; }
    else                    { rel = 2; lb = b - nb0 - nb1; dg = deg + NP_PAD + NA_PAD; offs = offs2; n = n2; }

    const int i0 = lb * 4096 + threadIdx.x * 16;
    int vals[16];
    int s = 0;
#pragma unroll
    for (int j = 0; j < 16; j++) {
        int idx = i0 + j;
        int v = (idx < n) ? dg[idx] : 0;
        vals[j] = s;
        s += v;
    }
    int lane = threadIdx.x & 31, wid = threadIdx.x >> 5;
    int x = s;
#pragma unroll
    for (int o = 1; o < 32; o <<= 1) {
        int y = __shfl_up_sync(0xffffffffu, x, o);
        if (lane >= o) x += y;
    }
    __shared__ int wsum[8];
    if (lane == 31) wsum[wid] = x;
    __syncthreads();
    if (wid == 0 && lane < 8) {
        int y = wsum[lane];
#pragma unroll
        for (int o = 1; o < 8; o <<= 1) {
            int z = __shfl_up_sync(0xffu, y, o);
            if (lane >= o) y += z;
        }
        wsum[lane] = y;
    }
    __syncthreads();
    int thread_excl = (x - s) + (wid > 0 ? wsum[wid - 1] : 0);
#pragma unroll
    for (int j = 0; j < 16; j++) {
        int idx = i0 + j;
        if (idx < n) offs[idx] = thread_excl + vals[j];
    }
    if (threadIdx.x == 255) bsum[rel * 64 + lb] = thread_excl + s;
}

__global__ void scan_bsums3(int* __restrict__ bsum, int nb0, int nb1, int nb2) {
    int r = blockIdx.x;
    int nb = (r == 0) ? nb0 : (r == 1) ? nb1 : nb2;
    if (threadIdx.x == 0) {
        int* p = bsum + r * 64;
        int s = 0;
        for (int i = 0; i < nb; i++) { int x = p[i]; p[i] = s; s += x; }
    }
}

__global__ void scan_add3(int* __restrict__ offs0, int* __restrict__ offs1,
                          int* __restrict__ offs2, const int* __restrict__ bsum,
                          int* __restrict__ cur,
                          int n0, int n1, int n2, int E0, int E1, int E2) {
    int i = blockIdx.x * blockDim.x + threadIdx.x;
    if (i < n0) {
        int v = offs0[i] + bsum[i >> 12];
        offs0[i] = v; cur[i] = v;
        if (i == 0) offs0[n0] = E0;
    } else if (i < n0 + n1) {
        int j = i - n0;
        int v = offs1[j] + bsum[64 + (j >> 12)];
        offs1[j] = v; cur[NP_PAD + j] = v;
        if (j == 0) offs1[n1] = E1;
    } else if (i < n0 + n1 + n2) {
        int j = i - n0 - n1;
        int v = offs2[j] + bsum[128 + (j >> 12)];
        offs2[j] = v; cur[NP_PAD + NA_PAD + j] = v;
        if (j == 0) offs2[n2] = E2;
    }
}

__global__ void fill3(const int* __restrict__ s0, const int* __restrict__ d0,
                      const int* __restrict__ s1, const int* __restrict__ d1,
                      const int* __restrict__ s2, const int* __restrict__ d2,
                      int* __restrict__ cur,
                      int* __restrict__ c0, int* __restrict__ c1, int* __restrict__ c2,
                      int E0, int E1, int E2) {
    int i = blockIdx.x * blockDim.x + threadIdx.x;
    if (i < E0) {
        int p = atomicAdd(&cur[d0[i]], 1);
        c0[p] = s0[i];
    } else if (i < E0 + E1) {
        int j = i - E0;
        int p = atomicAdd(&cur[NP_PAD + d1[j]], 1);
        c1[p] = s1[j];
    } else if (i < E0 + E1 + E2) {
        int j = i - E0 - E1;
        int p = atomicAdd(&cur[NP_PAD + NA_PAD + d2[j]], 1);
        c2[p] = s2[j];
    }
}

// ---------------------------------------------------------------------------
// Layer-1 GEMM, multi-output: paper blocks do 2 weight phases from one X tile,
// author blocks do 1. bf16 MMA, whole-K-resident smem, bf16 output.
// ---------------------------------------------------------------------------
#define XS_STRIDE 68
#define GEMM128_SMEM (2 * 128 * XS_STRIDE * 4)

__global__ void __launch_bounds__(256)
gemm128_l1(const float* __restrict__ Xp, const float* __restrict__ Xa,
           const float* __restrict__ Wc,  const float* __restrict__ bc,  __nv_bfloat16* __restrict__ m0,
           const float* __restrict__ Wwb, const float* __restrict__ bwb, __nv_bfloat16* __restrict__ m2,
           const float* __restrict__ Wwr, const float* __restrict__ bwr, __nv_bfloat16* __restrict__ m1,
           int nP, int nA, int nbP) {
    extern __shared__ uint32_t sm[];
    uint32_t* xs = sm;
    uint32_t* wt = sm + 128 * XS_STRIDE;
    __shared__ float bs[128];

    const int tid = threadIdx.x;
    const int wid = tid >> 5, lane = tid & 31;
    const int g = lane >> 2, tg = lane & 3;
    const int wrow = (wid >> 1) * 32;
    const int wcol = (wid & 1) * 64;

    const bool paper = (int)blockIdx.x < nbP;
    const float* X = paper ? Xp : Xa;
    const int M = paper ? nP : nA;
    const int row_base = (paper ? blockIdx.x : blockIdx.x - nbP) * 128;
    const int nphase = paper ? 2 : 1;
    const float* Wl[2]  = { paper ? Wc : Wwr,  Wwb };
    const float* bl[2]  = { paper ? bc : bwr,  bwb };
    __nv_bfloat16* Yl[2] = { paper ? m0 : m1,  m2 };

    // X tile -> bf16x2 smem (once)
#pragma unroll
    for (int i = 0; i < 16; i++) {
        int idx = tid + 256 * i;
        int r = idx >> 5, c4 = idx & 31;
        int gr = row_base + r;
        float4 v = make_float4(0.f, 0.f, 0.f, 0.f);
        if (gr < M) v = __ldg(reinterpret_cast<const float4*>(X + (long)gr * 128) + c4);
        xs[r * XS_STRIDE + c4 * 2 + 0] = pack_bf2(v.x, v.y);
        xs[r * XS_STRIDE + c4 * 2 + 1] = pack_bf2(v.z, v.w);
    }

    for (int ph = 0; ph < nphase; ph++) {
        const float* W = Wl[ph];
        // W -> transposed bf16x2 smem
#pragma unroll
        for (int i = 0; i < 8; i++) {
            int u = tid + 256 * i;
            int n4 = u >> 6;
            int kp = u & 63;
            float4 wa = __ldg(reinterpret_cast<const float4*>(W + (long)(2 * kp) * 128) + n4);
            float4 wb = __ldg(reinterpret_cast<const float4*>(W + (long)(2 * kp + 1) * 128) + n4);
            wt[(n4 * 4 + 0) * XS_STRIDE + kp] = pack_bf2(wa.x, wb.x);
            wt[(n4 * 4 + 1) * XS_STRIDE + kp] = pack_bf2(wa.y, wb.y);
            wt[(n4 * 4 + 2) * XS_STRIDE + kp] = pack_bf2(wa.z, wb.z);
            wt[(n4 * 4 + 3) * XS_STRIDE + kp] = pack_bf2(wa.w, wb.w);
        }
        if (tid < 128) bs[tid] = bl[ph][tid];
        __syncthreads();

        float acc[2][8][4];
#pragma unroll
        for (int mi = 0; mi < 2; mi++)
#pragma unroll
            for (int nt = 0; nt < 8; nt++)
#pragma unroll
                for (int j = 0; j < 4; j++) acc[mi][nt][j] = 0.f;

#pragma unroll
        for (int s = 0; s < 8; s++) {
            uint32_t a[2][4];
#pragma unroll
            for (int mi = 0; mi < 2; mi++) {
                int rb = (wrow + mi * 16 + g) * XS_STRIDE + s * 8;
                int rb8 = rb + 8 * XS_STRIDE;
                a[mi][0] = xs[rb + tg];
                a[mi][1] = xs[rb8 + tg];
                a[mi][2] = xs[rb + 4 + tg];
                a[mi][3] = xs[rb8 + 4 + tg];
            }
#pragma unroll
            for (int nt = 0; nt < 8; nt++) {
                int cb = (wcol + nt * 8 + g) * XS_STRIDE + s * 8 + tg;
                uint32_t b0 = wt[cb];
                uint32_t b1 = wt[cb + 4];
                mma_bf16(acc[0][nt], a[0], b0, b1);
                mma_bf16(acc[1][nt], a[1], b0, b1);
            }
        }

        uint32_t* Yu = reinterpret_cast<uint32_t*>(Yl[ph]);
#pragma unroll
        for (int mi = 0; mi < 2; mi++) {
            int r0 = row_base + wrow + mi * 16 + g;
            int r1 = r0 + 8;
#pragma unroll
            for (int nt = 0; nt < 8; nt++) {
                int c = wcol + nt * 8 + tg * 2;
                if (r0 < M)
                    Yu[(long)r0 * 64 + (c >> 1)] = pack_bf2(acc[mi][nt][0] + bs[c], acc[mi][nt][1] + bs[c + 1]);
                if (r1 < M)
                    Yu[(long)r1 * 64 + (c >> 1)] = pack_bf2(acc[mi][nt][2] + bs[c], acc[mi][nt][3] + bs[c + 1]);
            }
        }
        __syncthreads();  // wt/bs reads done before next phase overwrites
    }
}

// ---------------------------------------------------------------------------
// Layer-1 fused gather: warps [0,nP) papers (dual relation), [nP,nP+nA) authors.
// Reads bf16 messages, writes fp16 h1. out = relu(relu(sumA) + sumB).
// ---------------------------------------------------------------------------
__global__ void gather_l1(const __nv_bfloat16* __restrict__ m0, const int* __restrict__ offs0,
                          const int* __restrict__ csr0,
                          const __nv_bfloat16* __restrict__ m1, const int* __restrict__ offs2,
                          const int* __restrict__ csr2,
                          const __nv_bfloat16* __restrict__ m2, const int* __restrict__ offs1,
                          const int* __restrict__ csr1,
                          __half* __restrict__ h1p, __half* __restrict__ h1a,
                          int nP, int nA) {
    int w = blockIdx.x * (blockDim.x >> 5) + (threadIdx.x >> 5);
    int lane = threadIdx.x & 31;
    float4 acc = make_float4(0.f, 0.f, 0.f, 0.f);
    __half* outp;

    if (w < nP) {
        int d = w;
        int a0 = __ldg(offs0 + d), a1 = __ldg(offs0 + d + 1);
        for (int j = a0; j < a1; j++) {
            int s = __ldg(csr0 + j);
            uint2 v = __ldg(reinterpret_cast<const uint2*>(m0 + (long)s * 128) + lane);
            float2 f0 = __bfloat1622float2(*reinterpret_cast<__nv_bfloat162*>(&v.x));
            float2 f1 = __bfloat1622float2(*reinterpret_cast<__nv_bfloat162*>(&v.y));
            acc.x += f0.x; acc.y += f0.y; acc.z += f1.x; acc.w += f1.y;
        }
        acc.x = fmaxf(acc.x, 0.f); acc.y = fmaxf(acc.y, 0.f);
        acc.z = fmaxf(acc.z, 0.f); acc.w = fmaxf(acc.w, 0.f);
        int b0 = __ldg(offs2 + d), b1e = __ldg(offs2 + d + 1);
        for (int j = b0; j < b1e; j++) {
            int s = __ldg(csr2 + j);
            uint2 v = __ldg(reinterpret_cast<const uint2*>(m1 + (long)s * 128) + lane);
            float2 f0 = __bfloat1622float2(*reinterpret_cast<__nv_bfloat162*>(&v.x));
            float2 f1 = __bfloat1622float2(*reinterpret_cast<__nv_bfloat162*>(&v.y));
            acc.x += f0.x; acc.y += f0.y; acc.z += f1.x; acc.w += f1.y;
        }
        outp = h1p + (long)d * 128;
    } else {
        int d = w - nP;
        if (d >= nA) return;
        int s0 = __ldg(offs1 + d), s1 = __ldg(offs1 + d + 1);
        for (int j = s0; j < s1; j++) {
            int s = __ldg(csr1 + j);
            uint2 v = __ldg(reinterpret_cast<const uint2*>(m2 + (long)s * 128) + lane);
            float2 f0 = __bfloat1622float2(*reinterpret_cast<__nv_bfloat162*>(&v.x));
            float2 f1 = __bfloat1622float2(*reinterpret_cast<__nv_bfloat162*>(&v.y));
            acc.x += f0.x; acc.y += f0.y; acc.z += f1.x; acc.w += f1.y;
        }
        outp = h1a + (long)d * 128;
    }
    acc.x = fmaxf(acc.x, 0.f); acc.y = fmaxf(acc.y, 0.f);
    acc.z = fmaxf(acc.z, 0.f); acc.w = fmaxf(acc.w, 0.f);
    __half2 p0 = __floats2half2_rn(acc.x, acc.y);
    __half2 p1 = __floats2half2_rn(acc.z, acc.w);
    uint2 st;
    st.x = *reinterpret_cast<uint32_t*>(&p0);
    st.y = *reinterpret_cast<uint32_t*>(&p1);
    reinterpret_cast<uint2*>(outp)[lane] = st;
}

// ---------------------------------------------------------------------------
// Layer-2 GEMM, fp16 input, multi-output: paper blocks produce mA (W2_cites)
// and mC (W2_writtenby) from one h1p tile; author blocks produce mB (W2_writes).
// ---------------------------------------------------------------------------
__global__ void __launch_bounds__(256)
gemm16_l2(const __half* __restrict__ Xp, const __half* __restrict__ Xa,
          const float* __restrict__ Wc,  const float* __restrict__ bc,  float* __restrict__ mA,
          const float* __restrict__ Wwb, const float* __restrict__ bwb, float* __restrict__ mC,
          const float* __restrict__ Wwr, const float* __restrict__ bwr, float* __restrict__ mB,
          int nP, int nA, int nbP) {
    __shared__ float xs[128][33];
    __shared__ float wsA[128 * 16];
    __shared__ float wsB[128 * 16];
    __shared__ float bsA[16], bsB[16];

    const int tid = threadIdx.x;
    const bool paper = (int)blockIdx.x < nbP;
    const __half* X = paper ? Xp : Xa;
    const int M = paper ? nP : nA;
    const int row_base = (paper ? blockIdx.x : blockIdx.x - nbP) * 128;
    const float* WA = paper ? Wc : Wwr;
    const float* bA = paper ? bc : bwr;
    float* YA = paper ? mA : mB;

    // Load full weights up front
#pragma unroll
    for (int i = 0; i < 8; i++) {
        int idx = tid + 256 * i;
        wsA[idx] = __ldg(WA + idx);
        if (paper) wsB[idx] = __ldg(Wwb + idx);
    }
    if (tid < 16) {
        bsA[tid] = bA[tid];
        if (paper) bsB[tid] = bwb[tid];
    }

    const int tx = tid & 15;
    const int ty = tid >> 4;

    float accA[8], accB[8];
#pragma unroll
    for (int i = 0; i < 8; i++) { accA[i] = 0.f; accB[i] = 0.f; }

    for (int kc = 0; kc < 4; kc++) {
        // Load 128 rows x 32 k (fp16 -> fp32 smem)
#pragma unroll
        for (int i = 0; i < 8; i++) {
            int idx = tid + 256 * i;        // 0..2047
            int r = idx >> 4, c2 = idx & 15;
            int gr = row_base + r;
            float2 f = make_float2(0.f, 0.f);
            if (gr < M)
                f = __half22float2(__ldg(reinterpret_cast<const __half2*>(X + (long)gr * 128 + kc * 32) + c2));
            xs[r][c2 * 2 + 0] = f.x;
            xs[r][c2 * 2 + 1] = f.y;
        }
        __syncthreads();

#pragma unroll
        for (int k = 0; k < 32; k++) {
            float wvA = wsA[(kc * 32 + k) * 16 + tx];
            float wvB = wsB[(kc * 32 + k) * 16 + tx];
#pragma unroll
            for (int rm = 0; rm < 8; rm++) {
                float xv = xs[ty * 8 + rm][k];
                accA[rm] += xv * wvA;
                accB[rm] += xv * wvB;
            }
        }
        __syncthreads();
    }

#pragma unroll
    for (int rm = 0; rm < 8; rm++) {
        int gr = row_base + ty * 8 + rm;
        if (gr < M) {
            YA[(long)gr * 16 + tx] = accA[rm] + bsA[tx];
            if (paper) mC[(long)gr * 16 + tx] = accB[rm] + bsB[tx];
        }
    }
}

// ---------------------------------------------------------------------------
// Layer-2 fused gather (F=16 fp32): rows [0,nP) papers dual, [nP,nP+nA) authors.
// ---------------------------------------------------------------------------
__global__ void gather_l2(const float* __restrict__ mA, const int* __restrict__ offs0,
                          const int* __restrict__ csr0,
                          const float* __restrict__ mB, const int* __restrict__ offs2,
                          const int* __restrict__ csr2,
                          const float* __restrict__ mC, const int* __restrict__ offs1,
                          const int* __restrict__ csr1,
                          float* __restrict__ out_paper, float* __restrict__ out_author,
                          int nP, int nA) {
    long idx = (long)blockIdx.x * blockDim.x + threadIdx.x;
    if (idx >= (long)(nP + nA) * 4) return;
    int dr = (int)(idx >> 2), q = (int)(idx & 3);
    float4 acc = make_float4(0.f, 0.f, 0.f, 0.f);
    float* outp;

    if (dr < nP) {
        int d = dr;
        int a0 = __ldg(offs0 + d), a1 = __ldg(offs0 + d + 1);
        for (int j = a0; j < a1; j++) {
            int s = __ldg(csr0 + j);
            float4 v = __ldg(reinterpret_cast<const float4*>(mA + (long)s * 16) + q);
            acc.x += v.x; acc.y += v.y; acc.z += v.z; acc.w += v.w;
        }
        acc.x = fmaxf(acc.x, 0.f); acc.y = fmaxf(acc.y, 0.f);
        acc.z = fmaxf(acc.z, 0.f); acc.w = fmaxf(acc.w, 0.f);
        int b0 = __ldg(offs2 + d), b1e = __ldg(offs2 + d + 1);
        for (int j = b0; j < b1e; j++) {
            int s = __ldg(csr2 + j);
            float4 v = __ldg(reinterpret_cast<const float4*>(mB + (long)s * 16) + q);
            acc.x += v.x; acc.y += v.y; acc.z += v.z; acc.w += v.w;
        }
        outp = out_paper + (long)d * 16;
    } else {
        int d = dr - nP;
        int s0 = __ldg(offs1 + d), s1 = __ldg(offs1 + d + 1);
        for (int j = s0; j < s1; j++) {
            int s = __ldg(csr1 + j);
            float4 v = __ldg(reinterpret_cast<const float4*>(mC + (long)s * 16) + q);
            acc.x += v.x; acc.y += v.y; acc.z += v.z; acc.w += v.w;
        }
        outp = out_author + (long)d * 16;
    }
    acc.x = fmaxf(acc.x, 0.f); acc.y = fmaxf(acc.y, 0.f);
    acc.z = fmaxf(acc.z, 0.f); acc.w = fmaxf(acc.w, 0.f);
    reinterpret_cast<float4*>(outp)[q] = acc;
}

static inline int cdiv(long a, long b) { return (int)((a + b - 1) / b); }

// ---------------------------------------------------------------------------
extern "C" void kernel_launch(void* const* d_in, const int* in_sizes, int n_in,
                              void* d_out, int out_size) {
    const float* embed_paper  = (const float*)d_in[0];
    const float* embed_author = (const float*)d_in[1];
    const float* W1_cites     = (const float*)d_in[2];
    const float* b1_cites     = (const float*)d_in[3];
    const float* W1_writtenby = (const float*)d_in[4];
    const float* b1_writtenby = (const float*)d_in[5];
    const float* W1_writes    = (const float*)d_in[6];
    const float* b1_writes    = (const float*)d_in[7];
    const float* W2_cites     = (const float*)d_in[8];
    const float* b2_cites     = (const float*)d_in[9];
    const float* W2_writtenby = (const float*)d_in[10];
    const float* b2_writtenby = (const float*)d_in[11];
    const float* W2_writes    = (const float*)d_in[12];
    const float* b2_writes    = (const float*)d_in[13];
    const int* cites_src      = (const int*)d_in[14];
    const int* cites_dst      = (const int*)d_in[15];
    const int* writtenby_src  = (const int*)d_in[16];
    const int* writtenby_dst  = (const int*)d_in[17];
    const int* writes_src     = (const int*)d_in[18];
    const int* writes_dst     = (const int*)d_in[19];

    const int n_paper  = in_sizes[0] / 128;
    const int n_author = in_sizes[1] / 128;
    const int E0 = in_sizes[14];   // cites
    const int E1 = in_sizes[16];   // writtenby
    const int E2 = in_sizes[18];   // writes

    __nv_bfloat16 *m0, *m1, *m2;
    __half *h1p, *h1a;
    float *mA, *mB, *mC;
    cudaGetSymbolAddress((void**)&m0,  g_m0);
    cudaGetSymbolAddress((void**)&m1,  g_m1);
    cudaGetSymbolAddress((void**)&m2,  g_m2);
    cudaGetSymbolAddress((void**)&h1p, g_h1p);
    cudaGetSymbolAddress((void**)&h1a, g_h1a);
    cudaGetSymbolAddress((void**)&mA,  g_mA);
    cudaGetSymbolAddress((void**)&mB,  g_mB);
    cudaGetSymbolAddress((void**)&mC,  g_mC);
    int *offs0, *offs1, *offs2, *csr0, *csr1, *csr2, *deg, *cur, *bsum;
    cudaGetSymbolAddress((void**)&offs0, g_offs0);
    cudaGetSymbolAddress((void**)&offs1, g_offs1);
    cudaGetSymbolAddress((void**)&offs2, g_offs2);
    cudaGetSymbolAddress((void**)&csr0, g_csr0);
    cudaGetSymbolAddress((void**)&csr1, g_csr1);
    cudaGetSymbolAddress((void**)&csr2, g_csr2);
    cudaGetSymbolAddress((void**)&deg,  g_deg);
    cudaGetSymbolAddress((void**)&cur,  g_cur);
    cudaGetSymbolAddress((void**)&bsum, g_bsum);

    cudaFuncSetAttribute(gemm128_l1,
                         cudaFuncAttributeMaxDynamicSharedMemorySize, GEMM128_SMEM);

    float* out_paper  = (float*)d_out;
    float* out_author = (float*)d_out + (long)n_paper * 16;

    // ---------------- Batched CSR build ----------------
    cudaMemsetAsync(deg, 0, (size_t)(2 * NP_PAD + NA_PAD) * sizeof(int));
    hist3<<<cdiv((long)E0 + E1 + E2, 256), 256>>>(cites_dst, writtenby_dst, writes_dst,
                                                  deg, E0, E1, E2);
    int nb0 = cdiv(n_paper, 4096), nb1 = cdiv(n_author, 4096), nb2 = cdiv(n_paper, 4096);
    scan_block3<<<nb0 + nb1 + nb2, 256>>>(deg, offs0, offs1, offs2, bsum,
                                          n_paper, n_author, n_paper);
    scan_bsums3<<<3, 32>>>(bsum, nb0, nb1, nb2);
    scan_add3<<<cdiv((long)n_paper + n_author + n_paper, 256), 256>>>(
        offs0, offs1, offs2, bsum, cur, n_paper, n_author, n_paper, E0, E1, E2);
    fill3<<<cdiv((long)E0 + E1 + E2, 256), 256>>>(
        cites_src, cites_dst, writtenby_src, writtenby_dst, writes_src, writes_dst,
        cur, csr0, csr1, csr2, E0, E1, E2);

    // ---------------- Layer 1 ----------------
    const int nbP128 = cdiv(n_paper, 128), nbA128 = cdiv(n_author, 128);
    gemm128_l1<<<nbP128 + nbA128, 256, GEMM128_SMEM>>>(
        embed_paper, embed_author,
        W1_cites, b1_cites, m0,
        W1_writtenby, b1_writtenby, m2,
        W1_writes, b1_writes, m1,
        n_paper, n_author, nbP128);

    gather_l1<<<cdiv((long)n_paper + n_author, 8), 256>>>(
        m0, offs0, csr0, m1, offs2, csr2, m2, offs1, csr1,
        h1p, h1a, n_paper, n_author);

    // ---------------- Layer 2 ----------------
    gemm16_l2<<<nbP128 + nbA128, 256>>>(
        h1p, h1a,
        W2_cites, b2_cites, mA,
        W2_writtenby, b2_writtenby, mC,
        W2_writes, b2_writes, mB,
        n_paper, n_author, nbP128);

    gather_l2<<<cdiv(((long)n_paper + n_author) * 4, 256), 256>>>(
        mA, offs0, csr0, mB, offs2, csr2, mC, offs1, csr1,
        out_paper, out_author, n_paper, n_author);
}

// round 7
// speedup vs baseline: 3.5909x; 1.0449x over previous
#include <cuda_runtime.h>
#include <cuda_bf16.h>
#include <cuda_fp16.h>
#include <cstdint>

// ---------------------------------------------------------------------------
// EntityClassify: 2-layer hetero R-GCN.
// R7: CSR build overlapped with L1 GEMM on a side stream (graph fork/join),
//     2-way unrolled gather loops for MLP. Multi-output GEMMs, fp16 h1.
// ---------------------------------------------------------------------------

#define N_PAPER_MAX 200000
#define N_AUTHOR_MAX 100000
#define E_MAX 500000
#define NP_PAD 200064
#define NA_PAD 100064

// layer-1 messages (bf16)
__device__ __nv_bfloat16 g_m0[N_PAPER_MAX * 128];   // embed_paper  @ W1_cites
__device__ __nv_bfloat16 g_m2[N_PAPER_MAX * 128];   // embed_paper  @ W1_writtenby
__device__ __nv_bfloat16 g_m1[N_AUTHOR_MAX * 128];  // embed_author @ W1_writes
// layer-1 outputs (fp16)
__device__ __half g_h1p[N_PAPER_MAX * 128];
__device__ __half g_h1a[N_AUTHOR_MAX * 128];
// layer-2 messages (fp32)
__device__ float g_mA[N_PAPER_MAX * 16];
__device__ float g_mC[N_PAPER_MAX * 16];
__device__ float g_mB[N_AUTHOR_MAX * 16];

// CSR scratch (0=cites->paper, 1=writtenby->author, 2=writes->paper)
__device__ int g_offs0[NP_PAD + 1];
__device__ int g_offs1[NA_PAD + 1];
__device__ int g_offs2[NP_PAD + 1];
__device__ int g_csr0[E_MAX];
__device__ int g_csr1[E_MAX];
__device__ int g_csr2[E_MAX];
__device__ int g_deg[2 * NP_PAD + NA_PAD];
__device__ int g_cur[2 * NP_PAD + NA_PAD];
__device__ int g_bsum[3 * 64];

__device__ __forceinline__ uint32_t pack_bf2(float a, float b) {
    __nv_bfloat162 p = __floats2bfloat162_rn(a, b);
    return *reinterpret_cast<uint32_t*>(&p);
}

__device__ __forceinline__ void mma_bf16(float* c, const uint32_t* a,
                                         uint32_t b0, uint32_t b1) {
    asm volatile(
        "mma.sync.aligned.m16n8k16.row.col.f32.bf16.bf16.f32 "
        "{%0,%1,%2,%3}, {%4,%5,%6,%7}, {%8,%9}, {%0,%1,%2,%3};"
        : "+f"(c[0]), "+f"(c[1]), "+f"(c[2]), "+f"(c[3])
        : "r"(a[0]), "r"(a[1]), "r"(a[2]), "r"(a[3]), "r"(b0), "r"(b1));
}

__device__ __forceinline__ void bf2_acc(float4& acc, uint2 v) {
    float2 f0 = __bfloat1622float2(*reinterpret_cast<__nv_bfloat162*>(&v.x));
    float2 f1 = __bfloat1622float2(*reinterpret_cast<__nv_bfloat162*>(&v.y));
    acc.x += f0.x; acc.y += f0.y; acc.z += f1.x; acc.w += f1.y;
}

// ---------------------------------------------------------------------------
// Batched CSR build
// ---------------------------------------------------------------------------
__global__ void hist3(const int* __restrict__ d0, const int* __restrict__ d1,
                      const int* __restrict__ d2, int* __restrict__ deg,
                      int E0, int E1, int E2) {
    int i = blockIdx.x * blockDim.x + threadIdx.x;
    if (i < E0) {
        atomicAdd(&deg[d0[i]], 1);
    } else if (i < E0 + E1) {
        atomicAdd(&deg[NP_PAD + d1[i - E0]], 1);
    } else if (i < E0 + E1 + E2) {
        atomicAdd(&deg[NP_PAD + NA_PAD + d2[i - E0 - E1]], 1);
    }
}

__global__ void scan_block3(const int* __restrict__ deg,
                            int* __restrict__ offs0, int* __restrict__ offs1,
                            int* __restrict__ offs2, int* __restrict__ bsum,
                            int n0, int n1, int n2) {
    const int nb0 = (n0 + 4095) >> 12, nb1 = (n1 + 4095) >> 12;
    int b = blockIdx.x;
    int rel, lb, n;
    const int* dg;
    int* offs;
    if (b < nb0)            { rel = 0; lb = b;             dg = deg;                   offs = offs0; n = n0; }
    else if (b < nb0 + nb1) { rel = 1; lb = b - nb0;       dg = deg + NP_PAD;          offs = offs1; n = n1; }
    else                    { rel = 2; lb = b - nb0 - nb1; dg = deg + NP_PAD + NA_PAD; offs = offs2; n = n2; }

    const int i0 = lb * 4096 + threadIdx.x * 16;
    int vals[16];
    int s = 0;
#pragma unroll
    for (int j = 0; j < 16; j++) {
        int idx = i0 + j;
        int v = (idx < n) ? dg[idx] : 0;
        vals[j] = s;
        s += v;
    }
    int lane = threadIdx.x & 31, wid = threadIdx.x >> 5;
    int x = s;
#pragma unroll
    for (int o = 1; o < 32; o <<= 1) {
        int y = __shfl_up_sync(0xffffffffu, x, o);
        if (lane >= o) x += y;
    }
    __shared__ int wsum[8];
    if (lane == 31) wsum[wid] = x;
    __syncthreads();
    if (wid == 0 && lane < 8) {
        int y = wsum[lane];
#pragma unroll
        for (int o = 1; o < 8; o <<= 1) {
            int z = __shfl_up_sync(0xffu, y, o);
            if (lane >= o) y += z;
        }
        wsum[lane] = y;
    }
    __syncthreads();
    int thread_excl = (x - s) + (wid > 0 ? wsum[wid - 1] : 0);
#pragma unroll
    for (int j = 0; j < 16; j++) {
        int idx = i0 + j;
        if (idx < n) offs[idx] = thread_excl + vals[j];
    }
    if (threadIdx.x == 255) bsum[rel * 64 + lb] = thread_excl + s;
}

__global__ void scan_bsums3(int* __restrict__ bsum, int nb0, int nb1, int nb2) {
    int r = blockIdx.x;
    int nb = (r == 0) ? nb0 : (r == 1) ? nb1 : nb2;
    if (threadIdx.x == 0) {
        int* p = bsum + r * 64;
        int s = 0;
        for (int i = 0; i < nb; i++) { int x = p[i]; p[i] = s; s += x; }
    }
}

__global__ void scan_add3(int* __restrict__ offs0, int* __restrict__ offs1,
                          int* __restrict__ offs2, const int* __restrict__ bsum,
                          int* __restrict__ cur,
                          int n0, int n1, int n2, int E0, int E1, int E2) {
    int i = blockIdx.x * blockDim.x + threadIdx.x;
    if (i < n0) {
        int v = offs0[i] + bsum[i >> 12];
        offs0[i] = v; cur[i] = v;
        if (i == 0) offs0[n0] = E0;
    } else if (i < n0 + n1) {
        int j = i - n0;
        int v = offs1[j] + bsum[64 + (j >> 12)];
        offs1[j] = v; cur[NP_PAD + j] = v;
        if (j == 0) offs1[n1] = E1;
    } else if (i < n0 + n1 + n2) {
        int j = i - n0 - n1;
        int v = offs2[j] + bsum[128 + (j >> 12)];
        offs2[j] = v; cur[NP_PAD + NA_PAD + j] = v;
        if (j == 0) offs2[n2] = E2;
    }
}

__global__ void fill3(const int* __restrict__ s0, const int* __restrict__ d0,
                      const int* __restrict__ s1, const int* __restrict__ d1,
                      const int* __restrict__ s2, const int* __restrict__ d2,
                      int* __restrict__ cur,
                      int* __restrict__ c0, int* __restrict__ c1, int* __restrict__ c2,
                      int E0, int E1, int E2) {
    int i = blockIdx.x * blockDim.x + threadIdx.x;
    if (i < E0) {
        int p = atomicAdd(&cur[d0[i]], 1);
        c0[p] = s0[i];
    } else if (i < E0 + E1) {
        int j = i - E0;
        int p = atomicAdd(&cur[NP_PAD + d1[j]], 1);
        c1[p] = s1[j];
    } else if (i < E0 + E1 + E2) {
        int j = i - E0 - E1;
        int p = atomicAdd(&cur[NP_PAD + NA_PAD + d2[j]], 1);
        c2[p] = s2[j];
    }
}

// ---------------------------------------------------------------------------
// Layer-1 GEMM, multi-output (paper: 2 phases, author: 1), bf16 MMA.
// ---------------------------------------------------------------------------
#define XS_STRIDE 68
#define GEMM128_SMEM (2 * 128 * XS_STRIDE * 4)

__global__ void __launch_bounds__(256)
gemm128_l1(const float* __restrict__ Xp, const float* __restrict__ Xa,
           const float* __restrict__ Wc,  const float* __restrict__ bc,  __nv_bfloat16* __restrict__ m0,
           const float* __restrict__ Wwb, const float* __restrict__ bwb, __nv_bfloat16* __restrict__ m2,
           const float* __restrict__ Wwr, const float* __restrict__ bwr, __nv_bfloat16* __restrict__ m1,
           int nP, int nA, int nbP) {
    extern __shared__ uint32_t sm[];
    uint32_t* xs = sm;
    uint32_t* wt = sm + 128 * XS_STRIDE;
    __shared__ float bs[128];

    const int tid = threadIdx.x;
    const int wid = tid >> 5, lane = tid & 31;
    const int g = lane >> 2, tg = lane & 3;
    const int wrow = (wid >> 1) * 32;
    const int wcol = (wid & 1) * 64;

    const bool paper = (int)blockIdx.x < nbP;
    const float* X = paper ? Xp : Xa;
    const int M = paper ? nP : nA;
    const int row_base = (paper ? blockIdx.x : blockIdx.x - nbP) * 128;
    const int nphase = paper ? 2 : 1;
    const float* Wl[2]  = { paper ? Wc : Wwr,  Wwb };
    const float* bl[2]  = { paper ? bc : bwr,  bwb };
    __nv_bfloat16* Yl[2] = { paper ? m0 : m1,  m2 };

#pragma unroll
    for (int i = 0; i < 16; i++) {
        int idx = tid + 256 * i;
        int r = idx >> 5, c4 = idx & 31;
        int gr = row_base + r;
        float4 v = make_float4(0.f, 0.f, 0.f, 0.f);
        if (gr < M) v = __ldg(reinterpret_cast<const float4*>(X + (long)gr * 128) + c4);
        xs[r * XS_STRIDE + c4 * 2 + 0] = pack_bf2(v.x, v.y);
        xs[r * XS_STRIDE + c4 * 2 + 1] = pack_bf2(v.z, v.w);
    }

    for (int ph = 0; ph < nphase; ph++) {
        const float* W = Wl[ph];
#pragma unroll
        for (int i = 0; i < 8; i++) {
            int u = tid + 256 * i;
            int n4 = u >> 6;
            int kp = u & 63;
            float4 wa = __ldg(reinterpret_cast<const float4*>(W + (long)(2 * kp) * 128) + n4);
            float4 wb = __ldg(reinterpret_cast<const float4*>(W + (long)(2 * kp + 1) * 128) + n4);
            wt[(n4 * 4 + 0) * XS_STRIDE + kp] = pack_bf2(wa.x, wb.x);
            wt[(n4 * 4 + 1) * XS_STRIDE + kp] = pack_bf2(wa.y, wb.y);
            wt[(n4 * 4 + 2) * XS_STRIDE + kp] = pack_bf2(wa.z, wb.z);
            wt[(n4 * 4 + 3) * XS_STRIDE + kp] = pack_bf2(wa.w, wb.w);
        }
        if (tid < 128) bs[tid] = bl[ph][tid];
        __syncthreads();

        float acc[2][8][4];
#pragma unroll
        for (int mi = 0; mi < 2; mi++)
#pragma unroll
            for (int nt = 0; nt < 8; nt++)
#pragma unroll
                for (int j = 0; j < 4; j++) acc[mi][nt][j] = 0.f;

#pragma unroll
        for (int s = 0; s < 8; s++) {
            uint32_t a[2][4];
#pragma unroll
            for (int mi = 0; mi < 2; mi++) {
                int rb = (wrow + mi * 16 + g) * XS_STRIDE + s * 8;
                int rb8 = rb + 8 * XS_STRIDE;
                a[mi][0] = xs[rb + tg];
                a[mi][1] = xs[rb8 + tg];
                a[mi][2] = xs[rb + 4 + tg];
                a[mi][3] = xs[rb8 + 4 + tg];
            }
#pragma unroll
            for (int nt = 0; nt < 8; nt++) {
                int cb = (wcol + nt * 8 + g) * XS_STRIDE + s * 8 + tg;
                uint32_t b0 = wt[cb];
                uint32_t b1 = wt[cb + 4];
                mma_bf16(acc[0][nt], a[0], b0, b1);
                mma_bf16(acc[1][nt], a[1], b0, b1);
            }
        }

        uint32_t* Yu = reinterpret_cast<uint32_t*>(Yl[ph]);
#pragma unroll
        for (int mi = 0; mi < 2; mi++) {
            int r0 = row_base + wrow + mi * 16 + g;
            int r1 = r0 + 8;
#pragma unroll
            for (int nt = 0; nt < 8; nt++) {
                int c = wcol + nt * 8 + tg * 2;
                if (r0 < M)
                    Yu[(long)r0 * 64 + (c >> 1)] = pack_bf2(acc[mi][nt][0] + bs[c], acc[mi][nt][1] + bs[c + 1]);
                if (r1 < M)
                    Yu[(long)r1 * 64 + (c >> 1)] = pack_bf2(acc[mi][nt][2] + bs[c], acc[mi][nt][3] + bs[c + 1]);
            }
        }
        __syncthreads();
    }
}

// ---------------------------------------------------------------------------
// Layer-1 fused gather (2-way unrolled loops). bf16 in, fp16 out.
// ---------------------------------------------------------------------------
__device__ __forceinline__ void gather_rel_128(const __nv_bfloat16* __restrict__ m,
                                               const int* __restrict__ csr,
                                               int j0, int j1, int lane, float4& acc) {
    int j = j0;
    for (; j + 2 <= j1; j += 2) {
        int sa = __ldg(csr + j), sb = __ldg(csr + j + 1);
        uint2 va = __ldg(reinterpret_cast<const uint2*>(m + (long)sa * 128) + lane);
        uint2 vb = __ldg(reinterpret_cast<const uint2*>(m + (long)sb * 128) + lane);
        bf2_acc(acc, va);
        bf2_acc(acc, vb);
    }
    if (j < j1) {
        int sa = __ldg(csr + j);
        uint2 va = __ldg(reinterpret_cast<const uint2*>(m + (long)sa * 128) + lane);
        bf2_acc(acc, va);
    }
}

__global__ void gather_l1(const __nv_bfloat16* __restrict__ m0, const int* __restrict__ offs0,
                          const int* __restrict__ csr0,
                          const __nv_bfloat16* __restrict__ m1, const int* __restrict__ offs2,
                          const int* __restrict__ csr2,
                          const __nv_bfloat16* __restrict__ m2, const int* __restrict__ offs1,
                          const int* __restrict__ csr1,
                          __half* __restrict__ h1p, __half* __restrict__ h1a,
                          int nP, int nA) {
    int w = blockIdx.x * (blockDim.x >> 5) + (threadIdx.x >> 5);
    int lane = threadIdx.x & 31;
    float4 acc = make_float4(0.f, 0.f, 0.f, 0.f);
    __half* outp;

    if (w < nP) {
        int d = w;
        gather_rel_128(m0, csr0, __ldg(offs0 + d), __ldg(offs0 + d + 1), lane, acc);
        acc.x = fmaxf(acc.x, 0.f); acc.y = fmaxf(acc.y, 0.f);
        acc.z = fmaxf(acc.z, 0.f); acc.w = fmaxf(acc.w, 0.f);
        gather_rel_128(m1, csr2, __ldg(offs2 + d), __ldg(offs2 + d + 1), lane, acc);
        outp = h1p + (long)d * 128;
    } else {
        int d = w - nP;
        if (d >= nA) return;
        gather_rel_128(m2, csr1, __ldg(offs1 + d), __ldg(offs1 + d + 1), lane, acc);
        outp = h1a + (long)d * 128;
    }
    acc.x = fmaxf(acc.x, 0.f); acc.y = fmaxf(acc.y, 0.f);
    acc.z = fmaxf(acc.z, 0.f); acc.w = fmaxf(acc.w, 0.f);
    __half2 p0 = __floats2half2_rn(acc.x, acc.y);
    __half2 p1 = __floats2half2_rn(acc.z, acc.w);
    uint2 st;
    st.x = *reinterpret_cast<uint32_t*>(&p0);
    st.y = *reinterpret_cast<uint32_t*>(&p1);
    reinterpret_cast<uint2*>(outp)[lane] = st;
}

// ---------------------------------------------------------------------------
// Layer-2 GEMM, fp16 input, multi-output.
// ---------------------------------------------------------------------------
__global__ void __launch_bounds__(256)
gemm16_l2(const __half* __restrict__ Xp, const __half* __restrict__ Xa,
          const float* __restrict__ Wc,  const float* __restrict__ bc,  float* __restrict__ mA,
          const float* __restrict__ Wwb, const float* __restrict__ bwb, float* __restrict__ mC,
          const float* __restrict__ Wwr, const float* __restrict__ bwr, float* __restrict__ mB,
          int nP, int nA, int nbP) {
    __shared__ float xs[128][33];
    __shared__ float wsA[128 * 16];
    __shared__ float wsB[128 * 16];
    __shared__ float bsA[16], bsB[16];

    const int tid = threadIdx.x;
    const bool paper = (int)blockIdx.x < nbP;
    const __half* X = paper ? Xp : Xa;
    const int M = paper ? nP : nA;
    const int row_base = (paper ? blockIdx.x : blockIdx.x - nbP) * 128;
    const float* WA = paper ? Wc : Wwr;
    const float* bA = paper ? bc : bwr;
    float* YA = paper ? mA : mB;

#pragma unroll
    for (int i = 0; i < 8; i++) {
        int idx = tid + 256 * i;
        wsA[idx] = __ldg(WA + idx);
        if (paper) wsB[idx] = __ldg(Wwb + idx);
    }
    if (tid < 16) {
        bsA[tid] = bA[tid];
        if (paper) bsB[tid] = bwb[tid];
    }

    const int tx = tid & 15;
    const int ty = tid >> 4;

    float accA[8], accB[8];
#pragma unroll
    for (int i = 0; i < 8; i++) { accA[i] = 0.f; accB[i] = 0.f; }

    for (int kc = 0; kc < 4; kc++) {
#pragma unroll
        for (int i = 0; i < 8; i++) {
            int idx = tid + 256 * i;
            int r = idx >> 4, c2 = idx & 15;
            int gr = row_base + r;
            float2 f = make_float2(0.f, 0.f);
            if (gr < M)
                f = __half22float2(__ldg(reinterpret_cast<const __half2*>(X + (long)gr * 128 + kc * 32) + c2));
            xs[r][c2 * 2 + 0] = f.x;
            xs[r][c2 * 2 + 1] = f.y;
        }
        __syncthreads();

#pragma unroll
        for (int k = 0; k < 32; k++) {
            float wvA = wsA[(kc * 32 + k) * 16 + tx];
            float wvB = wsB[(kc * 32 + k) * 16 + tx];
#pragma unroll
            for (int rm = 0; rm < 8; rm++) {
                float xv = xs[ty * 8 + rm][k];
                accA[rm] += xv * wvA;
                accB[rm] += xv * wvB;
            }
        }
        __syncthreads();
    }

#pragma unroll
    for (int rm = 0; rm < 8; rm++) {
        int gr = row_base + ty * 8 + rm;
        if (gr < M) {
            YA[(long)gr * 16 + tx] = accA[rm] + bsA[tx];
            if (paper) mC[(long)gr * 16 + tx] = accB[rm] + bsB[tx];
        }
    }
}

// ---------------------------------------------------------------------------
// Layer-2 fused gather (F=16 fp32, 2-way unrolled).
// ---------------------------------------------------------------------------
__device__ __forceinline__ void gather_rel_16(const float* __restrict__ m,
                                              const int* __restrict__ csr,
                                              int j0, int j1, int q, float4& acc) {
    int j = j0;
    for (; j + 2 <= j1; j += 2) {
        int sa = __ldg(csr + j), sb = __ldg(csr + j + 1);
        float4 va = __ldg(reinterpret_cast<const float4*>(m + (long)sa * 16) + q);
        float4 vb = __ldg(reinterpret_cast<const float4*>(m + (long)sb * 16) + q);
        acc.x += va.x + vb.x; acc.y += va.y + vb.y;
        acc.z += va.z + vb.z; acc.w += va.w + vb.w;
    }
    if (j < j1) {
        int sa = __ldg(csr + j);
        float4 va = __ldg(reinterpret_cast<const float4*>(m + (long)sa * 16) + q);
        acc.x += va.x; acc.y += va.y; acc.z += va.z; acc.w += va.w;
    }
}

__global__ void gather_l2(const float* __restrict__ mA, const int* __restrict__ offs0,
                          const int* __restrict__ csr0,
                          const float* __restrict__ mB, const int* __restrict__ offs2,
                          const int* __restrict__ csr2,
                          const float* __restrict__ mC, const int* __restrict__ offs1,
                          const int* __restrict__ csr1,
                          float* __restrict__ out_paper, float* __restrict__ out_author,
                          int nP, int nA) {
    long idx = (long)blockIdx.x * blockDim.x + threadIdx.x;
    if (idx >= (long)(nP + nA) * 4) return;
    int dr = (int)(idx >> 2), q = (int)(idx & 3);
    float4 acc = make_float4(0.f, 0.f, 0.f, 0.f);
    float* outp;

    if (dr < nP) {
        int d = dr;
        gather_rel_16(mA, csr0, __ldg(offs0 + d), __ldg(offs0 + d + 1), q, acc);
        acc.x = fmaxf(acc.x, 0.f); acc.y = fmaxf(acc.y, 0.f);
        acc.z = fmaxf(acc.z, 0.f); acc.w = fmaxf(acc.w, 0.f);
        gather_rel_16(mB, csr2, __ldg(offs2 + d), __ldg(offs2 + d + 1), q, acc);
        outp = out_paper + (long)d * 16;
    } else {
        int d = dr - nP;
        gather_rel_16(mC, csr1, __ldg(offs1 + d), __ldg(offs1 + d + 1), q, acc);
        outp = out_author + (long)d * 16;
    }
    acc.x = fmaxf(acc.x, 0.f); acc.y = fmaxf(acc.y, 0.f);
    acc.z = fmaxf(acc.z, 0.f); acc.w = fmaxf(acc.w, 0.f);
    reinterpret_cast<float4*>(outp)[q] = acc;
}

static inline int cdiv(long a, long b) { return (int)((a + b - 1) / b); }

// ---------------------------------------------------------------------------
extern "C" void kernel_launch(void* const* d_in, const int* in_sizes, int n_in,
                              void* d_out, int out_size) {
    const float* embed_paper  = (const float*)d_in[0];
    const float* embed_author = (const float*)d_in[1];
    const float* W1_cites     = (const float*)d_in[2];
    const float* b1_cites     = (const float*)d_in[3];
    const float* W1_writtenby = (const float*)d_in[4];
    const float* b1_writtenby = (const float*)d_in[5];
    const float* W1_writes    = (const float*)d_in[6];
    const float* b1_writes    = (const float*)d_in[7];
    const float* W2_cites     = (const float*)d_in[8];
    const float* b2_cites     = (const float*)d_in[9];
    const float* W2_writtenby = (const float*)d_in[10];
    const float* b2_writtenby = (const float*)d_in[11];
    const float* W2_writes    = (const float*)d_in[12];
    const float* b2_writes    = (const float*)d_in[13];
    const int* cites_src      = (const int*)d_in[14];
    const int* cites_dst      = (const int*)d_in[15];
    const int* writtenby_src  = (const int*)d_in[16];
    const int* writtenby_dst  = (const int*)d_in[17];
    const int* writes_src     = (const int*)d_in[18];
    const int* writes_dst     = (const int*)d_in[19];

    const int n_paper  = in_sizes[0] / 128;
    const int n_author = in_sizes[1] / 128;
    const int E0 = in_sizes[14];
    const int E1 = in_sizes[16];
    const int E2 = in_sizes[18];

    __nv_bfloat16 *m0, *m1, *m2;
    __half *h1p, *h1a;
    float *mA, *mB, *mC;
    cudaGetSymbolAddress((void**)&m0,  g_m0);
    cudaGetSymbolAddress((void**)&m1,  g_m1);
    cudaGetSymbolAddress((void**)&m2,  g_m2);
    cudaGetSymbolAddress((void**)&h1p, g_h1p);
    cudaGetSymbolAddress((void**)&h1a, g_h1a);
    cudaGetSymbolAddress((void**)&mA,  g_mA);
    cudaGetSymbolAddress((void**)&mB,  g_mB);
    cudaGetSymbolAddress((void**)&mC,  g_mC);
    int *offs0, *offs1, *offs2, *csr0, *csr1, *csr2, *deg, *cur, *bsum;
    cudaGetSymbolAddress((void**)&offs0, g_offs0);
    cudaGetSymbolAddress((void**)&offs1, g_offs1);
    cudaGetSymbolAddress((void**)&offs2, g_offs2);
    cudaGetSymbolAddress((void**)&csr0, g_csr0);
    cudaGetSymbolAddress((void**)&csr1, g_csr1);
    cudaGetSymbolAddress((void**)&csr2, g_csr2);
    cudaGetSymbolAddress((void**)&deg,  g_deg);
    cudaGetSymbolAddress((void**)&cur,  g_cur);
    cudaGetSymbolAddress((void**)&bsum, g_bsum);

    cudaFuncSetAttribute(gemm128_l1,
                         cudaFuncAttributeMaxDynamicSharedMemorySize, GEMM128_SMEM);

    // Side stream + events for CSR/GEMM overlap (created once; capture-safe).
    static cudaStream_t s_side = nullptr;
    static cudaEvent_t s_evFork = nullptr, s_evJoin = nullptr;
    if (!s_side) {
        cudaStreamCreateWithFlags(&s_side, cudaStreamNonBlocking);
        cudaEventCreateWithFlags(&s_evFork, cudaEventDisableTiming);
        cudaEventCreateWithFlags(&s_evJoin, cudaEventDisableTiming);
    }

    float* out_paper  = (float*)d_out;
    float* out_author = (float*)d_out + (long)n_paper * 16;

    // ---------------- Fork: CSR build on side stream ----------------
    cudaEventRecord(s_evFork, 0);
    cudaStreamWaitEvent(s_side, s_evFork, 0);

    cudaMemsetAsync(deg, 0, (size_t)(2 * NP_PAD + NA_PAD) * sizeof(int), s_side);
    hist3<<<cdiv((long)E0 + E1 + E2, 256), 256, 0, s_side>>>(
        cites_dst, writtenby_dst, writes_dst, deg, E0, E1, E2);
    int nb0 = cdiv(n_paper, 4096), nb1 = cdiv(n_author, 4096), nb2 = cdiv(n_paper, 4096);
    scan_block3<<<nb0 + nb1 + nb2, 256, 0, s_side>>>(deg, offs0, offs1, offs2, bsum,
                                                     n_paper, n_author, n_paper);
    scan_bsums3<<<3, 32, 0, s_side>>>(bsum, nb0, nb1, nb2);
    scan_add3<<<cdiv((long)n_paper + n_author + n_paper, 256), 256, 0, s_side>>>(
        offs0, offs1, offs2, bsum, cur, n_paper, n_author, n_paper, E0, E1, E2);
    fill3<<<cdiv((long)E0 + E1 + E2, 256), 256, 0, s_side>>>(
        cites_src, cites_dst, writtenby_src, writtenby_dst, writes_src, writes_dst,
        cur, csr0, csr1, csr2, E0, E1, E2);
    cudaEventRecord(s_evJoin, s_side);

    // ---------------- Main stream: Layer-1 GEMM (independent of CSR) --------
    const int nbP128 = cdiv(n_paper, 128), nbA128 = cdiv(n_author, 128);
    gemm128_l1<<<nbP128 + nbA128, 256, GEMM128_SMEM>>>(
        embed_paper, embed_author,
        W1_cites, b1_cites, m0,
        W1_writtenby, b1_writtenby, m2,
        W1_writes, b1_writes, m1,
        n_paper, n_author, nbP128);

    // ---------------- Join, then gathers / layer 2 ----------------
    cudaStreamWaitEvent(0, s_evJoin, 0);

    gather_l1<<<cdiv((long)n_paper + n_author, 8), 256>>>(
        m0, offs0, csr0, m1, offs2, csr2, m2, offs1, csr1,
        h1p, h1a, n_paper, n_author);

    gemm16_l2<<<nbP128 + nbA128, 256>>>(
        h1p, h1a,
        W2_cites, b2_cites, mA,
        W2_writtenby, b2_writtenby, mC,
        W2_writes, b2_writes, mB,
        n_paper, n_author, nbP128);

    gather_l2<<<cdiv(((long)n_paper + n_author) * 4, 256), 256>>>(
        mA, offs0, csr0, mB, offs2, csr2, mC, offs1, csr1,
        out_paper, out_author, n_paper, n_author);
}

// round 8
// speedup vs baseline: 4.0874x; 1.1383x over previous
#include <cuda_runtime.h>
#include <cuda_bf16.h>
#include <cuda_fp16.h>
#include <cstdint>

// ---------------------------------------------------------------------------
// EntityClassify: 2-layer hetero R-GCN.
// R8: gather_l1 + layer-2 GEMM fused into one block-tile kernel (h1 lives in
//     smem only, layer-2 transform on fp16 tensor cores). CSR build overlapped
//     with L1 GEMM. 9 launches.
// ---------------------------------------------------------------------------

#define N_PAPER_MAX 200000
#define N_AUTHOR_MAX 100000
#define E_MAX 500000
#define NP_PAD 200064
#define NA_PAD 100064

// layer-1 messages (bf16)
__device__ __nv_bfloat16 g_m0[N_PAPER_MAX * 128];   // embed_paper  @ W1_cites
__device__ __nv_bfloat16 g_m2[N_PAPER_MAX * 128];   // embed_paper  @ W1_writtenby
__device__ __nv_bfloat16 g_m1[N_AUTHOR_MAX * 128];  // embed_author @ W1_writes
// layer-2 messages (fp32)
__device__ float g_mA[N_PAPER_MAX * 16];   // h1p @ W2_cites
__device__ float g_mC[N_PAPER_MAX * 16];   // h1p @ W2_writtenby
__device__ float g_mB[N_AUTHOR_MAX * 16];  // h1a @ W2_writes

// CSR scratch (0=cites->paper, 1=writtenby->author, 2=writes->paper)
__device__ int g_offs0[NP_PAD + 1];
__device__ int g_offs1[NA_PAD + 1];
__device__ int g_offs2[NP_PAD + 1];
__device__ int g_csr0[E_MAX];
__device__ int g_csr1[E_MAX];
__device__ int g_csr2[E_MAX];
__device__ int g_deg[2 * NP_PAD + NA_PAD];
__device__ int g_cur[2 * NP_PAD + NA_PAD];
__device__ int g_bsum[3 * 64];

__device__ __forceinline__ uint32_t pack_bf2(float a, float b) {
    __nv_bfloat162 p = __floats2bfloat162_rn(a, b);
    return *reinterpret_cast<uint32_t*>(&p);
}
__device__ __forceinline__ uint32_t pack_h2(float a, float b) {
    __half2 p = __floats2half2_rn(a, b);
    return *reinterpret_cast<uint32_t*>(&p);
}

__device__ __forceinline__ void mma_bf16(float* c, const uint32_t* a,
                                         uint32_t b0, uint32_t b1) {
    asm volatile(
        "mma.sync.aligned.m16n8k16.row.col.f32.bf16.bf16.f32 "
        "{%0,%1,%2,%3}, {%4,%5,%6,%7}, {%8,%9}, {%0,%1,%2,%3};"
        : "+f"(c[0]), "+f"(c[1]), "+f"(c[2]), "+f"(c[3])
        : "r"(a[0]), "r"(a[1]), "r"(a[2]), "r"(a[3]), "r"(b0), "r"(b1));
}

__device__ __forceinline__ void mma_f16(float* c, const uint32_t* a,
                                        uint32_t b0, uint32_t b1) {
    asm volatile(
        "mma.sync.aligned.m16n8k16.row.col.f32.f16.f16.f32 "
        "{%0,%1,%2,%3}, {%4,%5,%6,%7}, {%8,%9}, {%0,%1,%2,%3};"
        : "+f"(c[0]), "+f"(c[1]), "+f"(c[2]), "+f"(c[3])
        : "r"(a[0]), "r"(a[1]), "r"(a[2]), "r"(a[3]), "r"(b0), "r"(b1));
}

__device__ __forceinline__ void bf2_acc(float4& acc, uint2 v) {
    float2 f0 = __bfloat1622float2(*reinterpret_cast<__nv_bfloat162*>(&v.x));
    float2 f1 = __bfloat1622float2(*reinterpret_cast<__nv_bfloat162*>(&v.y));
    acc.x += f0.x; acc.y += f0.y; acc.z += f1.x; acc.w += f1.y;
}

// ---------------------------------------------------------------------------
// Batched CSR build
// ---------------------------------------------------------------------------
__global__ void hist3(const int* __restrict__ d0, const int* __restrict__ d1,
                      const int* __restrict__ d2, int* __restrict__ deg,
                      int E0, int E1, int E2) {
    int i = blockIdx.x * blockDim.x + threadIdx.x;
    if (i < E0) {
        atomicAdd(&deg[d0[i]], 1);
    } else if (i < E0 + E1) {
        atomicAdd(&deg[NP_PAD + d1[i - E0]], 1);
    } else if (i < E0 + E1 + E2) {
        atomicAdd(&deg[NP_PAD + NA_PAD + d2[i - E0 - E1]], 1);
    }
}

__global__ void scan_block3(const int* __restrict__ deg,
                            int* __restrict__ offs0, int* __restrict__ offs1,
                            int* __restrict__ offs2, int* __restrict__ bsum,
                            int n0, int n1, int n2) {
    const int nb0 = (n0 + 4095) >> 12, nb1 = (n1 + 4095) >> 12;
    int b = blockIdx.x;
    int rel, lb, n;
    const int* dg;
    int* offs;
    if (b < nb0)            { rel = 0; lb = b;             dg = deg;                   offs = offs0; n = n0; }
    else if (b < nb0 + nb1) { rel = 1; lb = b - nb0;       dg = deg + NP_PAD;          offs = offs1; n = n1; }
    else                    { rel = 2; lb = b - nb0 - nb1; dg = deg + NP_PAD + NA_PAD; offs = offs2; n = n2; }

    const int i0 = lb * 4096 + threadIdx.x * 16;
    int vals[16];
    int s = 0;
#pragma unroll
    for (int j = 0; j < 16; j++) {
        int idx = i0 + j;
        int v = (idx < n) ? dg[idx] : 0;
        vals[j] = s;
        s += v;
    }
    int lane = threadIdx.x & 31, wid = threadIdx.x >> 5;
    int x = s;
#pragma unroll
    for (int o = 1; o < 32; o <<= 1) {
        int y = __shfl_up_sync(0xffffffffu, x, o);
        if (lane >= o) x += y;
    }
    __shared__ int wsum[8];
    if (lane == 31) wsum[wid] = x;
    __syncthreads();
    if (wid == 0 && lane < 8) {
        int y = wsum[lane];
#pragma unroll
        for (int o = 1; o < 8; o <<= 1) {
            int z = __shfl_up_sync(0xffu, y, o);
            if (lane >= o) y += z;
        }
        wsum[lane] = y;
    }
    __syncthreads();
    int thread_excl = (x - s) + (wid > 0 ? wsum[wid - 1] : 0);
#pragma unroll
    for (int j = 0; j < 16; j++) {
        int idx = i0 + j;
        if (idx < n) offs[idx] = thread_excl + vals[j];
    }
    if (threadIdx.x == 255) bsum[rel * 64 + lb] = thread_excl + s;
}

__global__ void scan_bsums3(int* __restrict__ bsum, int nb0, int nb1, int nb2) {
    int r = blockIdx.x;
    int nb = (r == 0) ? nb0 : (r == 1) ? nb1 : nb2;
    if (threadIdx.x == 0) {
        int* p = bsum + r * 64;
        int s = 0;
        for (int i = 0; i < nb; i++) { int x = p[i]; p[i] = s; s += x; }
    }
}

__global__ void scan_add3(int* __restrict__ offs0, int* __restrict__ offs1,
                          int* __restrict__ offs2, const int* __restrict__ bsum,
                          int* __restrict__ cur,
                          int n0, int n1, int n2, int E0, int E1, int E2) {
    int i = blockIdx.x * blockDim.x + threadIdx.x;
    if (i < n0) {
        int v = offs0[i] + bsum[i >> 12];
        offs0[i] = v; cur[i] = v;
        if (i == 0) offs0[n0] = E0;
    } else if (i < n0 + n1) {
        int j = i - n0;
        int v = offs1[j] + bsum[64 + (j >> 12)];
        offs1[j] = v; cur[NP_PAD + j] = v;
        if (j == 0) offs1[n1] = E1;
    } else if (i < n0 + n1 + n2) {
        int j = i - n0 - n1;
        int v = offs2[j] + bsum[128 + (j >> 12)];
        offs2[j] = v; cur[NP_PAD + NA_PAD + j] = v;
        if (j == 0) offs2[n2] = E2;
    }
}

__global__ void fill3(const int* __restrict__ s0, const int* __restrict__ d0,
                      const int* __restrict__ s1, const int* __restrict__ d1,
                      const int* __restrict__ s2, const int* __restrict__ d2,
                      int* __restrict__ cur,
                      int* __restrict__ c0, int* __restrict__ c1, int* __restrict__ c2,
                      int E0, int E1, int E2) {
    int i = blockIdx.x * blockDim.x + threadIdx.x;
    if (i < E0) {
        int p = atomicAdd(&cur[d0[i]], 1);
        c0[p] = s0[i];
    } else if (i < E0 + E1) {
        int j = i - E0;
        int p = atomicAdd(&cur[NP_PAD + d1[j]], 1);
        c1[p] = s1[j];
    } else if (i < E0 + E1 + E2) {
        int j = i - E0 - E1;
        int p = atomicAdd(&cur[NP_PAD + NA_PAD + d2[j]], 1);
        c2[p] = s2[j];
    }
}

// ---------------------------------------------------------------------------
// Layer-1 GEMM, multi-output (paper: 2 phases, author: 1), bf16 MMA.
// ---------------------------------------------------------------------------
#define XS_STRIDE 68
#define GEMM128_SMEM (2 * 128 * XS_STRIDE * 4)

__global__ void __launch_bounds__(256)
gemm128_l1(const float* __restrict__ Xp, const float* __restrict__ Xa,
           const float* __restrict__ Wc,  const float* __restrict__ bc,  __nv_bfloat16* __restrict__ m0,
           const float* __restrict__ Wwb, const float* __restrict__ bwb, __nv_bfloat16* __restrict__ m2,
           const float* __restrict__ Wwr, const float* __restrict__ bwr, __nv_bfloat16* __restrict__ m1,
           int nP, int nA, int nbP) {
    extern __shared__ uint32_t sm[];
    uint32_t* xs = sm;
    uint32_t* wt = sm + 128 * XS_STRIDE;
    __shared__ float bs[128];

    const int tid = threadIdx.x;
    const int wid = tid >> 5, lane = tid & 31;
    const int g = lane >> 2, tg = lane & 3;
    const int wrow = (wid >> 1) * 32;
    const int wcol = (wid & 1) * 64;

    const bool paper = (int)blockIdx.x < nbP;
    const float* X = paper ? Xp : Xa;
    const int M = paper ? nP : nA;
    const int row_base = (paper ? blockIdx.x : blockIdx.x - nbP) * 128;
    const int nphase = paper ? 2 : 1;
    const float* Wl[2]  = { paper ? Wc : Wwr,  Wwb };
    const float* bl[2]  = { paper ? bc : bwr,  bwb };
    __nv_bfloat16* Yl[2] = { paper ? m0 : m1,  m2 };

#pragma unroll
    for (int i = 0; i < 16; i++) {
        int idx = tid + 256 * i;
        int r = idx >> 5, c4 = idx & 31;
        int gr = row_base + r;
        float4 v = make_float4(0.f, 0.f, 0.f, 0.f);
        if (gr < M) v = __ldg(reinterpret_cast<const float4*>(X + (long)gr * 128) + c4);
        xs[r * XS_STRIDE + c4 * 2 + 0] = pack_bf2(v.x, v.y);
        xs[r * XS_STRIDE + c4 * 2 + 1] = pack_bf2(v.z, v.w);
    }

    for (int ph = 0; ph < nphase; ph++) {
        const float* W = Wl[ph];
#pragma unroll
        for (int i = 0; i < 8; i++) {
            int u = tid + 256 * i;
            int n4 = u >> 6;
            int kp = u & 63;
            float4 wa = __ldg(reinterpret_cast<const float4*>(W + (long)(2 * kp) * 128) + n4);
            float4 wb = __ldg(reinterpret_cast<const float4*>(W + (long)(2 * kp + 1) * 128) + n4);
            wt[(n4 * 4 + 0) * XS_STRIDE + kp] = pack_bf2(wa.x, wb.x);
            wt[(n4 * 4 + 1) * XS_STRIDE + kp] = pack_bf2(wa.y, wb.y);
            wt[(n4 * 4 + 2) * XS_STRIDE + kp] = pack_bf2(wa.z, wb.z);
            wt[(n4 * 4 + 3) * XS_STRIDE + kp] = pack_bf2(wa.w, wb.w);
        }
        if (tid < 128) bs[tid] = bl[ph][tid];
        __syncthreads();

        float acc[2][8][4];
#pragma unroll
        for (int mi = 0; mi < 2; mi++)
#pragma unroll
            for (int nt = 0; nt < 8; nt++)
#pragma unroll
                for (int j = 0; j < 4; j++) acc[mi][nt][j] = 0.f;

#pragma unroll
        for (int s = 0; s < 8; s++) {
            uint32_t a[2][4];
#pragma unroll
            for (int mi = 0; mi < 2; mi++) {
                int rb = (wrow + mi * 16 + g) * XS_STRIDE + s * 8;
                int rb8 = rb + 8 * XS_STRIDE;
                a[mi][0] = xs[rb + tg];
                a[mi][1] = xs[rb8 + tg];
                a[mi][2] = xs[rb + 4 + tg];
                a[mi][3] = xs[rb8 + 4 + tg];
            }
#pragma unroll
            for (int nt = 0; nt < 8; nt++) {
                int cb = (wcol + nt * 8 + g) * XS_STRIDE + s * 8 + tg;
                uint32_t b0 = wt[cb];
                uint32_t b1 = wt[cb + 4];
                mma_bf16(acc[0][nt], a[0], b0, b1);
                mma_bf16(acc[1][nt], a[1], b0, b1);
            }
        }

        uint32_t* Yu = reinterpret_cast<uint32_t*>(Yl[ph]);
#pragma unroll
        for (int mi = 0; mi < 2; mi++) {
            int r0 = row_base + wrow + mi * 16 + g;
            int r1 = r0 + 8;
#pragma unroll
            for (int nt = 0; nt < 8; nt++) {
                int c = wcol + nt * 8 + tg * 2;
                if (r0 < M)
                    Yu[(long)r0 * 64 + (c >> 1)] = pack_bf2(acc[mi][nt][0] + bs[c], acc[mi][nt][1] + bs[c + 1]);
                if (r1 < M)
                    Yu[(long)r1 * 64 + (c >> 1)] = pack_bf2(acc[mi][nt][2] + bs[c], acc[mi][nt][3] + bs[c + 1]);
            }
        }
        __syncthreads();
    }
}

// ---------------------------------------------------------------------------
// Gather helper (2-way unrolled).
// ---------------------------------------------------------------------------
__device__ __forceinline__ void gather_rel_128(const __nv_bfloat16* __restrict__ m,
                                               const int* __restrict__ csr,
                                               int j0, int j1, int lane, float4& acc) {
    int j = j0;
    for (; j + 2 <= j1; j += 2) {
        int sa = __ldg(csr + j), sb = __ldg(csr + j + 1);
        uint2 va = __ldg(reinterpret_cast<const uint2*>(m + (long)sa * 128) + lane);
        uint2 vb = __ldg(reinterpret_cast<const uint2*>(m + (long)sb * 128) + lane);
        bf2_acc(acc, va);
        bf2_acc(acc, vb);
    }
    if (j < j1) {
        int sa = __ldg(csr + j);
        uint2 va = __ldg(reinterpret_cast<const uint2*>(m + (long)sa * 128) + lane);
        bf2_acc(acc, va);
    }
}

// ---------------------------------------------------------------------------
// Fused gather_l1 + layer-2 transform. Block = 128 dst rows.
// Phase A: warp-per-row gather (16 rows/warp) -> h1 tile in smem (fp16).
// Phase B: h1_tile[128,128] @ W2cat[128,32] via fp16 MMA (+bias) -> mA/mC or mB.
// smem: h1s 128*68 u32 + wt 32*68 u32 = 43.5 KB dynamic.
// ---------------------------------------------------------------------------
#define FUSED_SMEM ((128 + 32) * XS_STRIDE * 4)

__global__ void __launch_bounds__(256)
fused_gather_l2(const __nv_bfloat16* __restrict__ m0, const int* __restrict__ offs0,
                const int* __restrict__ csr0,
                const __nv_bfloat16* __restrict__ m1, const int* __restrict__ offs2,
                const int* __restrict__ csr2,
                const __nv_bfloat16* __restrict__ m2, const int* __restrict__ offs1,
                const int* __restrict__ csr1,
                const float* __restrict__ Wc,  const float* __restrict__ bc,
                const float* __restrict__ Wwb, const float* __restrict__ bwb,
                const float* __restrict__ Wwr, const float* __restrict__ bwr,
                float* __restrict__ mA, float* __restrict__ mC, float* __restrict__ mB,
                int nP, int nA, int nbP) {
    extern __shared__ uint32_t sm[];
    uint32_t* h1s = sm;                      // 128 * 68
    uint32_t* wt  = sm + 128 * XS_STRIDE;    // 32 * 68  (W2cat^T, fp16x2 along k)
    __shared__ float bsA[16], bsB[16];

    const int tid = threadIdx.x;
    const int w = tid >> 5, lane = tid & 31;
    const bool paper = (int)blockIdx.x < nbP;
    const int base = (paper ? blockIdx.x : blockIdx.x - nbP) * 128;
    const int M = paper ? nP : nA;

    // --- W2cat -> smem (fp16, transposed): wt[n][kp] = (W[2kp][n], W[2kp+1][n])
    const float* Wp = paper ? Wc : Wwr;
#pragma unroll
    for (int i = 0; i < 4; i++) {
        int u = tid + 256 * i;               // 0..1023
        int n = u >> 6, kp = u & 63;
        float a = __ldg(Wp + (2 * kp) * 16 + n);
        float b = __ldg(Wp + (2 * kp + 1) * 16 + n);
        wt[n * XS_STRIDE + kp] = pack_h2(a, b);
        float a2 = 0.f, b2 = 0.f;
        if (paper) {
            a2 = __ldg(Wwb + (2 * kp) * 16 + n);
            b2 = __ldg(Wwb + (2 * kp + 1) * 16 + n);
        }
        wt[(16 + n) * XS_STRIDE + kp] = pack_h2(a2, b2);
    }
    if (tid < 16) {
        bsA[tid] = paper ? bc[tid] : bwr[tid];
        bsB[tid] = paper ? bwb[tid] : 0.f;
    }

    // --- Phase A: gather 16 rows per warp into smem fp16 tile
    for (int i = 0; i < 16; i++) {
        int r = w * 16 + i;
        int d = base + r;
        float4 acc = make_float4(0.f, 0.f, 0.f, 0.f);
        if (d < M) {
            if (paper) {
                gather_rel_128(m0, csr0, __ldg(offs0 + d), __ldg(offs0 + d + 1), lane, acc);
                acc.x = fmaxf(acc.x, 0.f); acc.y = fmaxf(acc.y, 0.f);
                acc.z = fmaxf(acc.z, 0.f); acc.w = fmaxf(acc.w, 0.f);
                gather_rel_128(m1, csr2, __ldg(offs2 + d), __ldg(offs2 + d + 1), lane, acc);
            } else {
                gather_rel_128(m2, csr1, __ldg(offs1 + d), __ldg(offs1 + d + 1), lane, acc);
            }
            acc.x = fmaxf(acc.x, 0.f); acc.y = fmaxf(acc.y, 0.f);
            acc.z = fmaxf(acc.z, 0.f); acc.w = fmaxf(acc.w, 0.f);
        }
        h1s[r * XS_STRIDE + lane * 2 + 0] = pack_h2(acc.x, acc.y);
        h1s[r * XS_STRIDE + lane * 2 + 1] = pack_h2(acc.z, acc.w);
    }
    __syncthreads();

    // --- Phase B: [128,128] @ [128,32] fp16 MMA
    const int g = lane >> 2, tg = lane & 3;
    const int wrow = (w >> 1) * 32;          // 4 row groups of 32
    const int wcol = (w & 1) * 16;           // 2 col groups of 16
    if (!paper && wcol == 16) return;        // authors: no secondary matrix

    float acc2[2][2][4];
#pragma unroll
    for (int mi = 0; mi < 2; mi++)
#pragma unroll
        for (int nt = 0; nt < 2; nt++)
#pragma unroll
            for (int j = 0; j < 4; j++) acc2[mi][nt][j] = 0.f;

#pragma unroll
    for (int s = 0; s < 8; s++) {
        uint32_t a[2][4];
#pragma unroll
        for (int mi = 0; mi < 2; mi++) {
            int rb = (wrow + mi * 16 + g) * XS_STRIDE + s * 8;
            int rb8 = rb + 8 * XS_STRIDE;
            a[mi][0] = h1s[rb + tg];
            a[mi][1] = h1s[rb8 + tg];
            a[mi][2] = h1s[rb + 4 + tg];
            a[mi][3] = h1s[rb8 + 4 + tg];
        }
#pragma unroll
        for (int nt = 0; nt < 2; nt++) {
            int cb = (wcol + nt * 8 + g) * XS_STRIDE + s * 8 + tg;
            uint32_t b0 = wt[cb];
            uint32_t b1 = wt[cb + 4];
            mma_f16(acc2[0][nt], a[0], b0, b1);
            mma_f16(acc2[1][nt], a[1], b0, b1);
        }
    }

    const bool secondary = (wcol == 16);
    float* out = secondary ? mC : (paper ? mA : mB);
#pragma unroll
    for (int mi = 0; mi < 2; mi++) {
        int r0 = base + wrow + mi * 16 + g;
        int r1 = r0 + 8;
#pragma unroll
        for (int nt = 0; nt < 2; nt++) {
            int c = wcol + nt * 8 + tg * 2;   // 0..31
            int cc = c & 15;
            float bias0 = secondary ? bsB[cc] : bsA[cc];
            float bias1 = secondary ? bsB[cc + 1] : bsA[cc + 1];
            if (r0 < M) {
                float2 v = make_float2(acc2[mi][nt][0] + bias0, acc2[mi][nt][1] + bias1);
                *reinterpret_cast<float2*>(out + (long)r0 * 16 + cc) = v;
            }
            if (r1 < M) {
                float2 v = make_float2(acc2[mi][nt][2] + bias0, acc2[mi][nt][3] + bias1);
                *reinterpret_cast<float2*>(out + (long)r1 * 16 + cc) = v;
            }
        }
    }
}

// ---------------------------------------------------------------------------
// Layer-2 fused gather (F=16 fp32, 2-way unrolled).
// ---------------------------------------------------------------------------
__device__ __forceinline__ void gather_rel_16(const float* __restrict__ m,
                                              const int* __restrict__ csr,
                                              int j0, int j1, int q, float4& acc) {
    int j = j0;
    for (; j + 2 <= j1; j += 2) {
        int sa = __ldg(csr + j), sb = __ldg(csr + j + 1);
        float4 va = __ldg(reinterpret_cast<const float4*>(m + (long)sa * 16) + q);
        float4 vb = __ldg(reinterpret_cast<const float4*>(m + (long)sb * 16) + q);
        acc.x += va.x + vb.x; acc.y += va.y + vb.y;
        acc.z += va.z + vb.z; acc.w += va.w + vb.w;
    }
    if (j < j1) {
        int sa = __ldg(csr + j);
        float4 va = __ldg(reinterpret_cast<const float4*>(m + (long)sa * 16) + q);
        acc.x += va.x; acc.y += va.y; acc.z += va.z; acc.w += va.w;
    }
}

__global__ void gather_l2(const float* __restrict__ mA, const int* __restrict__ offs0,
                          const int* __restrict__ csr0,
                          const float* __restrict__ mB, const int* __restrict__ offs2,
                          const int* __restrict__ csr2,
                          const float* __restrict__ mC, const int* __restrict__ offs1,
                          const int* __restrict__ csr1,
                          float* __restrict__ out_paper, float* __restrict__ out_author,
                          int nP, int nA) {
    long idx = (long)blockIdx.x * blockDim.x + threadIdx.x;
    if (idx >= (long)(nP + nA) * 4) return;
    int dr = (int)(idx >> 2), q = (int)(idx & 3);
    float4 acc = make_float4(0.f, 0.f, 0.f, 0.f);
    float* outp;

    if (dr < nP) {
        int d = dr;
        gather_rel_16(mA, csr0, __ldg(offs0 + d), __ldg(offs0 + d + 1), q, acc);
        acc.x = fmaxf(acc.x, 0.f); acc.y = fmaxf(acc.y, 0.f);
        acc.z = fmaxf(acc.z, 0.f); acc.w = fmaxf(acc.w, 0.f);
        gather_rel_16(mB, csr2, __ldg(offs2 + d), __ldg(offs2 + d + 1), q, acc);
        outp = out_paper + (long)d * 16;
    } else {
        int d = dr - nP;
        gather_rel_16(mC, csr1, __ldg(offs1 + d), __ldg(offs1 + d + 1), q, acc);
        outp = out_author + (long)d * 16;
    }
    acc.x = fmaxf(acc.x, 0.f); acc.y = fmaxf(acc.y, 0.f);
    acc.z = fmaxf(acc.z, 0.f); acc.w = fmaxf(acc.w, 0.f);
    reinterpret_cast<float4*>(outp)[q] = acc;
}

static inline int cdiv(long a, long b) { return (int)((a + b - 1) / b); }

// ---------------------------------------------------------------------------
extern "C" void kernel_launch(void* const* d_in, const int* in_sizes, int n_in,
                              void* d_out, int out_size) {
    const float* embed_paper  = (const float*)d_in[0];
    const float* embed_author = (const float*)d_in[1];
    const float* W1_cites     = (const float*)d_in[2];
    const float* b1_cites     = (const float*)d_in[3];
    const float* W1_writtenby = (const float*)d_in[4];
    const float* b1_writtenby = (const float*)d_in[5];
    const float* W1_writes    = (const float*)d_in[6];
    const float* b1_writes    = (const float*)d_in[7];
    const float* W2_cites     = (const float*)d_in[8];
    const float* b2_cites     = (const float*)d_in[9];
    const float* W2_writtenby = (const float*)d_in[10];
    const float* b2_writtenby = (const float*)d_in[11];
    const float* W2_writes    = (const float*)d_in[12];
    const float* b2_writes    = (const float*)d_in[13];
    const int* cites_src      = (const int*)d_in[14];
    const int* cites_dst      = (const int*)d_in[15];
    const int* writtenby_src  = (const int*)d_in[16];
    const int* writtenby_dst  = (const int*)d_in[17];
    const int* writes_src     = (const int*)d_in[18];
    const int* writes_dst     = (const int*)d_in[19];

    const int n_paper  = in_sizes[0] / 128;
    const int n_author = in_sizes[1] / 128;
    const int E0 = in_sizes[14];
    const int E1 = in_sizes[16];
    const int E2 = in_sizes[18];

    __nv_bfloat16 *m0, *m1, *m2;
    float *mA, *mB, *mC;
    cudaGetSymbolAddress((void**)&m0,  g_m0);
    cudaGetSymbolAddress((void**)&m1,  g_m1);
    cudaGetSymbolAddress((void**)&m2,  g_m2);
    cudaGetSymbolAddress((void**)&mA,  g_mA);
    cudaGetSymbolAddress((void**)&mB,  g_mB);
    cudaGetSymbolAddress((void**)&mC,  g_mC);
    int *offs0, *offs1, *offs2, *csr0, *csr1, *csr2, *deg, *cur, *bsum;
    cudaGetSymbolAddress((void**)&offs0, g_offs0);
    cudaGetSymbolAddress((void**)&offs1, g_offs1);
    cudaGetSymbolAddress((void**)&offs2, g_offs2);
    cudaGetSymbolAddress((void**)&csr0, g_csr0);
    cudaGetSymbolAddress((void**)&csr1, g_csr1);
    cudaGetSymbolAddress((void**)&csr2, g_csr2);
    cudaGetSymbolAddress((void**)&deg,  g_deg);
    cudaGetSymbolAddress((void**)&cur,  g_cur);
    cudaGetSymbolAddress((void**)&bsum, g_bsum);

    cudaFuncSetAttribute(gemm128_l1,
                         cudaFuncAttributeMaxDynamicSharedMemorySize, GEMM128_SMEM);
    cudaFuncSetAttribute(fused_gather_l2,
                         cudaFuncAttributeMaxDynamicSharedMemorySize, FUSED_SMEM);

    // Side stream + events for CSR/GEMM overlap (created once; capture-safe).
    static cudaStream_t s_side = nullptr;
    static cudaEvent_t s_evFork = nullptr, s_evJoin = nullptr;
    if (!s_side) {
        cudaStreamCreateWithFlags(&s_side, cudaStreamNonBlocking);
        cudaEventCreateWithFlags(&s_evFork, cudaEventDisableTiming);
        cudaEventCreateWithFlags(&s_evJoin, cudaEventDisableTiming);
    }

    float* out_paper  = (float*)d_out;
    float* out_author = (float*)d_out + (long)n_paper * 16;

    // ---------------- Fork: CSR build on side stream ----------------
    cudaEventRecord(s_evFork, 0);
    cudaStreamWaitEvent(s_side, s_evFork, 0);

    cudaMemsetAsync(deg, 0, (size_t)(2 * NP_PAD + NA_PAD) * sizeof(int), s_side);
    hist3<<<cdiv((long)E0 + E1 + E2, 256), 256, 0, s_side>>>(
        cites_dst, writtenby_dst, writes_dst, deg, E0, E1, E2);
    int nb0 = cdiv(n_paper, 4096), nb1 = cdiv(n_author, 4096), nb2 = cdiv(n_paper, 4096);
    scan_block3<<<nb0 + nb1 + nb2, 256, 0, s_side>>>(deg, offs0, offs1, offs2, bsum,
                                                     n_paper, n_author, n_paper);
    scan_bsums3<<<3, 32, 0, s_side>>>(bsum, nb0, nb1, nb2);
    scan_add3<<<cdiv((long)n_paper + n_author + n_paper, 256), 256, 0, s_side>>>(
        offs0, offs1, offs2, bsum, cur, n_paper, n_author, n_paper, E0, E1, E2);
    fill3<<<cdiv((long)E0 + E1 + E2, 256), 256, 0, s_side>>>(
        cites_src, cites_dst, writtenby_src, writtenby_dst, writes_src, writes_dst,
        cur, csr0, csr1, csr2, E0, E1, E2);
    cudaEventRecord(s_evJoin, s_side);

    // ---------------- Main stream: Layer-1 GEMM ----------------
    const int nbP128 = cdiv(n_paper, 128), nbA128 = cdiv(n_author, 128);
    gemm128_l1<<<nbP128 + nbA128, 256, GEMM128_SMEM>>>(
        embed_paper, embed_author,
        W1_cites, b1_cites, m0,
        W1_writtenby, b1_writtenby, m2,
        W1_writes, b1_writes, m1,
        n_paper, n_author, nbP128);

    // ---------------- Join, then fused gather+L2, final gather ----------------
    cudaStreamWaitEvent(0, s_evJoin, 0);

    fused_gather_l2<<<nbP128 + nbA128, 256, FUSED_SMEM>>>(
        m0, offs0, csr0, m1, offs2, csr2, m2, offs1, csr1,
        W2_cites, b2_cites, W2_writtenby, b2_writtenby, W2_writes, b2_writes,
        mA, mC, mB, n_paper, n_author, nbP128);

    gather_l2<<<cdiv(((long)n_paper + n_author) * 4, 256), 256>>>(
        mA, offs0, csr0, mB, offs2, csr2, mC, offs1, csr1,
        out_paper, out_author, n_paper, n_author);
}

// round 9
// speedup vs baseline: 4.0902x; 1.0007x over previous
#include <cuda_runtime.h>
#include <cuda_bf16.h>
#include <cuda_fp16.h>
#include <cstdint>

// ---------------------------------------------------------------------------
// EntityClassify: 2-layer hetero R-GCN.
// R9: 4-row interleaved gathers (MLP=4), fp16 layer-2 messages.
//     Fused gather+L2 transform, CSR build overlapped with L1 GEMM.
// ---------------------------------------------------------------------------

#define N_PAPER_MAX 200000
#define N_AUTHOR_MAX 100000
#define E_MAX 500000
#define NP_PAD 200064
#define NA_PAD 100064

// layer-1 messages (bf16)
__device__ __nv_bfloat16 g_m0[N_PAPER_MAX * 128];   // embed_paper  @ W1_cites
__device__ __nv_bfloat16 g_m2[N_PAPER_MAX * 128];   // embed_paper  @ W1_writtenby
__device__ __nv_bfloat16 g_m1[N_AUTHOR_MAX * 128];  // embed_author @ W1_writes
// layer-2 messages (fp16)
__device__ __half g_mA[N_PAPER_MAX * 16];   // h1p @ W2_cites
__device__ __half g_mC[N_PAPER_MAX * 16];   // h1p @ W2_writtenby
__device__ __half g_mB[N_AUTHOR_MAX * 16];  // h1a @ W2_writes

// CSR scratch (0=cites->paper, 1=writtenby->author, 2=writes->paper)
__device__ int g_offs0[NP_PAD + 1];
__device__ int g_offs1[NA_PAD + 1];
__device__ int g_offs2[NP_PAD + 1];
__device__ int g_csr0[E_MAX];
__device__ int g_csr1[E_MAX];
__device__ int g_csr2[E_MAX];
__device__ int g_deg[2 * NP_PAD + NA_PAD];
__device__ int g_cur[2 * NP_PAD + NA_PAD];
__device__ int g_bsum[3 * 64];

__device__ __forceinline__ uint32_t pack_bf2(float a, float b) {
    __nv_bfloat162 p = __floats2bfloat162_rn(a, b);
    return *reinterpret_cast<uint32_t*>(&p);
}
__device__ __forceinline__ uint32_t pack_h2(float a, float b) {
    __half2 p = __floats2half2_rn(a, b);
    return *reinterpret_cast<uint32_t*>(&p);
}

__device__ __forceinline__ void mma_bf16(float* c, const uint32_t* a,
                                         uint32_t b0, uint32_t b1) {
    asm volatile(
        "mma.sync.aligned.m16n8k16.row.col.f32.bf16.bf16.f32 "
        "{%0,%1,%2,%3}, {%4,%5,%6,%7}, {%8,%9}, {%0,%1,%2,%3};"
        : "+f"(c[0]), "+f"(c[1]), "+f"(c[2]), "+f"(c[3])
        : "r"(a[0]), "r"(a[1]), "r"(a[2]), "r"(a[3]), "r"(b0), "r"(b1));
}

__device__ __forceinline__ void mma_f16(float* c, const uint32_t* a,
                                        uint32_t b0, uint32_t b1) {
    asm volatile(
        "mma.sync.aligned.m16n8k16.row.col.f32.f16.f16.f32 "
        "{%0,%1,%2,%3}, {%4,%5,%6,%7}, {%8,%9}, {%0,%1,%2,%3};"
        : "+f"(c[0]), "+f"(c[1]), "+f"(c[2]), "+f"(c[3])
        : "r"(a[0]), "r"(a[1]), "r"(a[2]), "r"(a[3]), "r"(b0), "r"(b1));
}

__device__ __forceinline__ void bf2_acc(float4& acc, uint2 v) {
    float2 f0 = __bfloat1622float2(*reinterpret_cast<__nv_bfloat162*>(&v.x));
    float2 f1 = __bfloat1622float2(*reinterpret_cast<__nv_bfloat162*>(&v.y));
    acc.x += f0.x; acc.y += f0.y; acc.z += f1.x; acc.w += f1.y;
}
__device__ __forceinline__ void h2_acc(float4& acc, uint2 v) {
    float2 f0 = __half22float2(*reinterpret_cast<__half2*>(&v.x));
    float2 f1 = __half22float2(*reinterpret_cast<__half2*>(&v.y));
    acc.x += f0.x; acc.y += f0.y; acc.z += f1.x; acc.w += f1.y;
}
__device__ __forceinline__ void relu4(float4& a) {
    a.x = fmaxf(a.x, 0.f); a.y = fmaxf(a.y, 0.f);
    a.z = fmaxf(a.z, 0.f); a.w = fmaxf(a.w, 0.f);
}

// ---------------------------------------------------------------------------
// Batched CSR build
// ---------------------------------------------------------------------------
__global__ void hist3(const int* __restrict__ d0, const int* __restrict__ d1,
                      const int* __restrict__ d2, int* __restrict__ deg,
                      int E0, int E1, int E2) {
    int i = blockIdx.x * blockDim.x + threadIdx.x;
    if (i < E0) {
        atomicAdd(&deg[d0[i]], 1);
    } else if (i < E0 + E1) {
        atomicAdd(&deg[NP_PAD + d1[i - E0]], 1);
    } else if (i < E0 + E1 + E2) {
        atomicAdd(&deg[NP_PAD + NA_PAD + d2[i - E0 - E1]], 1);
    }
}

__global__ void scan_block3(const int* __restrict__ deg,
                            int* __restrict__ offs0, int* __restrict__ offs1,
                            int* __restrict__ offs2, int* __restrict__ bsum,
                            int n0, int n1, int n2) {
    const int nb0 = (n0 + 4095) >> 12, nb1 = (n1 + 4095) >> 12;
    int b = blockIdx.x;
    int rel, lb, n;
    const int* dg;
    int* offs;
    if (b < nb0)            { rel = 0; lb = b;             dg = deg;                   offs = offs0; n = n0; }
    else if (b < nb0 + nb1) { rel = 1; lb = b - nb0;       dg = deg + NP_PAD;          offs = offs1; n = n1; }
    else                    { rel = 2; lb = b - nb0 - nb1; dg = deg + NP_PAD + NA_PAD; offs = offs2; n = n2; }

    const int i0 = lb * 4096 + threadIdx.x * 16;
    int vals[16];
    int s = 0;
#pragma unroll
    for (int j = 0; j < 16; j++) {
        int idx = i0 + j;
        int v = (idx < n) ? dg[idx] : 0;
        vals[j] = s;
        s += v;
    }
    int lane = threadIdx.x & 31, wid = threadIdx.x >> 5;
    int x = s;
#pragma unroll
    for (int o = 1; o < 32; o <<= 1) {
        int y = __shfl_up_sync(0xffffffffu, x, o);
        if (lane >= o) x += y;
    }
    __shared__ int wsum[8];
    if (lane == 31) wsum[wid] = x;
    __syncthreads();
    if (wid == 0 && lane < 8) {
        int y = wsum[lane];
#pragma unroll
        for (int o = 1; o < 8; o <<= 1) {
            int z = __shfl_up_sync(0xffu, y, o);
            if (lane >= o) y += z;
        }
        wsum[lane] = y;
    }
    __syncthreads();
    int thread_excl = (x - s) + (wid > 0 ? wsum[wid - 1] : 0);
#pragma unroll
    for (int j = 0; j < 16; j++) {
        int idx = i0 + j;
        if (idx < n) offs[idx] = thread_excl + vals[j];
    }
    if (threadIdx.x == 255) bsum[rel * 64 + lb] = thread_excl + s;
}

__global__ void scan_bsums3(int* __restrict__ bsum, int nb0, int nb1, int nb2) {
    int r = blockIdx.x;
    int nb = (r == 0) ? nb0 : (r == 1) ? nb1 : nb2;
    if (threadIdx.x == 0) {
        int* p = bsum + r * 64;
        int s = 0;
        for (int i = 0; i < nb; i++) { int x = p[i]; p[i] = s; s += x; }
    }
}

__global__ void scan_add3(int* __restrict__ offs0, int* __restrict__ offs1,
                          int* __restrict__ offs2, const int* __restrict__ bsum,
                          int* __restrict__ cur,
                          int n0, int n1, int n2, int E0, int E1, int E2) {
    int i = blockIdx.x * blockDim.x + threadIdx.x;
    if (i < n0) {
        int v = offs0[i] + bsum[i >> 12];
        offs0[i] = v; cur[i] = v;
        if (i == 0) offs0[n0] = E0;
    } else if (i < n0 + n1) {
        int j = i - n0;
        int v = offs1[j] + bsum[64 + (j >> 12)];
        offs1[j] = v; cur[NP_PAD + j] = v;
        if (j == 0) offs1[n1] = E1;
    } else if (i < n0 + n1 + n2) {
        int j = i - n0 - n1;
        int v = offs2[j] + bsum[128 + (j >> 12)];
        offs2[j] = v; cur[NP_PAD + NA_PAD + j] = v;
        if (j == 0) offs2[n2] = E2;
    }
}

__global__ void fill3(const int* __restrict__ s0, const int* __restrict__ d0,
                      const int* __restrict__ s1, const int* __restrict__ d1,
                      const int* __restrict__ s2, const int* __restrict__ d2,
                      int* __restrict__ cur,
                      int* __restrict__ c0, int* __restrict__ c1, int* __restrict__ c2,
                      int E0, int E1, int E2) {
    int i = blockIdx.x * blockDim.x + threadIdx.x;
    if (i < E0) {
        int p = atomicAdd(&cur[d0[i]], 1);
        c0[p] = s0[i];
    } else if (i < E0 + E1) {
        int j = i - E0;
        int p = atomicAdd(&cur[NP_PAD + d1[j]], 1);
        c1[p] = s1[j];
    } else if (i < E0 + E1 + E2) {
        int j = i - E0 - E1;
        int p = atomicAdd(&cur[NP_PAD + NA_PAD + d2[j]], 1);
        c2[p] = s2[j];
    }
}

// ---------------------------------------------------------------------------
// Layer-1 GEMM, multi-output (paper: 2 phases, author: 1), bf16 MMA.
// ---------------------------------------------------------------------------
#define XS_STRIDE 68
#define GEMM128_SMEM (2 * 128 * XS_STRIDE * 4)

__global__ void __launch_bounds__(256)
gemm128_l1(const float* __restrict__ Xp, const float* __restrict__ Xa,
           const float* __restrict__ Wc,  const float* __restrict__ bc,  __nv_bfloat16* __restrict__ m0,
           const float* __restrict__ Wwb, const float* __restrict__ bwb, __nv_bfloat16* __restrict__ m2,
           const float* __restrict__ Wwr, const float* __restrict__ bwr, __nv_bfloat16* __restrict__ m1,
           int nP, int nA, int nbP) {
    extern __shared__ uint32_t sm[];
    uint32_t* xs = sm;
    uint32_t* wt = sm + 128 * XS_STRIDE;
    __shared__ float bs[128];

    const int tid = threadIdx.x;
    const int wid = tid >> 5, lane = tid & 31;
    const int g = lane >> 2, tg = lane & 3;
    const int wrow = (wid >> 1) * 32;
    const int wcol = (wid & 1) * 64;

    const bool paper = (int)blockIdx.x < nbP;
    const float* X = paper ? Xp : Xa;
    const int M = paper ? nP : nA;
    const int row_base = (paper ? blockIdx.x : blockIdx.x - nbP) * 128;
    const int nphase = paper ? 2 : 1;
    const float* Wl[2]  = { paper ? Wc : Wwr,  Wwb };
    const float* bl[2]  = { paper ? bc : bwr,  bwb };
    __nv_bfloat16* Yl[2] = { paper ? m0 : m1,  m2 };

#pragma unroll
    for (int i = 0; i < 16; i++) {
        int idx = tid + 256 * i;
        int r = idx >> 5, c4 = idx & 31;
        int gr = row_base + r;
        float4 v = make_float4(0.f, 0.f, 0.f, 0.f);
        if (gr < M) v = __ldg(reinterpret_cast<const float4*>(X + (long)gr * 128) + c4);
        xs[r * XS_STRIDE + c4 * 2 + 0] = pack_bf2(v.x, v.y);
        xs[r * XS_STRIDE + c4 * 2 + 1] = pack_bf2(v.z, v.w);
    }

    for (int ph = 0; ph < nphase; ph++) {
        const float* W = Wl[ph];
#pragma unroll
        for (int i = 0; i < 8; i++) {
            int u = tid + 256 * i;
            int n4 = u >> 6;
            int kp = u & 63;
            float4 wa = __ldg(reinterpret_cast<const float4*>(W + (long)(2 * kp) * 128) + n4);
            float4 wb = __ldg(reinterpret_cast<const float4*>(W + (long)(2 * kp + 1) * 128) + n4);
            wt[(n4 * 4 + 0) * XS_STRIDE + kp] = pack_bf2(wa.x, wb.x);
            wt[(n4 * 4 + 1) * XS_STRIDE + kp] = pack_bf2(wa.y, wb.y);
            wt[(n4 * 4 + 2) * XS_STRIDE + kp] = pack_bf2(wa.z, wb.z);
            wt[(n4 * 4 + 3) * XS_STRIDE + kp] = pack_bf2(wa.w, wb.w);
        }
        if (tid < 128) bs[tid] = bl[ph][tid];
        __syncthreads();

        float acc[2][8][4];
#pragma unroll
        for (int mi = 0; mi < 2; mi++)
#pragma unroll
            for (int nt = 0; nt < 8; nt++)
#pragma unroll
                for (int j = 0; j < 4; j++) acc[mi][nt][j] = 0.f;

#pragma unroll
        for (int s = 0; s < 8; s++) {
            uint32_t a[2][4];
#pragma unroll
            for (int mi = 0; mi < 2; mi++) {
                int rb = (wrow + mi * 16 + g) * XS_STRIDE + s * 8;
                int rb8 = rb + 8 * XS_STRIDE;
                a[mi][0] = xs[rb + tg];
                a[mi][1] = xs[rb8 + tg];
                a[mi][2] = xs[rb + 4 + tg];
                a[mi][3] = xs[rb8 + 4 + tg];
            }
#pragma unroll
            for (int nt = 0; nt < 8; nt++) {
                int cb = (wcol + nt * 8 + g) * XS_STRIDE + s * 8 + tg;
                uint32_t b0 = wt[cb];
                uint32_t b1 = wt[cb + 4];
                mma_bf16(acc[0][nt], a[0], b0, b1);
                mma_bf16(acc[1][nt], a[1], b0, b1);
            }
        }

        uint32_t* Yu = reinterpret_cast<uint32_t*>(Yl[ph]);
#pragma unroll
        for (int mi = 0; mi < 2; mi++) {
            int r0 = row_base + wrow + mi * 16 + g;
            int r1 = r0 + 8;
#pragma unroll
            for (int nt = 0; nt < 8; nt++) {
                int c = wcol + nt * 8 + tg * 2;
                if (r0 < M)
                    Yu[(long)r0 * 64 + (c >> 1)] = pack_bf2(acc[mi][nt][0] + bs[c], acc[mi][nt][1] + bs[c + 1]);
                if (r1 < M)
                    Yu[(long)r1 * 64 + (c >> 1)] = pack_bf2(acc[mi][nt][2] + bs[c], acc[mi][nt][3] + bs[c + 1]);
            }
        }
        __syncthreads();
    }
}

// ---------------------------------------------------------------------------
// 4-row interleaved gather: 4 independent index->message chains (MLP=4).
// j/je are per-row bounds, uniform across the warp.
// ---------------------------------------------------------------------------
__device__ __forceinline__ void gather4_128(const __nv_bfloat16* __restrict__ m,
                                            const int* __restrict__ csr,
                                            int* j, const int* je, int lane, float4* acc) {
    while (true) {
        bool a0 = j[0] < je[0], a1 = j[1] < je[1];
        bool a2 = j[2] < je[2], a3 = j[3] < je[3];
        if (!(a0 | a1 | a2 | a3)) break;
        uint2 v0, v1, v2, v3;
        if (a0) { int s = __ldg(csr + j[0]); v0 = __ldg(reinterpret_cast<const uint2*>(m + (long)s * 128) + lane); }
        if (a1) { int s = __ldg(csr + j[1]); v1 = __ldg(reinterpret_cast<const uint2*>(m + (long)s * 128) + lane); }
        if (a2) { int s = __ldg(csr + j[2]); v2 = __ldg(reinterpret_cast<const uint2*>(m + (long)s * 128) + lane); }
        if (a3) { int s = __ldg(csr + j[3]); v3 = __ldg(reinterpret_cast<const uint2*>(m + (long)s * 128) + lane); }
        if (a0) { bf2_acc(acc[0], v0); j[0]++; }
        if (a1) { bf2_acc(acc[1], v1); j[1]++; }
        if (a2) { bf2_acc(acc[2], v2); j[2]++; }
        if (a3) { bf2_acc(acc[3], v3); j[3]++; }
    }
}

__device__ __forceinline__ void load_bounds4(const int* __restrict__ offs, int d0, int M,
                                             int* j, int* je) {
#pragma unroll
    for (int r = 0; r < 4; r++) {
        int d = d0 + r;
        if (d < M) { j[r] = __ldg(offs + d); je[r] = __ldg(offs + d + 1); }
        else { j[r] = 0; je[r] = 0; }
    }
}

// ---------------------------------------------------------------------------
// Fused gather_l1 + layer-2 transform. Block = 128 dst rows.
// Phase A: 4-row interleaved gather -> h1 tile in smem (fp16).
// Phase B: h1_tile[128,128] @ W2cat[128,32] via fp16 MMA (+bias) -> fp16 msgs.
// ---------------------------------------------------------------------------
#define FUSED_SMEM ((128 + 32) * XS_STRIDE * 4)

__global__ void __launch_bounds__(256)
fused_gather_l2(const __nv_bfloat16* __restrict__ m0, const int* __restrict__ offs0,
                const int* __restrict__ csr0,
                const __nv_bfloat16* __restrict__ m1, const int* __restrict__ offs2,
                const int* __restrict__ csr2,
                const __nv_bfloat16* __restrict__ m2, const int* __restrict__ offs1,
                const int* __restrict__ csr1,
                const float* __restrict__ Wc,  const float* __restrict__ bc,
                const float* __restrict__ Wwb, const float* __restrict__ bwb,
                const float* __restrict__ Wwr, const float* __restrict__ bwr,
                __half* __restrict__ mA, __half* __restrict__ mC, __half* __restrict__ mB,
                int nP, int nA, int nbP) {
    extern __shared__ uint32_t sm[];
    uint32_t* h1s = sm;                      // 128 * 68
    uint32_t* wt  = sm + 128 * XS_STRIDE;    // 32 * 68  (W2cat^T, fp16x2 along k)
    __shared__ float bsA[16], bsB[16];

    const int tid = threadIdx.x;
    const int w = tid >> 5, lane = tid & 31;
    const bool paper = (int)blockIdx.x < nbP;
    const int base = (paper ? blockIdx.x : blockIdx.x - nbP) * 128;
    const int M = paper ? nP : nA;

    // --- W2cat -> smem (fp16, transposed)
    const float* Wp = paper ? Wc : Wwr;
#pragma unroll
    for (int i = 0; i < 4; i++) {
        int u = tid + 256 * i;               // 0..1023
        int n = u >> 6, kp = u & 63;
        float a = __ldg(Wp + (2 * kp) * 16 + n);
        float b = __ldg(Wp + (2 * kp + 1) * 16 + n);
        wt[n * XS_STRIDE + kp] = pack_h2(a, b);
        float a2 = 0.f, b2 = 0.f;
        if (paper) {
            a2 = __ldg(Wwb + (2 * kp) * 16 + n);
            b2 = __ldg(Wwb + (2 * kp + 1) * 16 + n);
        }
        wt[(16 + n) * XS_STRIDE + kp] = pack_h2(a2, b2);
    }
    if (tid < 16) {
        bsA[tid] = paper ? bc[tid] : bwr[tid];
        bsB[tid] = paper ? bwb[tid] : 0.f;
    }

    // --- Phase A: 4 groups of 4 interleaved rows per warp
#pragma unroll 1
    for (int grp = 0; grp < 4; grp++) {
        int rbase = w * 16 + grp * 4;
        int d0 = base + rbase;
        float4 acc[4];
#pragma unroll
        for (int r = 0; r < 4; r++) acc[r] = make_float4(0.f, 0.f, 0.f, 0.f);
        int j[4], je[4];

        if (paper) {
            load_bounds4(offs0, d0, M, j, je);
            gather4_128(m0, csr0, j, je, lane, acc);
#pragma unroll
            for (int r = 0; r < 4; r++) relu4(acc[r]);
            load_bounds4(offs2, d0, M, j, je);
            gather4_128(m1, csr2, j, je, lane, acc);
        } else {
            load_bounds4(offs1, d0, M, j, je);
            gather4_128(m2, csr1, j, je, lane, acc);
        }
#pragma unroll
        for (int r = 0; r < 4; r++) {
            relu4(acc[r]);
            h1s[(rbase + r) * XS_STRIDE + lane * 2 + 0] = pack_h2(acc[r].x, acc[r].y);
            h1s[(rbase + r) * XS_STRIDE + lane * 2 + 1] = pack_h2(acc[r].z, acc[r].w);
        }
    }
    __syncthreads();

    // --- Phase B: [128,128] @ [128,32] fp16 MMA
    const int g = lane >> 2, tg = lane & 3;
    const int wrow = (w >> 1) * 32;
    const int wcol = (w & 1) * 16;
    if (!paper && wcol == 16) return;

    float acc2[2][2][4];
#pragma unroll
    for (int mi = 0; mi < 2; mi++)
#pragma unroll
        for (int nt = 0; nt < 2; nt++)
#pragma unroll
            for (int j2 = 0; j2 < 4; j2++) acc2[mi][nt][j2] = 0.f;

#pragma unroll
    for (int s = 0; s < 8; s++) {
        uint32_t a[2][4];
#pragma unroll
        for (int mi = 0; mi < 2; mi++) {
            int rb = (wrow + mi * 16 + g) * XS_STRIDE + s * 8;
            int rb8 = rb + 8 * XS_STRIDE;
            a[mi][0] = h1s[rb + tg];
            a[mi][1] = h1s[rb8 + tg];
            a[mi][2] = h1s[rb + 4 + tg];
            a[mi][3] = h1s[rb8 + 4 + tg];
        }
#pragma unroll
        for (int nt = 0; nt < 2; nt++) {
            int cb = (wcol + nt * 8 + g) * XS_STRIDE + s * 8 + tg;
            uint32_t b0 = wt[cb];
            uint32_t b1 = wt[cb + 4];
            mma_f16(acc2[0][nt], a[0], b0, b1);
            mma_f16(acc2[1][nt], a[1], b0, b1);
        }
    }

    const bool secondary = (wcol == 16);
    __half* out = secondary ? mC : (paper ? mA : mB);
#pragma unroll
    for (int mi = 0; mi < 2; mi++) {
        int r0 = base + wrow + mi * 16 + g;
        int r1 = r0 + 8;
#pragma unroll
        for (int nt = 0; nt < 2; nt++) {
            int c = wcol + nt * 8 + tg * 2;
            int cc = c & 15;
            float bias0 = secondary ? bsB[cc] : bsA[cc];
            float bias1 = secondary ? bsB[cc + 1] : bsA[cc + 1];
            if (r0 < M)
                *reinterpret_cast<uint32_t*>(out + (long)r0 * 16 + cc) =
                    pack_h2(acc2[mi][nt][0] + bias0, acc2[mi][nt][1] + bias1);
            if (r1 < M)
                *reinterpret_cast<uint32_t*>(out + (long)r1 * 16 + cc) =
                    pack_h2(acc2[mi][nt][2] + bias0, acc2[mi][nt][3] + bias1);
        }
    }
}

// ---------------------------------------------------------------------------
// Layer-2 fused gather (fp16 messages, 2-way unrolled). 4 threads per dst row.
// ---------------------------------------------------------------------------
__device__ __forceinline__ void gather_rel_16h(const __half* __restrict__ m,
                                               const int* __restrict__ csr,
                                               int j0, int j1, int q, float4& acc) {
    int j = j0;
    for (; j + 2 <= j1; j += 2) {
        int sa = __ldg(csr + j), sb = __ldg(csr + j + 1);
        uint2 va = __ldg(reinterpret_cast<const uint2*>(m + (long)sa * 16) + q);
        uint2 vb = __ldg(reinterpret_cast<const uint2*>(m + (long)sb * 16) + q);
        h2_acc(acc, va);
        h2_acc(acc, vb);
    }
    if (j < j1) {
        int sa = __ldg(csr + j);
        uint2 va = __ldg(reinterpret_cast<const uint2*>(m + (long)sa * 16) + q);
        h2_acc(acc, va);
    }
}

__global__ void gather_l2(const __half* __restrict__ mA, const int* __restrict__ offs0,
                          const int* __restrict__ csr0,
                          const __half* __restrict__ mB, const int* __restrict__ offs2,
                          const int* __restrict__ csr2,
                          const __half* __restrict__ mC, const int* __restrict__ offs1,
                          const int* __restrict__ csr1,
                          float* __restrict__ out_paper, float* __restrict__ out_author,
                          int nP, int nA) {
    long idx = (long)blockIdx.x * blockDim.x + threadIdx.x;
    if (idx >= (long)(nP + nA) * 4) return;
    int dr = (int)(idx >> 2), q = (int)(idx & 3);
    float4 acc = make_float4(0.f, 0.f, 0.f, 0.f);
    float* outp;

    if (dr < nP) {
        int d = dr;
        gather_rel_16h(mA, csr0, __ldg(offs0 + d), __ldg(offs0 + d + 1), q, acc);
        relu4(acc);
        gather_rel_16h(mB, csr2, __ldg(offs2 + d), __ldg(offs2 + d + 1), q, acc);
        outp = out_paper + (long)d * 16;
    } else {
        int d = dr - nP;
        gather_rel_16h(mC, csr1, __ldg(offs1 + d), __ldg(offs1 + d + 1), q, acc);
        outp = out_author + (long)d * 16;
    }
    relu4(acc);
    reinterpret_cast<float4*>(outp)[q] = acc;
}

static inline int cdiv(long a, long b) { return (int)((a + b - 1) / b); }

// ---------------------------------------------------------------------------
extern "C" void kernel_launch(void* const* d_in, const int* in_sizes, int n_in,
                              void* d_out, int out_size) {
    const float* embed_paper  = (const float*)d_in[0];
    const float* embed_author = (const float*)d_in[1];
    const float* W1_cites     = (const float*)d_in[2];
    const float* b1_cites     = (const float*)d_in[3];
    const float* W1_writtenby = (const float*)d_in[4];
    const float* b1_writtenby = (const float*)d_in[5];
    const float* W1_writes    = (const float*)d_in[6];
    const float* b1_writes    = (const float*)d_in[7];
    const float* W2_cites     = (const float*)d_in[8];
    const float* b2_cites     = (const float*)d_in[9];
    const float* W2_writtenby = (const float*)d_in[10];
    const float* b2_writtenby = (const float*)d_in[11];
    const float* W2_writes    = (const float*)d_in[12];
    const float* b2_writes    = (const float*)d_in[13];
    const int* cites_src      = (const int*)d_in[14];
    const int* cites_dst      = (const int*)d_in[15];
    const int* writtenby_src  = (const int*)d_in[16];
    const int* writtenby_dst  = (const int*)d_in[17];
    const int* writes_src     = (const int*)d_in[18];
    const int* writes_dst     = (const int*)d_in[19];

    const int n_paper  = in_sizes[0] / 128;
    const int n_author = in_sizes[1] / 128;
    const int E0 = in_sizes[14];
    const int E1 = in_sizes[16];
    const int E2 = in_sizes[18];

    __nv_bfloat16 *m0, *m1, *m2;
    __half *mA, *mB, *mC;
    cudaGetSymbolAddress((void**)&m0,  g_m0);
    cudaGetSymbolAddress((void**)&m1,  g_m1);
    cudaGetSymbolAddress((void**)&m2,  g_m2);
    cudaGetSymbolAddress((void**)&mA,  g_mA);
    cudaGetSymbolAddress((void**)&mB,  g_mB);
    cudaGetSymbolAddress((void**)&mC,  g_mC);
    int *offs0, *offs1, *offs2, *csr0, *csr1, *csr2, *deg, *cur, *bsum;
    cudaGetSymbolAddress((void**)&offs0, g_offs0);
    cudaGetSymbolAddress((void**)&offs1, g_offs1);
    cudaGetSymbolAddress((void**)&offs2, g_offs2);
    cudaGetSymbolAddress((void**)&csr0, g_csr0);
    cudaGetSymbolAddress((void**)&csr1, g_csr1);
    cudaGetSymbolAddress((void**)&csr2, g_csr2);
    cudaGetSymbolAddress((void**)&deg,  g_deg);
    cudaGetSymbolAddress((void**)&cur,  g_cur);
    cudaGetSymbolAddress((void**)&bsum, g_bsum);

    cudaFuncSetAttribute(gemm128_l1,
                         cudaFuncAttributeMaxDynamicSharedMemorySize, GEMM128_SMEM);
    cudaFuncSetAttribute(fused_gather_l2,
                         cudaFuncAttributeMaxDynamicSharedMemorySize, FUSED_SMEM);

    // Side stream + events for CSR/GEMM overlap (created once; capture-safe).
    static cudaStream_t s_side = nullptr;
    static cudaEvent_t s_evFork = nullptr, s_evJoin = nullptr;
    if (!s_side) {
        cudaStreamCreateWithFlags(&s_side, cudaStreamNonBlocking);
        cudaEventCreateWithFlags(&s_evFork, cudaEventDisableTiming);
        cudaEventCreateWithFlags(&s_evJoin, cudaEventDisableTiming);
    }

    float* out_paper  = (float*)d_out;
    float* out_author = (float*)d_out + (long)n_paper * 16;

    // ---------------- Fork: CSR build on side stream ----------------
    cudaEventRecord(s_evFork, 0);
    cudaStreamWaitEvent(s_side, s_evFork, 0);

    cudaMemsetAsync(deg, 0, (size_t)(2 * NP_PAD + NA_PAD) * sizeof(int), s_side);
    hist3<<<cdiv((long)E0 + E1 + E2, 256), 256, 0, s_side>>>(
        cites_dst, writtenby_dst, writes_dst, deg, E0, E1, E2);
    int nb0 = cdiv(n_paper, 4096), nb1 = cdiv(n_author, 4096), nb2 = cdiv(n_paper, 4096);
    scan_block3<<<nb0 + nb1 + nb2, 256, 0, s_side>>>(deg, offs0, offs1, offs2, bsum,
                                                     n_paper, n_author, n_paper);
    scan_bsums3<<<3, 32, 0, s_side>>>(bsum, nb0, nb1, nb2);
    scan_add3<<<cdiv((long)n_paper + n_author + n_paper, 256), 256, 0, s_side>>>(
        offs0, offs1, offs2, bsum, cur, n_paper, n_author, n_paper, E0, E1, E2);
    fill3<<<cdiv((long)E0 + E1 + E2, 256), 256, 0, s_side>>>(
        cites_src, cites_dst, writtenby_src, writtenby_dst, writes_src, writes_dst,
        cur, csr0, csr1, csr2, E0, E1, E2);
    cudaEventRecord(s_evJoin, s_side);

    // ---------------- Main stream: Layer-1 GEMM ----------------
    const int nbP128 = cdiv(n_paper, 128), nbA128 = cdiv(n_author, 128);
    gemm128_l1<<<nbP128 + nbA128, 256, GEMM128_SMEM>>>(
        embed_paper, embed_author,
        W1_cites, b1_cites, m0,
        W1_writtenby, b1_writtenby, m2,
        W1_writes, b1_writes, m1,
        n_paper, n_author, nbP128);

    // ---------------- Join, then fused gather+L2, final gather ----------------
    cudaStreamWaitEvent(0, s_evJoin, 0);

    fused_gather_l2<<<nbP128 + nbA128, 256, FUSED_SMEM>>>(
        m0, offs0, csr0, m1, offs2, csr2, m2, offs1, csr1,
        W2_cites, b2_cites, W2_writtenby, b2_writtenby, W2_writes, b2_writes,
        mA, mC, mB, n_paper, n_author, nbP128);

    gather_l2<<<cdiv(((long)n_paper + n_author) * 4, 256), 256>>>(
        mA, offs0, csr0, mB, offs2, csr2, mC, offs1, csr1,
        out_paper, out_author, n_paper, n_author);
}